// round 12
// baseline (speedup 1.0000x reference)
#include <cuda_runtime.h>
#include <cuda_bf16.h>
#include <math.h>
#include <stdint.h>

#define NV   262080
#define DM   192
#define DFF  384
#define SETS 36
#define NSET 7280
#define NL   2
#define GRID 148
#define GRID2 296
#define NT96 2730          // NV / 96 exactly

typedef __nv_bfloat16 bf16;

// ---------------- scratch (device globals) ----------------
__device__ bf16 g_QKh[(size_t)NV * 384];   // Q|K natural order
__device__ bf16 g_Vh [(size_t)NV * 192];   // V natural order
__device__ bf16 g_Oh [(size_t)NV * 192];   // attention out, natural order
__device__ bf16 g_Hh [(size_t)NV * 384];   // FFN hidden
__device__ bf16 g_Xh [(size_t)NV * 192];   // LN1 bf16 out (FFN1 input)
__device__ float g_X[(size_t)NV * 192];    // running x (fp32)
__device__ bf16 g_Wh[2 * 294912];          // per-layer: 8 blocks of [k:192][n:192]

__device__ __forceinline__ float gelu_tanh(float x) {
    float x3 = x * x * x;
    return 0.5f * x * (1.0f + tanhf(0.7978845608028654f * (x + 0.044715f * x3)));
}
__device__ __forceinline__ uint32_t pk2(float a, float b) {
    __nv_bfloat162 t = __floats2bfloat162_rn(a, b);
    return *(uint32_t*)&t;
}
__device__ __forceinline__ void ldsm_x4(uint32_t r[4], uint32_t addr) {
    asm volatile("ldmatrix.sync.aligned.m8n8.x4.shared.b16 {%0,%1,%2,%3}, [%4];"
                 : "=r"(r[0]), "=r"(r[1]), "=r"(r[2]), "=r"(r[3]) : "r"(addr));
}
__device__ __forceinline__ void ldsm_x4_t(uint32_t r[4], uint32_t addr) {
    asm volatile("ldmatrix.sync.aligned.m8n8.x4.trans.shared.b16 {%0,%1,%2,%3}, [%4];"
                 : "=r"(r[0]), "=r"(r[1]), "=r"(r[2]), "=r"(r[3]) : "r"(addr));
}
__device__ __forceinline__ void mma_bf16(float c[4], const uint32_t a[4], const uint32_t* b) {
    asm volatile(
        "mma.sync.aligned.m16n8k16.row.col.f32.bf16.bf16.f32 "
        "{%0,%1,%2,%3}, {%4,%5,%6,%7}, {%8,%9}, {%0,%1,%2,%3};"
        : "+f"(c[0]), "+f"(c[1]), "+f"(c[2]), "+f"(c[3])
        : "r"(a[0]), "r"(a[1]), "r"(a[2]), "r"(a[3]), "r"(b[0]), "r"(b[1]));
}
__device__ __forceinline__ void cp_async16(uint32_t dst, const void* src) {
    asm volatile("cp.async.ca.shared.global [%0], [%1], 16;" :: "r"(dst), "l"(src));
}
#define CP_COMMIT() asm volatile("cp.async.commit_group;")
#define CP_WAIT0()  asm volatile("cp.async.wait_group 0;" ::: "memory")
#define CP_WAIT1()  asm volatile("cp.async.wait_group 1;" ::: "memory")

// XOR-swizzled smem offset: rows x 192 bf16 cols (384B row), 24 16B-chunks/row
__device__ __forceinline__ uint32_t swz(int row, int chunk) {
    return (uint32_t)(row * 384 + ((chunk ^ (row & 7)) << 4));
}

// ---------------- weight pack: both layers ----------------
__global__ void pack_kernel(const float* __restrict__ qkv_w, const float* __restrict__ out_w,
                            const float* __restrict__ w1, const float* __restrict__ w2) {
    int gi = blockIdx.x * 256 + threadIdx.x;
    if (gi >= 2 * 294912) return;
    int l = gi / 294912, i = gi % 294912;
    int blk = i / 36864, j = i % 36864;
    int k = j / 192, n = j % 192;
    float v;
    if (blk < 3)       v = qkv_w[(size_t)(l * 3 + blk) * 36864 + k * 192 + n];
    else if (blk == 3) v = out_w[(size_t)l * 36864 + k * 192 + n];
    else if (blk == 4) v = w1[(size_t)l * 73728 + k * 384 + n];
    else if (blk == 5) v = w1[(size_t)l * 73728 + k * 384 + 192 + n];
    else if (blk == 6) v = w2[(size_t)l * 73728 + k * 192 + n];
    else               v = w2[(size_t)l * 73728 + (192 + k) * 192 + n];
    g_Wh[gi] = __float2bfloat16(v);
}

// ============ QK dual-B GEMM (natural order, A = bf16(x + pos) staged in-kernel) ============
__global__ void __launch_bounds__(384)
gemm_qk(const float* __restrict__ X, const float* __restrict__ POS,
        const bf16* __restrict__ W0, const bf16* __restrict__ W1,
        const float* __restrict__ bias, bf16* __restrict__ C)
{
    extern __shared__ __align__(16) char smem[];
    const uint32_t smem_u32 = (uint32_t)__cvta_generic_to_shared(smem);
    const uint32_t b_u32[2] = { smem_u32, smem_u32 + 73728u };
    char* As = smem + 147456;
    __shared__ float sbias[384];

    const int tid = threadIdx.x, lane = tid & 31, wid = tid >> 5;
    const int wy = wid >> 2, wx = wid & 3;
    const int lane15 = lane & 15, lane16 = lane >> 4;
    const int g = lane >> 2, l4 = lane & 3;
    const int bx = (int)blockIdx.x;
    const uint32_t a_u32 = smem_u32 + 147456u;

    if (tid < 384) sbias[tid] = bias[tid];

    for (int f = tid; f < 4608; f += 384) {
        int r = f / 24, c = f % 24;
        cp_async16(b_u32[0] + swz(r, c), W0 + (size_t)r * 192 + c * 8);
        cp_async16(b_u32[1] + swz(r, c), W1 + (size_t)r * 192 + c * 8);
    }
    CP_COMMIT();

    const int nmine = (NT96 - bx + GRID - 1) / GRID;

    for (int ti = 0; ti < nmine; ti++) {
        const int t = bx + ti * GRID;
        #pragma unroll
        for (int u = 0; u < 6; u++) {
            int f = tid + u * 384;
            int r = f / 24, c = f % 24;
            const float4* xp = (const float4*)(X   + (size_t)(t * 96 + r) * 192 + c * 8);
            const float4* pp = (const float4*)(POS + (size_t)(t * 96 + r) * 192 + c * 8);
            float4 a0 = xp[0], a1 = xp[1], p0 = pp[0], p1 = pp[1];
            a0.x += p0.x; a0.y += p0.y; a0.z += p0.z; a0.w += p0.w;
            a1.x += p1.x; a1.y += p1.y; a1.z += p1.z; a1.w += p1.w;
            uint4 o;
            o.x = pk2(a0.x, a0.y); o.y = pk2(a0.z, a0.w);
            o.z = pk2(a1.x, a1.y); o.w = pk2(a1.z, a1.w);
            *(uint4*)(As + swz(r, c)) = o;
        }
        if (ti == 0) CP_WAIT0();
        __syncthreads();

        float acc[2][2][6][4];
        #pragma unroll
        for (int m = 0; m < 2; m++)
            #pragma unroll
            for (int mt = 0; mt < 2; mt++)
                #pragma unroll
                for (int nt = 0; nt < 6; nt++)
                    #pragma unroll
                    for (int i = 0; i < 4; i++) acc[m][mt][nt][i] = 0.f;

        #pragma unroll
        for (int kc = 0; kc < 12; kc++) {
            uint32_t a0[4], a1[4];
            ldsm_x4(a0, a_u32 + swz(wy * 32 + lane15,      kc * 2 + lane16));
            ldsm_x4(a1, a_u32 + swz(wy * 32 + 16 + lane15, kc * 2 + lane16));
            const int krow = kc * 16 + lane15;
            #pragma unroll
            for (int m = 0; m < 2; m++) {
                #pragma unroll
                for (int t16 = 0; t16 < 3; t16++) {
                    uint32_t B[4];
                    ldsm_x4_t(B, b_u32[m] + swz(krow, wx * 6 + t16 * 2 + lane16));
                    mma_bf16(acc[m][0][2 * t16],     a0, B + 0);
                    mma_bf16(acc[m][0][2 * t16 + 1], a0, B + 2);
                    mma_bf16(acc[m][1][2 * t16],     a1, B + 0);
                    mma_bf16(acc[m][1][2 * t16 + 1], a1, B + 2);
                }
            }
        }
        __syncthreads();

        const int row0 = t * 96;
        #pragma unroll
        for (int m = 0; m < 2; m++)
            #pragma unroll
            for (int mt = 0; mt < 2; mt++)
                #pragma unroll
                for (int half = 0; half < 2; half++) {
                    const int row = row0 + wy * 32 + mt * 16 + g + half * 8;
                    bf16* cp = C + (size_t)row * 384 + m * 192;
                    #pragma unroll
                    for (int t16 = 0; t16 < 3; t16++)
                        #pragma unroll
                        for (int b8 = 0; b8 < 2; b8++) {
                            const int col = wx * 48 + t16 * 16 + b8 * 8 + 2 * l4;
                            float ox = acc[m][mt][2 * t16 + b8][half * 2 + 0] + sbias[m * 192 + col];
                            float oy = acc[m][mt][2 * t16 + b8][half * 2 + 1] + sbias[m * 192 + col + 1];
                            __nv_bfloat162 o = __floats2bfloat162_rn(ox, oy);
                            *(__nv_bfloat162*)(cp + col) = o;
                        }
                }
    }
}

// ============ V GEMM (natural order, A = bf16(x) staged in-kernel) ============
__global__ void __launch_bounds__(256, 2)
gemm_v(const float* __restrict__ X, const bf16* __restrict__ W,
       const float* __restrict__ bias, bf16* __restrict__ C)
{
    extern __shared__ __align__(16) char smem[];
    const uint32_t smem_u32 = (uint32_t)__cvta_generic_to_shared(smem);
    const uint32_t b_u32 = smem_u32;
    char* As = smem + 73728;
    const uint32_t a_u32 = smem_u32 + 73728u;

    const int tid = threadIdx.x, lane = tid & 31, wid = tid >> 5;
    const int wy = wid >> 2, wx = wid & 3;
    const int lane15 = lane & 15, lane16 = lane >> 4;
    const int g = lane >> 2, l4 = lane & 3;
    const int bx = (int)blockIdx.x;

    for (int f = tid; f < 4608; f += 256) {
        int r = f / 24, c = f % 24;
        cp_async16(b_u32 + swz(r, c), W + (size_t)r * 192 + c * 8);
    }
    CP_COMMIT();

    const int nmine = (NT96 - bx + GRID2 - 1) / GRID2;

    for (int ti = 0; ti < nmine; ti++) {
        const int t = bx + ti * GRID2;
        #pragma unroll
        for (int u = 0; u < 9; u++) {
            int f = tid + u * 256;
            int r = f / 24, c = f % 24;
            const float4* xp = (const float4*)(X + (size_t)(t * 96 + r) * 192 + c * 8);
            float4 a0 = xp[0], a1 = xp[1];
            uint4 o;
            o.x = pk2(a0.x, a0.y); o.y = pk2(a0.z, a0.w);
            o.z = pk2(a1.x, a1.y); o.w = pk2(a1.z, a1.w);
            *(uint4*)(As + swz(r, c)) = o;
        }
        if (ti == 0) CP_WAIT0();
        __syncthreads();

        float acc[3][6][4];
        #pragma unroll
        for (int mt = 0; mt < 3; mt++)
            #pragma unroll
            for (int nt = 0; nt < 6; nt++)
                #pragma unroll
                for (int i = 0; i < 4; i++) acc[mt][nt][i] = 0.f;

        #pragma unroll
        for (int kc = 0; kc < 12; kc++) {
            uint32_t a[3][4];
            #pragma unroll
            for (int mt = 0; mt < 3; mt++)
                ldsm_x4(a[mt], a_u32 + swz(wy * 48 + mt * 16 + lane15, kc * 2 + lane16));
            const int krow = kc * 16 + lane15;
            #pragma unroll
            for (int t16 = 0; t16 < 3; t16++) {
                uint32_t B[4];
                ldsm_x4_t(B, b_u32 + swz(krow, wx * 6 + t16 * 2 + lane16));
                #pragma unroll
                for (int mt = 0; mt < 3; mt++) {
                    mma_bf16(acc[mt][2 * t16],     a[mt], B + 0);
                    mma_bf16(acc[mt][2 * t16 + 1], a[mt], B + 2);
                }
            }
        }
        __syncthreads();

        const int row0 = t * 96;
        #pragma unroll
        for (int mt = 0; mt < 3; mt++)
            #pragma unroll
            for (int half = 0; half < 2; half++) {
                const int row = row0 + wy * 48 + mt * 16 + g + half * 8;
                bf16* cp = C + (size_t)row * 192;
                #pragma unroll
                for (int t16 = 0; t16 < 3; t16++)
                    #pragma unroll
                    for (int b8 = 0; b8 < 2; b8++) {
                        const int col = wx * 48 + t16 * 16 + b8 * 8 + 2 * l4;
                        float ox = acc[mt][2 * t16 + b8][half * 2 + 0] + __ldg(bias + col);
                        float oy = acc[mt][2 * t16 + b8][half * 2 + 1] + __ldg(bias + col + 1);
                        __nv_bfloat162 o = __floats2bfloat162_rn(ox, oy);
                        *(__nv_bfloat162*)(cp + col) = o;
                    }
            }
    }
}

// ============ O-proj + residual + LN1 (natural order) ============
__global__ void __launch_bounds__(256, 2)
gemm_oln(const bf16* __restrict__ A, const bf16* __restrict__ W,
         const float* __restrict__ bias, const float* __restrict__ xres,
         const float* __restrict__ lnw, const float* __restrict__ lnb,
         float* __restrict__ Xf, bf16* __restrict__ Xh)
{
    extern __shared__ __align__(16) char smem[];
    const uint32_t smem_u32 = (uint32_t)__cvta_generic_to_shared(smem);
    const uint32_t b_u32 = smem_u32;
    const uint32_t a_u32 = smem_u32 + 73728u;
    __shared__ float rs[96], rq[96];

    const int tid = threadIdx.x, lane = tid & 31, wid = tid >> 5;
    const int wy = wid >> 2, wx = wid & 3;
    const int lane15 = lane & 15, lane16 = lane >> 4;
    const int g = lane >> 2, l4 = lane & 3;
    const int bx = (int)blockIdx.x;

    for (int f = tid; f < 4608; f += 256) {
        int r = f / 24, c = f % 24;
        cp_async16(b_u32 + swz(r, c), W + (size_t)r * 192 + c * 8);
    }
    auto loadA = [&](int t) {
        #pragma unroll
        for (int u = 0; u < 9; u++) {
            int f = tid + u * 256;
            int r = f / 24, c = f % 24;
            cp_async16(a_u32 + swz(r, c), A + (size_t)(t * 96 + r) * 192 + c * 8);
        }
    };

    const int nmine = (NT96 - bx + GRID2 - 1) / GRID2;
    loadA(bx);
    CP_COMMIT();

    for (int ti = 0; ti < nmine; ti++) {
        const int t = bx + ti * GRID2;
        CP_WAIT0();
        __syncthreads();
        if (tid < 96) { rs[tid] = 0.f; rq[tid] = 0.f; }

        float acc[3][6][4];
        #pragma unroll
        for (int mt = 0; mt < 3; mt++)
            #pragma unroll
            for (int nt = 0; nt < 6; nt++)
                #pragma unroll
                for (int i = 0; i < 4; i++) acc[mt][nt][i] = 0.f;

        #pragma unroll
        for (int kc = 0; kc < 12; kc++) {
            uint32_t a[3][4];
            #pragma unroll
            for (int mt = 0; mt < 3; mt++)
                ldsm_x4(a[mt], a_u32 + swz(wy * 48 + mt * 16 + lane15, kc * 2 + lane16));
            const int krow = kc * 16 + lane15;
            #pragma unroll
            for (int t16 = 0; t16 < 3; t16++) {
                uint32_t B[4];
                ldsm_x4_t(B, b_u32 + swz(krow, wx * 6 + t16 * 2 + lane16));
                #pragma unroll
                for (int mt = 0; mt < 3; mt++) {
                    mma_bf16(acc[mt][2 * t16],     a[mt], B + 0);
                    mma_bf16(acc[mt][2 * t16 + 1], a[mt], B + 2);
                }
            }
        }
        __syncthreads();

        if (ti + 1 < nmine) loadA(bx + (ti + 1) * GRID2);
        CP_COMMIT();

        const int row0 = t * 96;
        #pragma unroll
        for (int mt = 0; mt < 3; mt++)
            #pragma unroll
            for (int half = 0; half < 2; half++) {
                const int row = row0 + wy * 48 + mt * 16 + g + half * 8;
                const float* xp = xres + (size_t)row * 192;
                float sv = 0.f, qv = 0.f;
                #pragma unroll
                for (int t16 = 0; t16 < 3; t16++)
                    #pragma unroll
                    for (int b8 = 0; b8 < 2; b8++) {
                        const int col = wx * 48 + t16 * 16 + b8 * 8 + 2 * l4;
                        float2 xv = *(const float2*)(xp + col);
                        float v0 = acc[mt][2 * t16 + b8][half * 2 + 0] + __ldg(bias + col) + xv.x;
                        float v1 = acc[mt][2 * t16 + b8][half * 2 + 1] + __ldg(bias + col + 1) + xv.y;
                        acc[mt][2 * t16 + b8][half * 2 + 0] = v0;
                        acc[mt][2 * t16 + b8][half * 2 + 1] = v1;
                        sv += v0 + v1;
                        qv += v0 * v0 + v1 * v1;
                    }
                sv += __shfl_xor_sync(0xffffffffu, sv, 1);
                qv += __shfl_xor_sync(0xffffffffu, qv, 1);
                sv += __shfl_xor_sync(0xffffffffu, sv, 2);
                qv += __shfl_xor_sync(0xffffffffu, qv, 2);
                if (l4 == 0) {
                    const int rloc = wy * 48 + mt * 16 + g + half * 8;
                    atomicAdd(&rs[rloc], sv);
                    atomicAdd(&rq[rloc], qv);
                }
            }
        __syncthreads();
        #pragma unroll
        for (int mt = 0; mt < 3; mt++)
            #pragma unroll
            for (int half = 0; half < 2; half++) {
                const int rloc = wy * 48 + mt * 16 + g + half * 8;
                const int row = row0 + rloc;
                const float mean = rs[rloc] * (1.f / 192.f);
                const float inv  = rsqrtf(rq[rloc] * (1.f / 192.f) - mean * mean + 1e-5f);
                float* xo = Xf + (size_t)row * 192;
                bf16*  xh = Xh + (size_t)row * 192;
                #pragma unroll
                for (int t16 = 0; t16 < 3; t16++)
                    #pragma unroll
                    for (int b8 = 0; b8 < 2; b8++) {
                        const int col = wx * 48 + t16 * 16 + b8 * 8 + 2 * l4;
                        float v0 = acc[mt][2 * t16 + b8][half * 2 + 0];
                        float v1 = acc[mt][2 * t16 + b8][half * 2 + 1];
                        float o0 = (v0 - mean) * inv * __ldg(lnw + col) + __ldg(lnb + col);
                        float o1 = (v1 - mean) * inv * __ldg(lnw + col + 1) + __ldg(lnb + col + 1);
                        float2 of; of.x = o0; of.y = o1;
                        *(float2*)(xo + col) = of;
                        __nv_bfloat162 ob = __floats2bfloat162_rn(o0, o1);
                        *(__nv_bfloat162*)(xh + col) = ob;
                    }
            }
    }
}

// ============ FFN1 halves: bf16 A via cp.async, GELU epilogue ============
__global__ void __launch_bounds__(256, 2)
gemm_ffn1(const bf16* __restrict__ A, const bf16* __restrict__ W,
          const float* __restrict__ bias, bf16* __restrict__ C, int coff)
{
    extern __shared__ __align__(16) char smem[];
    const uint32_t smem_u32 = (uint32_t)__cvta_generic_to_shared(smem);
    const uint32_t b_u32 = smem_u32;
    const uint32_t a_u32 = smem_u32 + 73728u;

    const int tid = threadIdx.x, lane = tid & 31, wid = tid >> 5;
    const int wy = wid >> 2, wx = wid & 3;
    const int lane15 = lane & 15, lane16 = lane >> 4;
    const int g = lane >> 2, l4 = lane & 3;
    const int bx = (int)blockIdx.x;

    for (int f = tid; f < 4608; f += 256) {
        int r = f / 24, c = f % 24;
        cp_async16(b_u32 + swz(r, c), W + (size_t)r * 192 + c * 8);
    }
    auto loadA = [&](int t) {
        #pragma unroll
        for (int u = 0; u < 9; u++) {
            int f = tid + u * 256;
            int r = f / 24, c = f % 24;
            cp_async16(a_u32 + swz(r, c), A + (size_t)(t * 96 + r) * 192 + c * 8);
        }
    };

    const int nmine = (NT96 - bx + GRID2 - 1) / GRID2;
    loadA(bx);
    CP_COMMIT();

    for (int ti = 0; ti < nmine; ti++) {
        const int t = bx + ti * GRID2;
        CP_WAIT0();
        __syncthreads();

        float acc[3][6][4];
        #pragma unroll
        for (int mt = 0; mt < 3; mt++)
            #pragma unroll
            for (int nt = 0; nt < 6; nt++)
                #pragma unroll
                for (int i = 0; i < 4; i++) acc[mt][nt][i] = 0.f;

        #pragma unroll
        for (int kc = 0; kc < 12; kc++) {
            uint32_t a[3][4];
            #pragma unroll
            for (int mt = 0; mt < 3; mt++)
                ldsm_x4(a[mt], a_u32 + swz(wy * 48 + mt * 16 + lane15, kc * 2 + lane16));
            const int krow = kc * 16 + lane15;
            #pragma unroll
            for (int t16 = 0; t16 < 3; t16++) {
                uint32_t B[4];
                ldsm_x4_t(B, b_u32 + swz(krow, wx * 6 + t16 * 2 + lane16));
                #pragma unroll
                for (int mt = 0; mt < 3; mt++) {
                    mma_bf16(acc[mt][2 * t16],     a[mt], B + 0);
                    mma_bf16(acc[mt][2 * t16 + 1], a[mt], B + 2);
                }
            }
        }
        __syncthreads();

        if (ti + 1 < nmine) loadA(bx + (ti + 1) * GRID2);
        CP_COMMIT();

        const int row0 = t * 96;
        #pragma unroll
        for (int mt = 0; mt < 3; mt++)
            #pragma unroll
            for (int half = 0; half < 2; half++) {
                const int row = row0 + wy * 48 + mt * 16 + g + half * 8;
                bf16* cp = C + (size_t)row * 384 + coff;
                #pragma unroll
                for (int t16 = 0; t16 < 3; t16++)
                    #pragma unroll
                    for (int b8 = 0; b8 < 2; b8++) {
                        const int col = wx * 48 + t16 * 16 + b8 * 8 + 2 * l4;
                        float ox = acc[mt][2 * t16 + b8][half * 2 + 0] + __ldg(bias + col);
                        float oy = acc[mt][2 * t16 + b8][half * 2 + 1] + __ldg(bias + col + 1);
                        ox = gelu_tanh(ox); oy = gelu_tanh(oy);
                        __nv_bfloat162 o = __floats2bfloat162_rn(ox, oy);
                        *(__nv_bfloat162*)(cp + col) = o;
                    }
            }
    }
}

// ============ FFN2 (K=384) + residual + LN2 ============
__global__ void __launch_bounds__(384)
gemm_f2ln(const bf16* __restrict__ A,
          const bf16* __restrict__ W0, const bf16* __restrict__ W1,
          const float* __restrict__ bias, const float* __restrict__ xres,
          const float* __restrict__ lnw, const float* __restrict__ lnb,
          float* __restrict__ Out)
{
    extern __shared__ __align__(16) char smem[];
    const uint32_t smem_u32 = (uint32_t)__cvta_generic_to_shared(smem);
    const uint32_t b_u32[2] = { smem_u32, smem_u32 + 73728u };
    const uint32_t a_u32    = smem_u32 + 147456u;
    __shared__ float sbias[192], slnw[192], slnb[192];
    __shared__ float rs[96], rq[96];

    const int tid = threadIdx.x, lane = tid & 31, wid = tid >> 5;
    const int wy = wid >> 2, wx = wid & 3;
    const int lane15 = lane & 15, lane16 = lane >> 4;
    const int g = lane >> 2, l4 = lane & 3;
    const int bx = (int)blockIdx.x;

    if (tid < 192) { sbias[tid] = bias[tid]; slnw[tid] = lnw[tid]; slnb[tid] = lnb[tid]; }

    for (int f = tid; f < 4608; f += 384) {
        int r = f / 24, c = f % 24;
        cp_async16(b_u32[0] + swz(r, c), W0 + (size_t)r * 192 + c * 8);
        cp_async16(b_u32[1] + swz(r, c), W1 + (size_t)r * 192 + c * 8);
    }
    const int pr = tid >> 2, pc0 = (tid & 3) * 6;
    auto loadA = [&](int s, int buf) {
        const int t = bx + (s >> 1) * GRID, kh = s & 1;
        const bf16* src = A + (size_t)(t * 96 + pr) * 384 + kh * 192 + pc0 * 8;
        uint32_t dstb = a_u32 + buf * 36864u;
        #pragma unroll
        for (int u = 0; u < 6; u++)
            cp_async16(dstb + swz(pr, pc0 + u), src + u * 8);
    };

    const int nmine = (NT96 - bx + GRID - 1) / GRID;
    const int nst = nmine * 2;
    loadA(0, 0);
    CP_COMMIT();

    float acc[2][6][4];

    for (int s = 0; s < nst; s++) {
        const int kh = s & 1;
        if (s + 1 < nst) loadA(s + 1, (s + 1) & 1);
        CP_COMMIT();
        CP_WAIT1();
        __syncthreads();
        if (kh == 0) {
            if (tid < 96) { rs[tid] = 0.f; rq[tid] = 0.f; }
            #pragma unroll
            for (int mt = 0; mt < 2; mt++)
                #pragma unroll
                for (int nt = 0; nt < 6; nt++)
                    #pragma unroll
                    for (int i = 0; i < 4; i++) acc[mt][nt][i] = 0.f;
        }

        const uint32_t abuf = a_u32 + (uint32_t)((s & 1) * 36864);
        const uint32_t bb = b_u32[kh];
        #pragma unroll
        for (int kc = 0; kc < 12; kc++) {
            uint32_t a0[4], a1[4];
            ldsm_x4(a0, abuf + swz(wy * 32 + lane15,      kc * 2 + lane16));
            ldsm_x4(a1, abuf + swz(wy * 32 + 16 + lane15, kc * 2 + lane16));
            const int krow = kc * 16 + lane15;
            #pragma unroll
            for (int t16 = 0; t16 < 3; t16++) {
                uint32_t B[4];
                ldsm_x4_t(B, bb + swz(krow, wx * 6 + t16 * 2 + lane16));
                mma_bf16(acc[0][2 * t16],     a0, B + 0);
                mma_bf16(acc[0][2 * t16 + 1], a0, B + 2);
                mma_bf16(acc[1][2 * t16],     a1, B + 0);
                mma_bf16(acc[1][2 * t16 + 1], a1, B + 2);
            }
        }
        __syncthreads();

        if (kh == 1) {
            const int row0 = (bx + (s >> 1) * GRID) * 96;
            #pragma unroll
            for (int mt = 0; mt < 2; mt++)
                #pragma unroll
                for (int half = 0; half < 2; half++) {
                    const int row = row0 + wy * 32 + mt * 16 + g + half * 8;
                    const float* xp = xres + (size_t)row * 192;
                    float sv = 0.f, qv = 0.f;
                    #pragma unroll
                    for (int t16 = 0; t16 < 3; t16++)
                        #pragma unroll
                        for (int b8 = 0; b8 < 2; b8++) {
                            const int col = wx * 48 + t16 * 16 + b8 * 8 + 2 * l4;
                            float2 xv = *(const float2*)(xp + col);
                            float v0 = acc[mt][2 * t16 + b8][half * 2 + 0] + sbias[col] + xv.x;
                            float v1 = acc[mt][2 * t16 + b8][half * 2 + 1] + sbias[col + 1] + xv.y;
                            acc[mt][2 * t16 + b8][half * 2 + 0] = v0;
                            acc[mt][2 * t16 + b8][half * 2 + 1] = v1;
                            sv += v0 + v1; qv += v0 * v0 + v1 * v1;
                        }
                    sv += __shfl_xor_sync(0xffffffffu, sv, 1);
                    qv += __shfl_xor_sync(0xffffffffu, qv, 1);
                    sv += __shfl_xor_sync(0xffffffffu, sv, 2);
                    qv += __shfl_xor_sync(0xffffffffu, qv, 2);
                    if (l4 == 0) {
                        const int rloc = wy * 32 + mt * 16 + g + half * 8;
                        atomicAdd(&rs[rloc], sv);
                        atomicAdd(&rq[rloc], qv);
                    }
                }
            __syncthreads();
            #pragma unroll
            for (int mt = 0; mt < 2; mt++)
                #pragma unroll
                for (int half = 0; half < 2; half++) {
                    const int rloc = wy * 32 + mt * 16 + g + half * 8;
                    const int row = row0 + rloc;
                    const float mean = rs[rloc] * (1.f / 192.f);
                    const float inv  = rsqrtf(rq[rloc] * (1.f / 192.f) - mean * mean + 1e-5f);
                    float* op = Out + (size_t)row * 192;
                    #pragma unroll
                    for (int t16 = 0; t16 < 3; t16++)
                        #pragma unroll
                        for (int b8 = 0; b8 < 2; b8++) {
                            const int col = wx * 48 + t16 * 16 + b8 * 8 + 2 * l4;
                            float v0 = acc[mt][2 * t16 + b8][half * 2 + 0];
                            float v1 = acc[mt][2 * t16 + b8][half * 2 + 1];
                            float2 of;
                            of.x = (v0 - mean) * inv * slnw[col] + slnb[col];
                            of.y = (v1 - mean) * inv * slnw[col + 1] + slnb[col + 1];
                            *(float2*)(op + col) = of;
                        }
                }
        }
    }
}

// ================= tensor-core set attention =================
// 1 set per block, 256 threads = 8 warps = 8 heads.
// Per head: S(48x48x32) = Q @ K^T via mma; masked softmax on fragments;
// O(48x32x48) = P @ V with S-accums reused as bf16 A-fragments.
// smem: Q [8][48][40] bf16, Kt [8][32][56] bf16 (dim-major), V [8][48][40] bf16.
#define AQ_OFF 0
#define AK_OFF 30720        // 8*48*40*2
#define AV_OFF 59392        // AK_OFF + 8*32*56*2
#define ATTN_SMEM 90112     // AV_OFF + 30720

__global__ void __launch_bounds__(256, 2)
attn_tc(const bf16* __restrict__ QK, const bf16* __restrict__ V,
        const int* __restrict__ gidx, bf16* __restrict__ O)
{
    extern __shared__ __align__(16) char smem[];
    const uint32_t smem_u32 = (uint32_t)__cvta_generic_to_shared(smem);
    __shared__ int sidx[36];

    const int s = blockIdx.x, tid = threadIdx.x;
    const int lane = tid & 31, h = tid >> 5;
    const int lane15 = lane & 15, lane16 = lane >> 4;
    const int g = lane >> 2, l4 = lane & 3;

    if (tid < 36) sidx[tid] = __ldg(gidx + s * SETS + tid);
    // zero padded regions
    for (int i = tid; i < ATTN_SMEM / 16; i += 256)
        *(uint4*)(smem + i * 16) = make_uint4(0, 0, 0, 0);
    __syncthreads();

    // stage Q and V: (head, key, chunk of 8 dims)
    for (int f = tid; f < 864; f += 256) {
        int hh = f / 108, r = f % 108;
        int key = r / 3, c = r % 3;
        int grow = sidx[key];
        uint4 q = *(const uint4*)(QK + (size_t)grow * 384 + hh * 24 + c * 8);
        *(uint4*)(smem + AQ_OFF + (hh * 1920 + key * 40 + c * 8) * 2) = q;
        uint4 v = *(const uint4*)(V + (size_t)grow * 192 + hh * 24 + c * 8);
        *(uint4*)(smem + AV_OFF + (hh * 1920 + key * 40 + c * 8) * 2) = v;
    }
    // stage K transposed: Kt[h][dim][key]
    for (int f = tid; f < 864; f += 256) {
        int hh = f / 108, r = f % 108;
        int key = r / 3, c = r % 3;
        int grow = sidx[key];
        uint4 kv = *(const uint4*)(QK + (size_t)grow * 384 + 192 + hh * 24 + c * 8);
        bf16 tmp[8];
        *(uint4*)tmp = kv;
        bf16* kb = (bf16*)(smem + AK_OFF) + hh * 1792 + (c * 8) * 56 + key;
        #pragma unroll
        for (int d = 0; d < 8; d++) kb[d * 56] = tmp[d];
    }
    __syncthreads();

    const uint32_t qb = smem_u32 + AQ_OFF + (uint32_t)(h * 1920) * 2;
    const uint32_t kb = smem_u32 + AK_OFF + (uint32_t)(h * 1792) * 2;
    const uint32_t vb = smem_u32 + AV_OFF + (uint32_t)(h * 1920) * 2;

    // ---- S = Q @ K^T (3 m-tiles x 6 n8-tiles, K=32) ----
    float S[3][6][4];
    #pragma unroll
    for (int mt = 0; mt < 3; mt++)
        #pragma unroll
        for (int nt = 0; nt < 6; nt++)
            #pragma unroll
            for (int i = 0; i < 4; i++) S[mt][nt][i] = 0.f;

    #pragma unroll
    for (int kc = 0; kc < 2; kc++) {
        uint32_t a[3][4];
        #pragma unroll
        for (int mt = 0; mt < 3; mt++)
            ldsm_x4(a[mt], qb + (uint32_t)((mt * 16 + lane15) * 40 + kc * 16 + lane16 * 8) * 2);
        #pragma unroll
        for (int nt2 = 0; nt2 < 3; nt2++) {
            uint32_t B[4];
            ldsm_x4_t(B, kb + (uint32_t)((kc * 16 + lane15) * 56 + nt2 * 16 + lane16 * 8) * 2);
            #pragma unroll
            for (int mt = 0; mt < 3; mt++) {
                mma_bf16(S[mt][2 * nt2],     a[mt], B + 0);
                mma_bf16(S[mt][2 * nt2 + 1], a[mt], B + 2);
            }
        }
    }

    // ---- masked softmax on fragments (scale folded in) ----
    const float scale = 0.20412414523193154f;   // 1/sqrt(24)
    float inv_[3][2];
    #pragma unroll
    for (int mt = 0; mt < 3; mt++) {
        #pragma unroll
        for (int half = 0; half < 2; half++) {
            float mx = -1e30f;
            #pragma unroll
            for (int nt = 0; nt < 6; nt++) {
                #pragma unroll
                for (int cc = 0; cc < 2; cc++) {
                    const int col = nt * 8 + l4 * 2 + cc;
                    float v = (col < 36) ? S[mt][nt][half * 2 + cc] * scale : -1e30f;
                    S[mt][nt][half * 2 + cc] = v;
                    mx = fmaxf(mx, v);
                }
            }
            mx = fmaxf(mx, __shfl_xor_sync(0xffffffffu, mx, 1));
            mx = fmaxf(mx, __shfl_xor_sync(0xffffffffu, mx, 2));
            float sum = 0.f;
            #pragma unroll
            for (int nt = 0; nt < 6; nt++) {
                #pragma unroll
                for (int cc = 0; cc < 2; cc++) {
                    float e = __expf(S[mt][nt][half * 2 + cc] - mx);
                    S[mt][nt][half * 2 + cc] = e;
                    sum += e;
                }
            }
            sum += __shfl_xor_sync(0xffffffffu, sum, 1);
            sum += __shfl_xor_sync(0xffffffffu, sum, 2);
            inv_[mt][half] = 1.f / sum;
        }
    }

    // ---- pack P to bf16 A-fragments: P[mt][kt] covers keys kt*16..+15 ----
    uint32_t P[3][3][4];
    #pragma unroll
    for (int mt = 0; mt < 3; mt++)
        #pragma unroll
        for (int kt = 0; kt < 3; kt++) {
            P[mt][kt][0] = pk2(S[mt][2 * kt][0],     S[mt][2 * kt][1]);
            P[mt][kt][1] = pk2(S[mt][2 * kt][2],     S[mt][2 * kt][3]);
            P[mt][kt][2] = pk2(S[mt][2 * kt + 1][0], S[mt][2 * kt + 1][1]);
            P[mt][kt][3] = pk2(S[mt][2 * kt + 1][2], S[mt][2 * kt + 1][3]);
        }

    // ---- O = P @ V (3 m-tiles x 4 n8-tiles, K=48) ----
    float Oa[3][4][4];
    #pragma unroll
    for (int mt = 0; mt < 3; mt++)
        #pragma unroll
        for (int nt = 0; nt < 4; nt++)
            #pragma unroll
            for (int i = 0; i < 4; i++) Oa[mt][nt][i] = 0.f;

    #pragma unroll
    for (int kt = 0; kt < 3; kt++) {
        #pragma unroll
        for (int nt2 = 0; nt2 < 2; nt2++) {
            uint32_t B[4];
            ldsm_x4_t(B, vb + (uint32_t)((kt * 16 + lane15) * 40 + nt2 * 16 + lane16 * 8) * 2);
            #pragma unroll
            for (int mt = 0; mt < 3; mt++) {
                mma_bf16(Oa[mt][2 * nt2],     P[mt][kt], B + 0);
                mma_bf16(Oa[mt][2 * nt2 + 1], P[mt][kt], B + 2);
            }
        }
    }

    // ---- store (rows < 36 only, dims < 24 only), normalize by rowsum ----
    #pragma unroll
    for (int mt = 0; mt < 3; mt++)
        #pragma unroll
        for (int half = 0; half < 2; half++) {
            const int row = mt * 16 + g + half * 8;
            if (row >= 36) continue;
            const int grow = sidx[row];
            const float inv = inv_[mt][half];
            bf16* op = O + (size_t)grow * 192 + h * 24;
            #pragma unroll
            for (int nt = 0; nt < 3; nt++) {
                const int col = nt * 8 + l4 * 2;
                __nv_bfloat162 o = __floats2bfloat162_rn(
                    Oa[mt][nt][half * 2 + 0] * inv, Oa[mt][nt][half * 2 + 1] * inv);
                *(__nv_bfloat162*)(op + col) = o;
            }
        }
}

// ---------------- host ----------------
extern "C" void kernel_launch(void* const* d_in, const int* in_sizes, int n_in,
                              void* d_out, int out_size)
{
    (void)in_sizes; (void)n_in; (void)out_size;
    const float* src    = (const float*)d_in[0];
    const float* pos    = (const float*)d_in[1];
    const float* qkv_w  = (const float*)d_in[2];
    const float* qkv_b  = (const float*)d_in[3];
    const float* out_w  = (const float*)d_in[4];
    const float* out_b  = (const float*)d_in[5];
    const float* ln_w   = (const float*)d_in[6];
    const float* ln_b   = (const float*)d_in[7];
    const float* w1     = (const float*)d_in[8];
    const float* b1     = (const float*)d_in[9];
    const float* w2     = (const float*)d_in[10];
    const float* b2     = (const float*)d_in[11];
    const int*   inds   = (const int*)d_in[12];
    float*       outp   = (float*)d_out;

    bf16 *QKh, *Vh, *Oh, *Hh, *Xh, *Wh;
    float *Xb;
    cudaGetSymbolAddress((void**)&QKh, g_QKh);
    cudaGetSymbolAddress((void**)&Vh,  g_Vh);
    cudaGetSymbolAddress((void**)&Oh,  g_Oh);
    cudaGetSymbolAddress((void**)&Hh,  g_Hh);
    cudaGetSymbolAddress((void**)&Xh,  g_Xh);
    cudaGetSymbolAddress((void**)&Xb,  g_X);
    cudaGetSymbolAddress((void**)&Wh,  g_Wh);

    cudaFuncSetAttribute(attn_tc, cudaFuncAttributeMaxDynamicSharedMemorySize, ATTN_SMEM);

    const int sm_qk  = 2 * 73728 + 36864;              // 184320 (1 CTA/SM)
    const int sm_one = 73728 + 36864;                  // 110592 (2 CTAs/SM)
    const int sm_f2  = 2 * 73728 + 2 * 36864;          // 221184 (1 CTA/SM)
    cudaFuncSetAttribute((const void*)gemm_qk,
                         cudaFuncAttributeMaxDynamicSharedMemorySize, sm_qk);
    cudaFuncSetAttribute((const void*)gemm_v,
                         cudaFuncAttributeMaxDynamicSharedMemorySize, sm_one);
    cudaFuncSetAttribute((const void*)gemm_oln,
                         cudaFuncAttributeMaxDynamicSharedMemorySize, sm_one);
    cudaFuncSetAttribute((const void*)gemm_ffn1,
                         cudaFuncAttributeMaxDynamicSharedMemorySize, sm_one);
    cudaFuncSetAttribute((const void*)gemm_f2ln,
                         cudaFuncAttributeMaxDynamicSharedMemorySize, sm_f2);

    // pack both layers once
    pack_kernel<<<(2 * 294912 + 255) / 256, 256>>>(qkv_w, out_w, w1, w2);

    for (int l = 0; l < NL; l++) {
        const float* xin = (l == 0) ? src : Xb;
        const int*   idx = inds + (size_t)l * NV;
        const float* pel = pos  + (size_t)l * NV * DM;
        const float* qb  = qkv_b + (size_t)l * 3 * DM;
        bf16* Wl = Wh + (size_t)l * 294912;

        gemm_qk<<<GRID, 384, sm_qk>>>(xin, pel, Wl + 0 * 36864, Wl + 1 * 36864, qb, QKh);
        gemm_v<<<GRID2, 256, sm_one>>>(xin, Wl + 2 * 36864, qb + 384, Vh);

        attn_tc<<<NSET, 256, ATTN_SMEM>>>(QKh, Vh, idx, Oh);

        gemm_oln<<<GRID2, 256, sm_one>>>(Oh, Wl + 3 * 36864, out_b + (size_t)l * DM, xin,
                                         ln_w + (size_t)(l * 2) * DM, ln_b + (size_t)(l * 2) * DM,
                                         Xb, Xh);

        gemm_ffn1<<<GRID2, 256, sm_one>>>(Xh, Wl + 4 * 36864, b1 + (size_t)l * DFF, Hh, 0);
        gemm_ffn1<<<GRID2, 256, sm_one>>>(Xh, Wl + 5 * 36864, b1 + (size_t)l * DFF + 192, Hh, 192);

        float* lnout = (l == NL - 1) ? outp : Xb;
        gemm_f2ln<<<GRID, 384, sm_f2>>>(Hh, Wl + 6 * 36864, Wl + 7 * 36864,
                                        b2 + (size_t)l * DM, Xb,
                                        ln_w + (size_t)(l * 2 + 1) * DM,
                                        ln_b + (size_t)(l * 2 + 1) * DM, lnout);
    }
}

// round 13
// speedup vs baseline: 1.4628x; 1.4628x over previous
#include <cuda_runtime.h>
#include <cuda_bf16.h>
#include <math.h>
#include <stdint.h>

#define NV   262080
#define DM   192
#define DFF  384
#define SETS 36
#define NSET 7280
#define NL   2
#define GRID 148
#define GRID2 296
#define NT96 2730          // NV / 96 exactly

typedef __nv_bfloat16 bf16;

// ---------------- scratch (device globals) ----------------
__device__ bf16 g_QKh[(size_t)NV * 384];   // Q|K natural order
__device__ bf16 g_Vh [(size_t)NV * 192];   // V natural order
__device__ bf16 g_Oh [(size_t)NV * 192];   // attention out, natural order
__device__ bf16 g_Hh [(size_t)NV * 384];   // FFN hidden
__device__ bf16 g_Xh [(size_t)NV * 192];   // LN1 bf16 out (FFN1 input)
__device__ float g_X[(size_t)NV * 192];    // running x (fp32)
__device__ bf16 g_Wh[2 * 294912];          // per-layer: 8 blocks of [k:192][n:192]

__device__ __forceinline__ float gelu_tanh(float x) {
    float x3 = x * x * x;
    return 0.5f * x * (1.0f + tanhf(0.7978845608028654f * (x + 0.044715f * x3)));
}
__device__ __forceinline__ uint32_t pk2(float a, float b) {
    __nv_bfloat162 t = __floats2bfloat162_rn(a, b);
    return *(uint32_t*)&t;
}
__device__ __forceinline__ void ldsm_x4(uint32_t r[4], uint32_t addr) {
    asm volatile("ldmatrix.sync.aligned.m8n8.x4.shared.b16 {%0,%1,%2,%3}, [%4];"
                 : "=r"(r[0]), "=r"(r[1]), "=r"(r[2]), "=r"(r[3]) : "r"(addr));
}
__device__ __forceinline__ void ldsm_x4_t(uint32_t r[4], uint32_t addr) {
    asm volatile("ldmatrix.sync.aligned.m8n8.x4.trans.shared.b16 {%0,%1,%2,%3}, [%4];"
                 : "=r"(r[0]), "=r"(r[1]), "=r"(r[2]), "=r"(r[3]) : "r"(addr));
}
__device__ __forceinline__ void mma_bf16(float c[4], const uint32_t a[4], const uint32_t* b) {
    asm volatile(
        "mma.sync.aligned.m16n8k16.row.col.f32.bf16.bf16.f32 "
        "{%0,%1,%2,%3}, {%4,%5,%6,%7}, {%8,%9}, {%0,%1,%2,%3};"
        : "+f"(c[0]), "+f"(c[1]), "+f"(c[2]), "+f"(c[3])
        : "r"(a[0]), "r"(a[1]), "r"(a[2]), "r"(a[3]), "r"(b[0]), "r"(b[1]));
}
__device__ __forceinline__ void mma_bf16_2(float c[4], const uint32_t a[4],
                                           uint32_t b0, uint32_t b1) {
    asm volatile(
        "mma.sync.aligned.m16n8k16.row.col.f32.bf16.bf16.f32 "
        "{%0,%1,%2,%3}, {%4,%5,%6,%7}, {%8,%9}, {%0,%1,%2,%3};"
        : "+f"(c[0]), "+f"(c[1]), "+f"(c[2]), "+f"(c[3])
        : "r"(a[0]), "r"(a[1]), "r"(a[2]), "r"(a[3]), "r"(b0), "r"(b1));
}
__device__ __forceinline__ void cp_async16(uint32_t dst, const void* src) {
    asm volatile("cp.async.ca.shared.global [%0], [%1], 16;" :: "r"(dst), "l"(src));
}
#define CP_COMMIT() asm volatile("cp.async.commit_group;")
#define CP_WAIT0()  asm volatile("cp.async.wait_group 0;" ::: "memory")
#define CP_WAIT1()  asm volatile("cp.async.wait_group 1;" ::: "memory")

// XOR-swizzled smem offset: rows x 192 bf16 cols (384B row), 24 16B-chunks/row
__device__ __forceinline__ uint32_t swz(int row, int chunk) {
    return (uint32_t)(row * 384 + ((chunk ^ (row & 7)) << 4));
}

// ---------------- weight pack: both layers ----------------
__global__ void pack_kernel(const float* __restrict__ qkv_w, const float* __restrict__ out_w,
                            const float* __restrict__ w1, const float* __restrict__ w2) {
    int gi = blockIdx.x * 256 + threadIdx.x;
    if (gi >= 2 * 294912) return;
    int l = gi / 294912, i = gi % 294912;
    int blk = i / 36864, j = i % 36864;
    int k = j / 192, n = j % 192;
    float v;
    if (blk < 3)       v = qkv_w[(size_t)(l * 3 + blk) * 36864 + k * 192 + n];
    else if (blk == 3) v = out_w[(size_t)l * 36864 + k * 192 + n];
    else if (blk == 4) v = w1[(size_t)l * 73728 + k * 384 + n];
    else if (blk == 5) v = w1[(size_t)l * 73728 + k * 384 + 192 + n];
    else if (blk == 6) v = w2[(size_t)l * 73728 + k * 192 + n];
    else               v = w2[(size_t)l * 73728 + (192 + k) * 192 + n];
    g_Wh[gi] = __float2bfloat16(v);
}

// ============ QK dual-B GEMM (natural order, A = bf16(x + pos) staged in-kernel) ============
__global__ void __launch_bounds__(384)
gemm_qk(const float* __restrict__ X, const float* __restrict__ POS,
        const bf16* __restrict__ W0, const bf16* __restrict__ W1,
        const float* __restrict__ bias, bf16* __restrict__ C)
{
    extern __shared__ __align__(16) char smem[];
    const uint32_t smem_u32 = (uint32_t)__cvta_generic_to_shared(smem);
    const uint32_t b_u32[2] = { smem_u32, smem_u32 + 73728u };
    char* As = smem + 147456;
    __shared__ float sbias[384];

    const int tid = threadIdx.x, lane = tid & 31, wid = tid >> 5;
    const int wy = wid >> 2, wx = wid & 3;
    const int lane15 = lane & 15, lane16 = lane >> 4;
    const int g = lane >> 2, l4 = lane & 3;
    const int bx = (int)blockIdx.x;
    const uint32_t a_u32 = smem_u32 + 147456u;

    if (tid < 384) sbias[tid] = bias[tid];

    for (int f = tid; f < 4608; f += 384) {
        int r = f / 24, c = f % 24;
        cp_async16(b_u32[0] + swz(r, c), W0 + (size_t)r * 192 + c * 8);
        cp_async16(b_u32[1] + swz(r, c), W1 + (size_t)r * 192 + c * 8);
    }
    CP_COMMIT();

    const int nmine = (NT96 - bx + GRID - 1) / GRID;

    for (int ti = 0; ti < nmine; ti++) {
        const int t = bx + ti * GRID;
        #pragma unroll
        for (int u = 0; u < 6; u++) {
            int f = tid + u * 384;
            int r = f / 24, c = f % 24;
            const float4* xp = (const float4*)(X   + (size_t)(t * 96 + r) * 192 + c * 8);
            const float4* pp = (const float4*)(POS + (size_t)(t * 96 + r) * 192 + c * 8);
            float4 a0 = xp[0], a1 = xp[1], p0 = pp[0], p1 = pp[1];
            a0.x += p0.x; a0.y += p0.y; a0.z += p0.z; a0.w += p0.w;
            a1.x += p1.x; a1.y += p1.y; a1.z += p1.z; a1.w += p1.w;
            uint4 o;
            o.x = pk2(a0.x, a0.y); o.y = pk2(a0.z, a0.w);
            o.z = pk2(a1.x, a1.y); o.w = pk2(a1.z, a1.w);
            *(uint4*)(As + swz(r, c)) = o;
        }
        if (ti == 0) CP_WAIT0();
        __syncthreads();

        float acc[2][2][6][4];
        #pragma unroll
        for (int m = 0; m < 2; m++)
            #pragma unroll
            for (int mt = 0; mt < 2; mt++)
                #pragma unroll
                for (int nt = 0; nt < 6; nt++)
                    #pragma unroll
                    for (int i = 0; i < 4; i++) acc[m][mt][nt][i] = 0.f;

        #pragma unroll
        for (int kc = 0; kc < 12; kc++) {
            uint32_t a0[4], a1[4];
            ldsm_x4(a0, a_u32 + swz(wy * 32 + lane15,      kc * 2 + lane16));
            ldsm_x4(a1, a_u32 + swz(wy * 32 + 16 + lane15, kc * 2 + lane16));
            const int krow = kc * 16 + lane15;
            #pragma unroll
            for (int m = 0; m < 2; m++) {
                #pragma unroll
                for (int t16 = 0; t16 < 3; t16++) {
                    uint32_t B[4];
                    ldsm_x4_t(B, b_u32[m] + swz(krow, wx * 6 + t16 * 2 + lane16));
                    mma_bf16(acc[m][0][2 * t16],     a0, B + 0);
                    mma_bf16(acc[m][0][2 * t16 + 1], a0, B + 2);
                    mma_bf16(acc[m][1][2 * t16],     a1, B + 0);
                    mma_bf16(acc[m][1][2 * t16 + 1], a1, B + 2);
                }
            }
        }
        __syncthreads();

        const int row0 = t * 96;
        #pragma unroll
        for (int m = 0; m < 2; m++)
            #pragma unroll
            for (int mt = 0; mt < 2; mt++)
                #pragma unroll
                for (int half = 0; half < 2; half++) {
                    const int row = row0 + wy * 32 + mt * 16 + g + half * 8;
                    bf16* cp = C + (size_t)row * 384 + m * 192;
                    #pragma unroll
                    for (int t16 = 0; t16 < 3; t16++)
                        #pragma unroll
                        for (int b8 = 0; b8 < 2; b8++) {
                            const int col = wx * 48 + t16 * 16 + b8 * 8 + 2 * l4;
                            float ox = acc[m][mt][2 * t16 + b8][half * 2 + 0] + sbias[m * 192 + col];
                            float oy = acc[m][mt][2 * t16 + b8][half * 2 + 1] + sbias[m * 192 + col + 1];
                            __nv_bfloat162 o = __floats2bfloat162_rn(ox, oy);
                            *(__nv_bfloat162*)(cp + col) = o;
                        }
                }
    }
}

// ============ V GEMM (natural order, A = bf16(x) staged in-kernel) ============
__global__ void __launch_bounds__(256, 2)
gemm_v(const float* __restrict__ X, const bf16* __restrict__ W,
       const float* __restrict__ bias, bf16* __restrict__ C)
{
    extern __shared__ __align__(16) char smem[];
    const uint32_t smem_u32 = (uint32_t)__cvta_generic_to_shared(smem);
    const uint32_t b_u32 = smem_u32;
    char* As = smem + 73728;
    const uint32_t a_u32 = smem_u32 + 73728u;

    const int tid = threadIdx.x, lane = tid & 31, wid = tid >> 5;
    const int wy = wid >> 2, wx = wid & 3;
    const int lane15 = lane & 15, lane16 = lane >> 4;
    const int g = lane >> 2, l4 = lane & 3;
    const int bx = (int)blockIdx.x;

    for (int f = tid; f < 4608; f += 256) {
        int r = f / 24, c = f % 24;
        cp_async16(b_u32 + swz(r, c), W + (size_t)r * 192 + c * 8);
    }
    CP_COMMIT();

    const int nmine = (NT96 - bx + GRID2 - 1) / GRID2;

    for (int ti = 0; ti < nmine; ti++) {
        const int t = bx + ti * GRID2;
        #pragma unroll
        for (int u = 0; u < 9; u++) {
            int f = tid + u * 256;
            int r = f / 24, c = f % 24;
            const float4* xp = (const float4*)(X + (size_t)(t * 96 + r) * 192 + c * 8);
            float4 a0 = xp[0], a1 = xp[1];
            uint4 o;
            o.x = pk2(a0.x, a0.y); o.y = pk2(a0.z, a0.w);
            o.z = pk2(a1.x, a1.y); o.w = pk2(a1.z, a1.w);
            *(uint4*)(As + swz(r, c)) = o;
        }
        if (ti == 0) CP_WAIT0();
        __syncthreads();

        float acc[3][6][4];
        #pragma unroll
        for (int mt = 0; mt < 3; mt++)
            #pragma unroll
            for (int nt = 0; nt < 6; nt++)
                #pragma unroll
                for (int i = 0; i < 4; i++) acc[mt][nt][i] = 0.f;

        #pragma unroll
        for (int kc = 0; kc < 12; kc++) {
            uint32_t a[3][4];
            #pragma unroll
            for (int mt = 0; mt < 3; mt++)
                ldsm_x4(a[mt], a_u32 + swz(wy * 48 + mt * 16 + lane15, kc * 2 + lane16));
            const int krow = kc * 16 + lane15;
            #pragma unroll
            for (int t16 = 0; t16 < 3; t16++) {
                uint32_t B[4];
                ldsm_x4_t(B, b_u32 + swz(krow, wx * 6 + t16 * 2 + lane16));
                #pragma unroll
                for (int mt = 0; mt < 3; mt++) {
                    mma_bf16(acc[mt][2 * t16],     a[mt], B + 0);
                    mma_bf16(acc[mt][2 * t16 + 1], a[mt], B + 2);
                }
            }
        }
        __syncthreads();

        const int row0 = t * 96;
        #pragma unroll
        for (int mt = 0; mt < 3; mt++)
            #pragma unroll
            for (int half = 0; half < 2; half++) {
                const int row = row0 + wy * 48 + mt * 16 + g + half * 8;
                bf16* cp = C + (size_t)row * 192;
                #pragma unroll
                for (int t16 = 0; t16 < 3; t16++)
                    #pragma unroll
                    for (int b8 = 0; b8 < 2; b8++) {
                        const int col = wx * 48 + t16 * 16 + b8 * 8 + 2 * l4;
                        float ox = acc[mt][2 * t16 + b8][half * 2 + 0] + __ldg(bias + col);
                        float oy = acc[mt][2 * t16 + b8][half * 2 + 1] + __ldg(bias + col + 1);
                        __nv_bfloat162 o = __floats2bfloat162_rn(ox, oy);
                        *(__nv_bfloat162*)(cp + col) = o;
                    }
            }
    }
}

// ============ O-proj + residual + LN1 (natural order) ============
__global__ void __launch_bounds__(256, 2)
gemm_oln(const bf16* __restrict__ A, const bf16* __restrict__ W,
         const float* __restrict__ bias, const float* __restrict__ xres,
         const float* __restrict__ lnw, const float* __restrict__ lnb,
         float* __restrict__ Xf, bf16* __restrict__ Xh)
{
    extern __shared__ __align__(16) char smem[];
    const uint32_t smem_u32 = (uint32_t)__cvta_generic_to_shared(smem);
    const uint32_t b_u32 = smem_u32;
    const uint32_t a_u32 = smem_u32 + 73728u;
    __shared__ float rs[96], rq[96];

    const int tid = threadIdx.x, lane = tid & 31, wid = tid >> 5;
    const int wy = wid >> 2, wx = wid & 3;
    const int lane15 = lane & 15, lane16 = lane >> 4;
    const int g = lane >> 2, l4 = lane & 3;
    const int bx = (int)blockIdx.x;

    for (int f = tid; f < 4608; f += 256) {
        int r = f / 24, c = f % 24;
        cp_async16(b_u32 + swz(r, c), W + (size_t)r * 192 + c * 8);
    }
    auto loadA = [&](int t) {
        #pragma unroll
        for (int u = 0; u < 9; u++) {
            int f = tid + u * 256;
            int r = f / 24, c = f % 24;
            cp_async16(a_u32 + swz(r, c), A + (size_t)(t * 96 + r) * 192 + c * 8);
        }
    };

    const int nmine = (NT96 - bx + GRID2 - 1) / GRID2;
    loadA(bx);
    CP_COMMIT();

    for (int ti = 0; ti < nmine; ti++) {
        const int t = bx + ti * GRID2;
        CP_WAIT0();
        __syncthreads();
        if (tid < 96) { rs[tid] = 0.f; rq[tid] = 0.f; }

        float acc[3][6][4];
        #pragma unroll
        for (int mt = 0; mt < 3; mt++)
            #pragma unroll
            for (int nt = 0; nt < 6; nt++)
                #pragma unroll
                for (int i = 0; i < 4; i++) acc[mt][nt][i] = 0.f;

        #pragma unroll
        for (int kc = 0; kc < 12; kc++) {
            uint32_t a[3][4];
            #pragma unroll
            for (int mt = 0; mt < 3; mt++)
                ldsm_x4(a[mt], a_u32 + swz(wy * 48 + mt * 16 + lane15, kc * 2 + lane16));
            const int krow = kc * 16 + lane15;
            #pragma unroll
            for (int t16 = 0; t16 < 3; t16++) {
                uint32_t B[4];
                ldsm_x4_t(B, b_u32 + swz(krow, wx * 6 + t16 * 2 + lane16));
                #pragma unroll
                for (int mt = 0; mt < 3; mt++) {
                    mma_bf16(acc[mt][2 * t16],     a[mt], B + 0);
                    mma_bf16(acc[mt][2 * t16 + 1], a[mt], B + 2);
                }
            }
        }
        __syncthreads();

        if (ti + 1 < nmine) loadA(bx + (ti + 1) * GRID2);
        CP_COMMIT();

        const int row0 = t * 96;
        #pragma unroll
        for (int mt = 0; mt < 3; mt++)
            #pragma unroll
            for (int half = 0; half < 2; half++) {
                const int row = row0 + wy * 48 + mt * 16 + g + half * 8;
                const float* xp = xres + (size_t)row * 192;
                float sv = 0.f, qv = 0.f;
                #pragma unroll
                for (int t16 = 0; t16 < 3; t16++)
                    #pragma unroll
                    for (int b8 = 0; b8 < 2; b8++) {
                        const int col = wx * 48 + t16 * 16 + b8 * 8 + 2 * l4;
                        float2 xv = *(const float2*)(xp + col);
                        float v0 = acc[mt][2 * t16 + b8][half * 2 + 0] + __ldg(bias + col) + xv.x;
                        float v1 = acc[mt][2 * t16 + b8][half * 2 + 1] + __ldg(bias + col + 1) + xv.y;
                        acc[mt][2 * t16 + b8][half * 2 + 0] = v0;
                        acc[mt][2 * t16 + b8][half * 2 + 1] = v1;
                        sv += v0 + v1;
                        qv += v0 * v0 + v1 * v1;
                    }
                sv += __shfl_xor_sync(0xffffffffu, sv, 1);
                qv += __shfl_xor_sync(0xffffffffu, qv, 1);
                sv += __shfl_xor_sync(0xffffffffu, sv, 2);
                qv += __shfl_xor_sync(0xffffffffu, qv, 2);
                if (l4 == 0) {
                    const int rloc = wy * 48 + mt * 16 + g + half * 8;
                    atomicAdd(&rs[rloc], sv);
                    atomicAdd(&rq[rloc], qv);
                }
            }
        __syncthreads();
        #pragma unroll
        for (int mt = 0; mt < 3; mt++)
            #pragma unroll
            for (int half = 0; half < 2; half++) {
                const int rloc = wy * 48 + mt * 16 + g + half * 8;
                const int row = row0 + rloc;
                const float mean = rs[rloc] * (1.f / 192.f);
                const float inv  = rsqrtf(rq[rloc] * (1.f / 192.f) - mean * mean + 1e-5f);
                float* xo = Xf + (size_t)row * 192;
                bf16*  xh = Xh + (size_t)row * 192;
                #pragma unroll
                for (int t16 = 0; t16 < 3; t16++)
                    #pragma unroll
                    for (int b8 = 0; b8 < 2; b8++) {
                        const int col = wx * 48 + t16 * 16 + b8 * 8 + 2 * l4;
                        float v0 = acc[mt][2 * t16 + b8][half * 2 + 0];
                        float v1 = acc[mt][2 * t16 + b8][half * 2 + 1];
                        float o0 = (v0 - mean) * inv * __ldg(lnw + col) + __ldg(lnb + col);
                        float o1 = (v1 - mean) * inv * __ldg(lnw + col + 1) + __ldg(lnb + col + 1);
                        float2 of; of.x = o0; of.y = o1;
                        *(float2*)(xo + col) = of;
                        __nv_bfloat162 ob = __floats2bfloat162_rn(o0, o1);
                        *(__nv_bfloat162*)(xh + col) = ob;
                    }
            }
    }
}

// ============ FFN1 halves: bf16 A via cp.async, GELU epilogue ============
__global__ void __launch_bounds__(256, 2)
gemm_ffn1(const bf16* __restrict__ A, const bf16* __restrict__ W,
          const float* __restrict__ bias, bf16* __restrict__ C, int coff)
{
    extern __shared__ __align__(16) char smem[];
    const uint32_t smem_u32 = (uint32_t)__cvta_generic_to_shared(smem);
    const uint32_t b_u32 = smem_u32;
    const uint32_t a_u32 = smem_u32 + 73728u;

    const int tid = threadIdx.x, lane = tid & 31, wid = tid >> 5;
    const int wy = wid >> 2, wx = wid & 3;
    const int lane15 = lane & 15, lane16 = lane >> 4;
    const int g = lane >> 2, l4 = lane & 3;
    const int bx = (int)blockIdx.x;

    for (int f = tid; f < 4608; f += 256) {
        int r = f / 24, c = f % 24;
        cp_async16(b_u32 + swz(r, c), W + (size_t)r * 192 + c * 8);
    }
    auto loadA = [&](int t) {
        #pragma unroll
        for (int u = 0; u < 9; u++) {
            int f = tid + u * 256;
            int r = f / 24, c = f % 24;
            cp_async16(a_u32 + swz(r, c), A + (size_t)(t * 96 + r) * 192 + c * 8);
        }
    };

    const int nmine = (NT96 - bx + GRID2 - 1) / GRID2;
    loadA(bx);
    CP_COMMIT();

    for (int ti = 0; ti < nmine; ti++) {
        const int t = bx + ti * GRID2;
        CP_WAIT0();
        __syncthreads();

        float acc[3][6][4];
        #pragma unroll
        for (int mt = 0; mt < 3; mt++)
            #pragma unroll
            for (int nt = 0; nt < 6; nt++)
                #pragma unroll
                for (int i = 0; i < 4; i++) acc[mt][nt][i] = 0.f;

        #pragma unroll
        for (int kc = 0; kc < 12; kc++) {
            uint32_t a[3][4];
            #pragma unroll
            for (int mt = 0; mt < 3; mt++)
                ldsm_x4(a[mt], a_u32 + swz(wy * 48 + mt * 16 + lane15, kc * 2 + lane16));
            const int krow = kc * 16 + lane15;
            #pragma unroll
            for (int t16 = 0; t16 < 3; t16++) {
                uint32_t B[4];
                ldsm_x4_t(B, b_u32 + swz(krow, wx * 6 + t16 * 2 + lane16));
                #pragma unroll
                for (int mt = 0; mt < 3; mt++) {
                    mma_bf16(acc[mt][2 * t16],     a[mt], B + 0);
                    mma_bf16(acc[mt][2 * t16 + 1], a[mt], B + 2);
                }
            }
        }
        __syncthreads();

        if (ti + 1 < nmine) loadA(bx + (ti + 1) * GRID2);
        CP_COMMIT();

        const int row0 = t * 96;
        #pragma unroll
        for (int mt = 0; mt < 3; mt++)
            #pragma unroll
            for (int half = 0; half < 2; half++) {
                const int row = row0 + wy * 48 + mt * 16 + g + half * 8;
                bf16* cp = C + (size_t)row * 384 + coff;
                #pragma unroll
                for (int t16 = 0; t16 < 3; t16++)
                    #pragma unroll
                    for (int b8 = 0; b8 < 2; b8++) {
                        const int col = wx * 48 + t16 * 16 + b8 * 8 + 2 * l4;
                        float ox = acc[mt][2 * t16 + b8][half * 2 + 0] + __ldg(bias + col);
                        float oy = acc[mt][2 * t16 + b8][half * 2 + 1] + __ldg(bias + col + 1);
                        ox = gelu_tanh(ox); oy = gelu_tanh(oy);
                        __nv_bfloat162 o = __floats2bfloat162_rn(ox, oy);
                        *(__nv_bfloat162*)(cp + col) = o;
                    }
            }
    }
}

// ============ FFN2 (K=384) + residual + LN2 ============
__global__ void __launch_bounds__(384)
gemm_f2ln(const bf16* __restrict__ A,
          const bf16* __restrict__ W0, const bf16* __restrict__ W1,
          const float* __restrict__ bias, const float* __restrict__ xres,
          const float* __restrict__ lnw, const float* __restrict__ lnb,
          float* __restrict__ Out)
{
    extern __shared__ __align__(16) char smem[];
    const uint32_t smem_u32 = (uint32_t)__cvta_generic_to_shared(smem);
    const uint32_t b_u32[2] = { smem_u32, smem_u32 + 73728u };
    const uint32_t a_u32    = smem_u32 + 147456u;
    __shared__ float sbias[192], slnw[192], slnb[192];
    __shared__ float rs[96], rq[96];

    const int tid = threadIdx.x, lane = tid & 31, wid = tid >> 5;
    const int wy = wid >> 2, wx = wid & 3;
    const int lane15 = lane & 15, lane16 = lane >> 4;
    const int g = lane >> 2, l4 = lane & 3;
    const int bx = (int)blockIdx.x;

    if (tid < 192) { sbias[tid] = bias[tid]; slnw[tid] = lnw[tid]; slnb[tid] = lnb[tid]; }

    for (int f = tid; f < 4608; f += 384) {
        int r = f / 24, c = f % 24;
        cp_async16(b_u32[0] + swz(r, c), W0 + (size_t)r * 192 + c * 8);
        cp_async16(b_u32[1] + swz(r, c), W1 + (size_t)r * 192 + c * 8);
    }
    const int pr = tid >> 2, pc0 = (tid & 3) * 6;
    auto loadA = [&](int s, int buf) {
        const int t = bx + (s >> 1) * GRID, kh = s & 1;
        const bf16* src = A + (size_t)(t * 96 + pr) * 384 + kh * 192 + pc0 * 8;
        uint32_t dstb = a_u32 + buf * 36864u;
        #pragma unroll
        for (int u = 0; u < 6; u++)
            cp_async16(dstb + swz(pr, pc0 + u), src + u * 8);
    };

    const int nmine = (NT96 - bx + GRID - 1) / GRID;
    const int nst = nmine * 2;
    loadA(0, 0);
    CP_COMMIT();

    float acc[2][6][4];

    for (int s = 0; s < nst; s++) {
        const int kh = s & 1;
        if (s + 1 < nst) loadA(s + 1, (s + 1) & 1);
        CP_COMMIT();
        CP_WAIT1();
        __syncthreads();
        if (kh == 0) {
            if (tid < 96) { rs[tid] = 0.f; rq[tid] = 0.f; }
            #pragma unroll
            for (int mt = 0; mt < 2; mt++)
                #pragma unroll
                for (int nt = 0; nt < 6; nt++)
                    #pragma unroll
                    for (int i = 0; i < 4; i++) acc[mt][nt][i] = 0.f;
        }

        const uint32_t abuf = a_u32 + (uint32_t)((s & 1) * 36864);
        const uint32_t bb = b_u32[kh];
        #pragma unroll
        for (int kc = 0; kc < 12; kc++) {
            uint32_t a0[4], a1[4];
            ldsm_x4(a0, abuf + swz(wy * 32 + lane15,      kc * 2 + lane16));
            ldsm_x4(a1, abuf + swz(wy * 32 + 16 + lane15, kc * 2 + lane16));
            const int krow = kc * 16 + lane15;
            #pragma unroll
            for (int t16 = 0; t16 < 3; t16++) {
                uint32_t B[4];
                ldsm_x4_t(B, bb + swz(krow, wx * 6 + t16 * 2 + lane16));
                mma_bf16(acc[0][2 * t16],     a0, B + 0);
                mma_bf16(acc[0][2 * t16 + 1], a0, B + 2);
                mma_bf16(acc[1][2 * t16],     a1, B + 0);
                mma_bf16(acc[1][2 * t16 + 1], a1, B + 2);
            }
        }
        __syncthreads();

        if (kh == 1) {
            const int row0 = (bx + (s >> 1) * GRID) * 96;
            #pragma unroll
            for (int mt = 0; mt < 2; mt++)
                #pragma unroll
                for (int half = 0; half < 2; half++) {
                    const int row = row0 + wy * 32 + mt * 16 + g + half * 8;
                    const float* xp = xres + (size_t)row * 192;
                    float sv = 0.f, qv = 0.f;
                    #pragma unroll
                    for (int t16 = 0; t16 < 3; t16++)
                        #pragma unroll
                        for (int b8 = 0; b8 < 2; b8++) {
                            const int col = wx * 48 + t16 * 16 + b8 * 8 + 2 * l4;
                            float2 xv = *(const float2*)(xp + col);
                            float v0 = acc[mt][2 * t16 + b8][half * 2 + 0] + sbias[col] + xv.x;
                            float v1 = acc[mt][2 * t16 + b8][half * 2 + 1] + sbias[col + 1] + xv.y;
                            acc[mt][2 * t16 + b8][half * 2 + 0] = v0;
                            acc[mt][2 * t16 + b8][half * 2 + 1] = v1;
                            sv += v0 + v1; qv += v0 * v0 + v1 * v1;
                        }
                    sv += __shfl_xor_sync(0xffffffffu, sv, 1);
                    qv += __shfl_xor_sync(0xffffffffu, qv, 1);
                    sv += __shfl_xor_sync(0xffffffffu, sv, 2);
                    qv += __shfl_xor_sync(0xffffffffu, qv, 2);
                    if (l4 == 0) {
                        const int rloc = wy * 32 + mt * 16 + g + half * 8;
                        atomicAdd(&rs[rloc], sv);
                        atomicAdd(&rq[rloc], qv);
                    }
                }
            __syncthreads();
            #pragma unroll
            for (int mt = 0; mt < 2; mt++)
                #pragma unroll
                for (int half = 0; half < 2; half++) {
                    const int rloc = wy * 32 + mt * 16 + g + half * 8;
                    const int row = row0 + rloc;
                    const float mean = rs[rloc] * (1.f / 192.f);
                    const float inv  = rsqrtf(rq[rloc] * (1.f / 192.f) - mean * mean + 1e-5f);
                    float* op = Out + (size_t)row * 192;
                    #pragma unroll
                    for (int t16 = 0; t16 < 3; t16++)
                        #pragma unroll
                        for (int b8 = 0; b8 < 2; b8++) {
                            const int col = wx * 48 + t16 * 16 + b8 * 8 + 2 * l4;
                            float v0 = acc[mt][2 * t16 + b8][half * 2 + 0];
                            float v1 = acc[mt][2 * t16 + b8][half * 2 + 1];
                            float2 of;
                            of.x = (v0 - mean) * inv * slnw[col] + slnb[col];
                            of.y = (v1 - mean) * inv * slnw[col + 1] + slnb[col + 1];
                            *(float2*)(op + col) = of;
                        }
                }
        }
    }
}

// ================= tensor-core set attention (v2: no transpose staging) =================
// 1 set per block, 256 threads = 8 warps = 8 heads.
// Q,K,V all staged [8][48][40] bf16 (rows 36..47 and dims 24..31 zero-padded).
// S = Q K^T: A frags = ldsm(Q rows), B frags = ldsm(K rows) (K is [n][k] row-major,
//            so non-transposed ldmatrix yields valid B operands: n-lo={r0,r2}, n-hi={r1,r3}).
// O = P V:   B frags = ldsm_t(V rows) (V is [k][n] k-major).
#define HBUF 3840            // 48*40*2 bytes per head per buffer
#define AQ_OFF 0
#define AK_OFF 30720         // 8*HBUF
#define AV_OFF 61440
#define ATTN_SMEM 92160

__global__ void __launch_bounds__(256, 2)
attn_tc(const bf16* __restrict__ QK, const bf16* __restrict__ V,
        const int* __restrict__ gidx, bf16* __restrict__ O)
{
    extern __shared__ __align__(16) char smem[];
    const uint32_t smem_u32 = (uint32_t)__cvta_generic_to_shared(smem);
    __shared__ int sidx[36];

    const int s = blockIdx.x, tid = threadIdx.x;
    const int lane = tid & 31, h = tid >> 5;
    const int lane15 = lane & 15, lane16 = lane >> 4;
    const int g = lane >> 2, l4 = lane & 3;

    if (tid < 36) sidx[tid] = __ldg(gidx + s * SETS + tid);
    for (int i = tid; i < ATTN_SMEM / 16; i += 256)
        *(uint4*)(smem + i * 16) = make_uint4(0, 0, 0, 0);
    __syncthreads();

    // stage Q, K, V: 864 = 8 heads * 36 keys * 3 chunks
    for (int f = tid; f < 864; f += 256) {
        int hh = f / 108, r = f % 108;
        int key = r / 3, c = r % 3;
        int grow = sidx[key];
        uint4 q = *(const uint4*)(QK + (size_t)grow * 384 + hh * 24 + c * 8);
        *(uint4*)(smem + AQ_OFF + hh * HBUF + (key * 40 + c * 8) * 2) = q;
        uint4 k = *(const uint4*)(QK + (size_t)grow * 384 + 192 + hh * 24 + c * 8);
        *(uint4*)(smem + AK_OFF + hh * HBUF + (key * 40 + c * 8) * 2) = k;
        uint4 v = *(const uint4*)(V + (size_t)grow * 192 + hh * 24 + c * 8);
        *(uint4*)(smem + AV_OFF + hh * HBUF + (key * 40 + c * 8) * 2) = v;
    }
    __syncthreads();

    const uint32_t qb = smem_u32 + AQ_OFF + (uint32_t)(h * HBUF);
    const uint32_t kb = smem_u32 + AK_OFF + (uint32_t)(h * HBUF);
    const uint32_t vb = smem_u32 + AV_OFF + (uint32_t)(h * HBUF);

    // ---- S = Q @ K^T (3 m16 x 3 n16, K=32) ----
    float S[3][6][4];
    #pragma unroll
    for (int mt = 0; mt < 3; mt++)
        #pragma unroll
        for (int nt = 0; nt < 6; nt++)
            #pragma unroll
            for (int i = 0; i < 4; i++) S[mt][nt][i] = 0.f;

    #pragma unroll
    for (int kc = 0; kc < 2; kc++) {
        uint32_t a[3][4];
        #pragma unroll
        for (int mt = 0; mt < 3; mt++)
            ldsm_x4(a[mt], qb + (uint32_t)(((mt * 16 + lane15) * 40 + kc * 16 + lane16 * 8) * 2));
        #pragma unroll
        for (int nt2 = 0; nt2 < 3; nt2++) {
            uint32_t Br[4];
            ldsm_x4(Br, kb + (uint32_t)(((nt2 * 16 + lane15) * 40 + kc * 16 + lane16 * 8) * 2));
            #pragma unroll
            for (int mt = 0; mt < 3; mt++) {
                mma_bf16_2(S[mt][2 * nt2],     a[mt], Br[0], Br[2]);   // n-lo
                mma_bf16_2(S[mt][2 * nt2 + 1], a[mt], Br[1], Br[3]);   // n-hi
            }
        }
    }

    // ---- masked softmax on fragments ----
    const float scale = 0.20412414523193154f;   // 1/sqrt(24)
    float inv_[3][2];
    #pragma unroll
    for (int mt = 0; mt < 3; mt++) {
        #pragma unroll
        for (int half = 0; half < 2; half++) {
            float mx = -1e30f;
            #pragma unroll
            for (int nt = 0; nt < 6; nt++) {
                #pragma unroll
                for (int cc = 0; cc < 2; cc++) {
                    const int col = nt * 8 + l4 * 2 + cc;
                    float v = (col < 36) ? S[mt][nt][half * 2 + cc] * scale : -1e30f;
                    S[mt][nt][half * 2 + cc] = v;
                    mx = fmaxf(mx, v);
                }
            }
            mx = fmaxf(mx, __shfl_xor_sync(0xffffffffu, mx, 1));
            mx = fmaxf(mx, __shfl_xor_sync(0xffffffffu, mx, 2));
            float sum = 0.f;
            #pragma unroll
            for (int nt = 0; nt < 6; nt++) {
                #pragma unroll
                for (int cc = 0; cc < 2; cc++) {
                    float e = __expf(S[mt][nt][half * 2 + cc] - mx);
                    S[mt][nt][half * 2 + cc] = e;
                    sum += e;
                }
            }
            sum += __shfl_xor_sync(0xffffffffu, sum, 1);
            sum += __shfl_xor_sync(0xffffffffu, sum, 2);
            inv_[mt][half] = 1.f / sum;
        }
    }

    // ---- pack P to bf16 A-fragments (keys kt*16..+15) ----
    uint32_t P[3][3][4];
    #pragma unroll
    for (int mt = 0; mt < 3; mt++)
        #pragma unroll
        for (int kt = 0; kt < 3; kt++) {
            P[mt][kt][0] = pk2(S[mt][2 * kt][0],     S[mt][2 * kt][1]);
            P[mt][kt][1] = pk2(S[mt][2 * kt][2],     S[mt][2 * kt][3]);
            P[mt][kt][2] = pk2(S[mt][2 * kt + 1][0], S[mt][2 * kt + 1][1]);
            P[mt][kt][3] = pk2(S[mt][2 * kt + 1][2], S[mt][2 * kt + 1][3]);
        }

    // ---- O = P @ V (3 m16 x 2 n16, K=48) ----
    float Oa[3][4][4];
    #pragma unroll
    for (int mt = 0; mt < 3; mt++)
        #pragma unroll
        for (int nt = 0; nt < 4; nt++)
            #pragma unroll
            for (int i = 0; i < 4; i++) Oa[mt][nt][i] = 0.f;

    #pragma unroll
    for (int kt = 0; kt < 3; kt++) {
        #pragma unroll
        for (int nt2 = 0; nt2 < 2; nt2++) {
            uint32_t B[4];
            ldsm_x4_t(B, vb + (uint32_t)(((kt * 16 + lane15) * 40 + nt2 * 16 + lane16 * 8) * 2));
            #pragma unroll
            for (int mt = 0; mt < 3; mt++) {
                mma_bf16(Oa[mt][2 * nt2],     P[mt][kt], B + 0);
                mma_bf16(Oa[mt][2 * nt2 + 1], P[mt][kt], B + 2);
            }
        }
    }

    // ---- store (rows < 36, dims < 24), normalize by rowsum ----
    #pragma unroll
    for (int mt = 0; mt < 3; mt++)
        #pragma unroll
        for (int half = 0; half < 2; half++) {
            const int row = mt * 16 + g + half * 8;
            if (row >= 36) continue;
            const int grow = sidx[row];
            const float inv = inv_[mt][half];
            bf16* op = O + (size_t)grow * 192 + h * 24;
            #pragma unroll
            for (int nt = 0; nt < 3; nt++) {
                const int col = nt * 8 + l4 * 2;
                __nv_bfloat162 o = __floats2bfloat162_rn(
                    Oa[mt][nt][half * 2 + 0] * inv, Oa[mt][nt][half * 2 + 1] * inv);
                *(__nv_bfloat162*)(op + col) = o;
            }
        }
}

// ---------------- host ----------------
extern "C" void kernel_launch(void* const* d_in, const int* in_sizes, int n_in,
                              void* d_out, int out_size)
{
    (void)in_sizes; (void)n_in; (void)out_size;
    const float* src    = (const float*)d_in[0];
    const float* pos    = (const float*)d_in[1];
    const float* qkv_w  = (const float*)d_in[2];
    const float* qkv_b  = (const float*)d_in[3];
    const float* out_w  = (const float*)d_in[4];
    const float* out_b  = (const float*)d_in[5];
    const float* ln_w   = (const float*)d_in[6];
    const float* ln_b   = (const float*)d_in[7];
    const float* w1     = (const float*)d_in[8];
    const float* b1     = (const float*)d_in[9];
    const float* w2     = (const float*)d_in[10];
    const float* b2     = (const float*)d_in[11];
    const int*   inds   = (const int*)d_in[12];
    float*       outp   = (float*)d_out;

    bf16 *QKh, *Vh, *Oh, *Hh, *Xh, *Wh;
    float *Xb;
    cudaGetSymbolAddress((void**)&QKh, g_QKh);
    cudaGetSymbolAddress((void**)&Vh,  g_Vh);
    cudaGetSymbolAddress((void**)&Oh,  g_Oh);
    cudaGetSymbolAddress((void**)&Hh,  g_Hh);
    cudaGetSymbolAddress((void**)&Xh,  g_Xh);
    cudaGetSymbolAddress((void**)&Xb,  g_X);
    cudaGetSymbolAddress((void**)&Wh,  g_Wh);

    cudaFuncSetAttribute(attn_tc, cudaFuncAttributeMaxDynamicSharedMemorySize, ATTN_SMEM);

    const int sm_qk  = 2 * 73728 + 36864;              // 184320 (1 CTA/SM)
    const int sm_one = 73728 + 36864;                  // 110592 (2 CTAs/SM)
    const int sm_f2  = 2 * 73728 + 2 * 36864;          // 221184 (1 CTA/SM)
    cudaFuncSetAttribute((const void*)gemm_qk,
                         cudaFuncAttributeMaxDynamicSharedMemorySize, sm_qk);
    cudaFuncSetAttribute((const void*)gemm_v,
                         cudaFuncAttributeMaxDynamicSharedMemorySize, sm_one);
    cudaFuncSetAttribute((const void*)gemm_oln,
                         cudaFuncAttributeMaxDynamicSharedMemorySize, sm_one);
    cudaFuncSetAttribute((const void*)gemm_ffn1,
                         cudaFuncAttributeMaxDynamicSharedMemorySize, sm_one);
    cudaFuncSetAttribute((const void*)gemm_f2ln,
                         cudaFuncAttributeMaxDynamicSharedMemorySize, sm_f2);

    // pack both layers once
    pack_kernel<<<(2 * 294912 + 255) / 256, 256>>>(qkv_w, out_w, w1, w2);

    for (int l = 0; l < NL; l++) {
        const float* xin = (l == 0) ? src : Xb;
        const int*   idx = inds + (size_t)l * NV;
        const float* pel = pos  + (size_t)l * NV * DM;
        const float* qb  = qkv_b + (size_t)l * 3 * DM;
        bf16* Wl = Wh + (size_t)l * 294912;

        gemm_qk<<<GRID, 384, sm_qk>>>(xin, pel, Wl + 0 * 36864, Wl + 1 * 36864, qb, QKh);
        gemm_v<<<GRID2, 256, sm_one>>>(xin, Wl + 2 * 36864, qb + 384, Vh);

        attn_tc<<<NSET, 256, ATTN_SMEM>>>(QKh, Vh, idx, Oh);

        gemm_oln<<<GRID2, 256, sm_one>>>(Oh, Wl + 3 * 36864, out_b + (size_t)l * DM, xin,
                                         ln_w + (size_t)(l * 2) * DM, ln_b + (size_t)(l * 2) * DM,
                                         Xb, Xh);

        gemm_ffn1<<<GRID2, 256, sm_one>>>(Xh, Wl + 4 * 36864, b1 + (size_t)l * DFF, Hh, 0);
        gemm_ffn1<<<GRID2, 256, sm_one>>>(Xh, Wl + 5 * 36864, b1 + (size_t)l * DFF + 192, Hh, 192);

        float* lnout = (l == NL - 1) ? outp : Xb;
        gemm_f2ln<<<GRID, 384, sm_f2>>>(Hh, Wl + 6 * 36864, Wl + 7 * 36864,
                                        b2 + (size_t)l * DM, Xb,
                                        ln_w + (size_t)(l * 2 + 1) * DM,
                                        ln_b + (size_t)(l * 2 + 1) * DM, lnout);
    }
}

// round 14
// speedup vs baseline: 1.4868x; 1.0164x over previous
#include <cuda_runtime.h>
#include <cuda_bf16.h>
#include <math.h>
#include <stdint.h>

#define NV   262080
#define DM   192
#define DFF  384
#define SETS 36
#define NSET 7280
#define NL   2
#define GRID 148
#define GRID2 296
#define NT96 2730          // NV / 96 exactly

typedef __nv_bfloat16 bf16;

// ---------------- scratch (device globals) ----------------
__device__ bf16 g_QKh[(size_t)NV * 384];   // Q|K natural order
__device__ bf16 g_Vh [(size_t)NV * 192];   // V natural order
__device__ bf16 g_Oh [(size_t)NV * 192];   // attention out, natural order
__device__ bf16 g_Hh [(size_t)NV * 384];   // FFN hidden
__device__ bf16 g_Xh [(size_t)NV * 192];   // LN1 bf16 out (FFN1 input)
__device__ float g_X[(size_t)NV * 192];    // running x (fp32)
__device__ bf16 g_Wh[2 * 294912];          // per-layer: 8 blocks of [k:192][n:192]

__device__ __forceinline__ float gelu_tanh(float x) {
    float x3 = x * x * x;
    return 0.5f * x * (1.0f + tanhf(0.7978845608028654f * (x + 0.044715f * x3)));
}
__device__ __forceinline__ uint32_t pk2(float a, float b) {
    __nv_bfloat162 t = __floats2bfloat162_rn(a, b);
    return *(uint32_t*)&t;
}
__device__ __forceinline__ void ldsm_x4(uint32_t r[4], uint32_t addr) {
    asm volatile("ldmatrix.sync.aligned.m8n8.x4.shared.b16 {%0,%1,%2,%3}, [%4];"
                 : "=r"(r[0]), "=r"(r[1]), "=r"(r[2]), "=r"(r[3]) : "r"(addr));
}
__device__ __forceinline__ void ldsm_x4_t(uint32_t r[4], uint32_t addr) {
    asm volatile("ldmatrix.sync.aligned.m8n8.x4.trans.shared.b16 {%0,%1,%2,%3}, [%4];"
                 : "=r"(r[0]), "=r"(r[1]), "=r"(r[2]), "=r"(r[3]) : "r"(addr));
}
__device__ __forceinline__ void mma_bf16(float c[4], const uint32_t a[4], const uint32_t* b) {
    asm volatile(
        "mma.sync.aligned.m16n8k16.row.col.f32.bf16.bf16.f32 "
        "{%0,%1,%2,%3}, {%4,%5,%6,%7}, {%8,%9}, {%0,%1,%2,%3};"
        : "+f"(c[0]), "+f"(c[1]), "+f"(c[2]), "+f"(c[3])
        : "r"(a[0]), "r"(a[1]), "r"(a[2]), "r"(a[3]), "r"(b[0]), "r"(b[1]));
}
__device__ __forceinline__ void mma_bf16_2(float c[4], const uint32_t a[4],
                                           uint32_t b0, uint32_t b1) {
    asm volatile(
        "mma.sync.aligned.m16n8k16.row.col.f32.bf16.bf16.f32 "
        "{%0,%1,%2,%3}, {%4,%5,%6,%7}, {%8,%9}, {%0,%1,%2,%3};"
        : "+f"(c[0]), "+f"(c[1]), "+f"(c[2]), "+f"(c[3])
        : "r"(a[0]), "r"(a[1]), "r"(a[2]), "r"(a[3]), "r"(b0), "r"(b1));
}
__device__ __forceinline__ void cp_async16(uint32_t dst, const void* src) {
    asm volatile("cp.async.ca.shared.global [%0], [%1], 16;" :: "r"(dst), "l"(src));
}
#define CP_COMMIT() asm volatile("cp.async.commit_group;")
#define CP_WAIT0()  asm volatile("cp.async.wait_group 0;" ::: "memory")
#define CP_WAIT1()  asm volatile("cp.async.wait_group 1;" ::: "memory")

// XOR-swizzled smem offset: rows x 192 bf16 cols (384B row), 24 16B-chunks/row
__device__ __forceinline__ uint32_t swz(int row, int chunk) {
    return (uint32_t)(row * 384 + ((chunk ^ (row & 7)) << 4));
}

// ---------------- weight pack: both layers ----------------
__global__ void pack_kernel(const float* __restrict__ qkv_w, const float* __restrict__ out_w,
                            const float* __restrict__ w1, const float* __restrict__ w2) {
    int gi = blockIdx.x * 256 + threadIdx.x;
    if (gi >= 2 * 294912) return;
    int l = gi / 294912, i = gi % 294912;
    int blk = i / 36864, j = i % 36864;
    int k = j / 192, n = j % 192;
    float v;
    if (blk < 3)       v = qkv_w[(size_t)(l * 3 + blk) * 36864 + k * 192 + n];
    else if (blk == 3) v = out_w[(size_t)l * 36864 + k * 192 + n];
    else if (blk == 4) v = w1[(size_t)l * 73728 + k * 384 + n];
    else if (blk == 5) v = w1[(size_t)l * 73728 + k * 384 + 192 + n];
    else if (blk == 6) v = w2[(size_t)l * 73728 + k * 192 + n];
    else               v = w2[(size_t)l * 73728 + (192 + k) * 192 + n];
    g_Wh[gi] = __float2bfloat16(v);
}

// ============ QK dual-B GEMM (natural order, A = bf16(x + pos) staged in-kernel) ============
__global__ void __launch_bounds__(384)
gemm_qk(const float* __restrict__ X, const float* __restrict__ POS,
        const bf16* __restrict__ W0, const bf16* __restrict__ W1,
        const float* __restrict__ bias, bf16* __restrict__ C)
{
    extern __shared__ __align__(16) char smem[];
    const uint32_t smem_u32 = (uint32_t)__cvta_generic_to_shared(smem);
    const uint32_t b_u32[2] = { smem_u32, smem_u32 + 73728u };
    char* As = smem + 147456;
    __shared__ float sbias[384];

    const int tid = threadIdx.x, lane = tid & 31, wid = tid >> 5;
    const int wy = wid >> 2, wx = wid & 3;
    const int lane15 = lane & 15, lane16 = lane >> 4;
    const int g = lane >> 2, l4 = lane & 3;
    const int bx = (int)blockIdx.x;
    const uint32_t a_u32 = smem_u32 + 147456u;

    if (tid < 384) sbias[tid] = bias[tid];

    for (int f = tid; f < 4608; f += 384) {
        int r = f / 24, c = f % 24;
        cp_async16(b_u32[0] + swz(r, c), W0 + (size_t)r * 192 + c * 8);
        cp_async16(b_u32[1] + swz(r, c), W1 + (size_t)r * 192 + c * 8);
    }
    CP_COMMIT();

    const int nmine = (NT96 - bx + GRID - 1) / GRID;

    for (int ti = 0; ti < nmine; ti++) {
        const int t = bx + ti * GRID;
        #pragma unroll
        for (int u = 0; u < 6; u++) {
            int f = tid + u * 384;
            int r = f / 24, c = f % 24;
            const float4* xp = (const float4*)(X   + (size_t)(t * 96 + r) * 192 + c * 8);
            const float4* pp = (const float4*)(POS + (size_t)(t * 96 + r) * 192 + c * 8);
            float4 a0 = xp[0], a1 = xp[1], p0 = pp[0], p1 = pp[1];
            a0.x += p0.x; a0.y += p0.y; a0.z += p0.z; a0.w += p0.w;
            a1.x += p1.x; a1.y += p1.y; a1.z += p1.z; a1.w += p1.w;
            uint4 o;
            o.x = pk2(a0.x, a0.y); o.y = pk2(a0.z, a0.w);
            o.z = pk2(a1.x, a1.y); o.w = pk2(a1.z, a1.w);
            *(uint4*)(As + swz(r, c)) = o;
        }
        if (ti == 0) CP_WAIT0();
        __syncthreads();

        float acc[2][2][6][4];
        #pragma unroll
        for (int m = 0; m < 2; m++)
            #pragma unroll
            for (int mt = 0; mt < 2; mt++)
                #pragma unroll
                for (int nt = 0; nt < 6; nt++)
                    #pragma unroll
                    for (int i = 0; i < 4; i++) acc[m][mt][nt][i] = 0.f;

        #pragma unroll
        for (int kc = 0; kc < 12; kc++) {
            uint32_t a0[4], a1[4];
            ldsm_x4(a0, a_u32 + swz(wy * 32 + lane15,      kc * 2 + lane16));
            ldsm_x4(a1, a_u32 + swz(wy * 32 + 16 + lane15, kc * 2 + lane16));
            const int krow = kc * 16 + lane15;
            #pragma unroll
            for (int m = 0; m < 2; m++) {
                #pragma unroll
                for (int t16 = 0; t16 < 3; t16++) {
                    uint32_t B[4];
                    ldsm_x4_t(B, b_u32[m] + swz(krow, wx * 6 + t16 * 2 + lane16));
                    mma_bf16(acc[m][0][2 * t16],     a0, B + 0);
                    mma_bf16(acc[m][0][2 * t16 + 1], a0, B + 2);
                    mma_bf16(acc[m][1][2 * t16],     a1, B + 0);
                    mma_bf16(acc[m][1][2 * t16 + 1], a1, B + 2);
                }
            }
        }
        __syncthreads();

        const int row0 = t * 96;
        #pragma unroll
        for (int m = 0; m < 2; m++)
            #pragma unroll
            for (int mt = 0; mt < 2; mt++)
                #pragma unroll
                for (int half = 0; half < 2; half++) {
                    const int row = row0 + wy * 32 + mt * 16 + g + half * 8;
                    bf16* cp = C + (size_t)row * 384 + m * 192;
                    #pragma unroll
                    for (int t16 = 0; t16 < 3; t16++)
                        #pragma unroll
                        for (int b8 = 0; b8 < 2; b8++) {
                            const int col = wx * 48 + t16 * 16 + b8 * 8 + 2 * l4;
                            float ox = acc[m][mt][2 * t16 + b8][half * 2 + 0] + sbias[m * 192 + col];
                            float oy = acc[m][mt][2 * t16 + b8][half * 2 + 1] + sbias[m * 192 + col + 1];
                            __nv_bfloat162 o = __floats2bfloat162_rn(ox, oy);
                            *(__nv_bfloat162*)(cp + col) = o;
                        }
                }
    }
}

// ============ V GEMM (natural order, A = bf16(x) staged in-kernel) ============
__global__ void __launch_bounds__(256, 2)
gemm_v(const float* __restrict__ X, const bf16* __restrict__ W,
       const float* __restrict__ bias, bf16* __restrict__ C)
{
    extern __shared__ __align__(16) char smem[];
    const uint32_t smem_u32 = (uint32_t)__cvta_generic_to_shared(smem);
    const uint32_t b_u32 = smem_u32;
    char* As = smem + 73728;
    const uint32_t a_u32 = smem_u32 + 73728u;

    const int tid = threadIdx.x, lane = tid & 31, wid = tid >> 5;
    const int wy = wid >> 2, wx = wid & 3;
    const int lane15 = lane & 15, lane16 = lane >> 4;
    const int g = lane >> 2, l4 = lane & 3;
    const int bx = (int)blockIdx.x;

    for (int f = tid; f < 4608; f += 256) {
        int r = f / 24, c = f % 24;
        cp_async16(b_u32 + swz(r, c), W + (size_t)r * 192 + c * 8);
    }
    CP_COMMIT();

    const int nmine = (NT96 - bx + GRID2 - 1) / GRID2;

    for (int ti = 0; ti < nmine; ti++) {
        const int t = bx + ti * GRID2;
        #pragma unroll
        for (int u = 0; u < 9; u++) {
            int f = tid + u * 256;
            int r = f / 24, c = f % 24;
            const float4* xp = (const float4*)(X + (size_t)(t * 96 + r) * 192 + c * 8);
            float4 a0 = xp[0], a1 = xp[1];
            uint4 o;
            o.x = pk2(a0.x, a0.y); o.y = pk2(a0.z, a0.w);
            o.z = pk2(a1.x, a1.y); o.w = pk2(a1.z, a1.w);
            *(uint4*)(As + swz(r, c)) = o;
        }
        if (ti == 0) CP_WAIT0();
        __syncthreads();

        float acc[3][6][4];
        #pragma unroll
        for (int mt = 0; mt < 3; mt++)
            #pragma unroll
            for (int nt = 0; nt < 6; nt++)
                #pragma unroll
                for (int i = 0; i < 4; i++) acc[mt][nt][i] = 0.f;

        #pragma unroll
        for (int kc = 0; kc < 12; kc++) {
            uint32_t a[3][4];
            #pragma unroll
            for (int mt = 0; mt < 3; mt++)
                ldsm_x4(a[mt], a_u32 + swz(wy * 48 + mt * 16 + lane15, kc * 2 + lane16));
            const int krow = kc * 16 + lane15;
            #pragma unroll
            for (int t16 = 0; t16 < 3; t16++) {
                uint32_t B[4];
                ldsm_x4_t(B, b_u32 + swz(krow, wx * 6 + t16 * 2 + lane16));
                #pragma unroll
                for (int mt = 0; mt < 3; mt++) {
                    mma_bf16(acc[mt][2 * t16],     a[mt], B + 0);
                    mma_bf16(acc[mt][2 * t16 + 1], a[mt], B + 2);
                }
            }
        }
        __syncthreads();

        const int row0 = t * 96;
        #pragma unroll
        for (int mt = 0; mt < 3; mt++)
            #pragma unroll
            for (int half = 0; half < 2; half++) {
                const int row = row0 + wy * 48 + mt * 16 + g + half * 8;
                bf16* cp = C + (size_t)row * 192;
                #pragma unroll
                for (int t16 = 0; t16 < 3; t16++)
                    #pragma unroll
                    for (int b8 = 0; b8 < 2; b8++) {
                        const int col = wx * 48 + t16 * 16 + b8 * 8 + 2 * l4;
                        float ox = acc[mt][2 * t16 + b8][half * 2 + 0] + __ldg(bias + col);
                        float oy = acc[mt][2 * t16 + b8][half * 2 + 1] + __ldg(bias + col + 1);
                        __nv_bfloat162 o = __floats2bfloat162_rn(ox, oy);
                        *(__nv_bfloat162*)(cp + col) = o;
                    }
            }
    }
}

// ============ O-proj + residual + LN1 (natural order) ============
__global__ void __launch_bounds__(256, 2)
gemm_oln(const bf16* __restrict__ A, const bf16* __restrict__ W,
         const float* __restrict__ bias, const float* __restrict__ xres,
         const float* __restrict__ lnw, const float* __restrict__ lnb,
         float* __restrict__ Xf, bf16* __restrict__ Xh)
{
    extern __shared__ __align__(16) char smem[];
    const uint32_t smem_u32 = (uint32_t)__cvta_generic_to_shared(smem);
    const uint32_t b_u32 = smem_u32;
    const uint32_t a_u32 = smem_u32 + 73728u;
    __shared__ float rs[96], rq[96];

    const int tid = threadIdx.x, lane = tid & 31, wid = tid >> 5;
    const int wy = wid >> 2, wx = wid & 3;
    const int lane15 = lane & 15, lane16 = lane >> 4;
    const int g = lane >> 2, l4 = lane & 3;
    const int bx = (int)blockIdx.x;

    for (int f = tid; f < 4608; f += 256) {
        int r = f / 24, c = f % 24;
        cp_async16(b_u32 + swz(r, c), W + (size_t)r * 192 + c * 8);
    }
    auto loadA = [&](int t) {
        #pragma unroll
        for (int u = 0; u < 9; u++) {
            int f = tid + u * 256;
            int r = f / 24, c = f % 24;
            cp_async16(a_u32 + swz(r, c), A + (size_t)(t * 96 + r) * 192 + c * 8);
        }
    };

    const int nmine = (NT96 - bx + GRID2 - 1) / GRID2;
    loadA(bx);
    CP_COMMIT();

    for (int ti = 0; ti < nmine; ti++) {
        const int t = bx + ti * GRID2;
        CP_WAIT0();
        __syncthreads();
        if (tid < 96) { rs[tid] = 0.f; rq[tid] = 0.f; }

        float acc[3][6][4];
        #pragma unroll
        for (int mt = 0; mt < 3; mt++)
            #pragma unroll
            for (int nt = 0; nt < 6; nt++)
                #pragma unroll
                for (int i = 0; i < 4; i++) acc[mt][nt][i] = 0.f;

        #pragma unroll
        for (int kc = 0; kc < 12; kc++) {
            uint32_t a[3][4];
            #pragma unroll
            for (int mt = 0; mt < 3; mt++)
                ldsm_x4(a[mt], a_u32 + swz(wy * 48 + mt * 16 + lane15, kc * 2 + lane16));
            const int krow = kc * 16 + lane15;
            #pragma unroll
            for (int t16 = 0; t16 < 3; t16++) {
                uint32_t B[4];
                ldsm_x4_t(B, b_u32 + swz(krow, wx * 6 + t16 * 2 + lane16));
                #pragma unroll
                for (int mt = 0; mt < 3; mt++) {
                    mma_bf16(acc[mt][2 * t16],     a[mt], B + 0);
                    mma_bf16(acc[mt][2 * t16 + 1], a[mt], B + 2);
                }
            }
        }
        __syncthreads();

        if (ti + 1 < nmine) loadA(bx + (ti + 1) * GRID2);
        CP_COMMIT();

        const int row0 = t * 96;
        #pragma unroll
        for (int mt = 0; mt < 3; mt++)
            #pragma unroll
            for (int half = 0; half < 2; half++) {
                const int row = row0 + wy * 48 + mt * 16 + g + half * 8;
                const float* xp = xres + (size_t)row * 192;
                float sv = 0.f, qv = 0.f;
                #pragma unroll
                for (int t16 = 0; t16 < 3; t16++)
                    #pragma unroll
                    for (int b8 = 0; b8 < 2; b8++) {
                        const int col = wx * 48 + t16 * 16 + b8 * 8 + 2 * l4;
                        float2 xv = *(const float2*)(xp + col);
                        float v0 = acc[mt][2 * t16 + b8][half * 2 + 0] + __ldg(bias + col) + xv.x;
                        float v1 = acc[mt][2 * t16 + b8][half * 2 + 1] + __ldg(bias + col + 1) + xv.y;
                        acc[mt][2 * t16 + b8][half * 2 + 0] = v0;
                        acc[mt][2 * t16 + b8][half * 2 + 1] = v1;
                        sv += v0 + v1;
                        qv += v0 * v0 + v1 * v1;
                    }
                sv += __shfl_xor_sync(0xffffffffu, sv, 1);
                qv += __shfl_xor_sync(0xffffffffu, qv, 1);
                sv += __shfl_xor_sync(0xffffffffu, sv, 2);
                qv += __shfl_xor_sync(0xffffffffu, qv, 2);
                if (l4 == 0) {
                    const int rloc = wy * 48 + mt * 16 + g + half * 8;
                    atomicAdd(&rs[rloc], sv);
                    atomicAdd(&rq[rloc], qv);
                }
            }
        __syncthreads();
        #pragma unroll
        for (int mt = 0; mt < 3; mt++)
            #pragma unroll
            for (int half = 0; half < 2; half++) {
                const int rloc = wy * 48 + mt * 16 + g + half * 8;
                const int row = row0 + rloc;
                const float mean = rs[rloc] * (1.f / 192.f);
                const float inv  = rsqrtf(rq[rloc] * (1.f / 192.f) - mean * mean + 1e-5f);
                float* xo = Xf + (size_t)row * 192;
                bf16*  xh = Xh + (size_t)row * 192;
                #pragma unroll
                for (int t16 = 0; t16 < 3; t16++)
                    #pragma unroll
                    for (int b8 = 0; b8 < 2; b8++) {
                        const int col = wx * 48 + t16 * 16 + b8 * 8 + 2 * l4;
                        float v0 = acc[mt][2 * t16 + b8][half * 2 + 0];
                        float v1 = acc[mt][2 * t16 + b8][half * 2 + 1];
                        float o0 = (v0 - mean) * inv * __ldg(lnw + col) + __ldg(lnb + col);
                        float o1 = (v1 - mean) * inv * __ldg(lnw + col + 1) + __ldg(lnb + col + 1);
                        float2 of; of.x = o0; of.y = o1;
                        *(float2*)(xo + col) = of;
                        __nv_bfloat162 ob = __floats2bfloat162_rn(o0, o1);
                        *(__nv_bfloat162*)(xh + col) = ob;
                    }
            }
    }
}

// ============ FFN1 halves: bf16 A via cp.async, GELU epilogue ============
__global__ void __launch_bounds__(256, 2)
gemm_ffn1(const bf16* __restrict__ A, const bf16* __restrict__ W,
          const float* __restrict__ bias, bf16* __restrict__ C, int coff)
{
    extern __shared__ __align__(16) char smem[];
    const uint32_t smem_u32 = (uint32_t)__cvta_generic_to_shared(smem);
    const uint32_t b_u32 = smem_u32;
    const uint32_t a_u32 = smem_u32 + 73728u;

    const int tid = threadIdx.x, lane = tid & 31, wid = tid >> 5;
    const int wy = wid >> 2, wx = wid & 3;
    const int lane15 = lane & 15, lane16 = lane >> 4;
    const int g = lane >> 2, l4 = lane & 3;
    const int bx = (int)blockIdx.x;

    for (int f = tid; f < 4608; f += 256) {
        int r = f / 24, c = f % 24;
        cp_async16(b_u32 + swz(r, c), W + (size_t)r * 192 + c * 8);
    }
    auto loadA = [&](int t) {
        #pragma unroll
        for (int u = 0; u < 9; u++) {
            int f = tid + u * 256;
            int r = f / 24, c = f % 24;
            cp_async16(a_u32 + swz(r, c), A + (size_t)(t * 96 + r) * 192 + c * 8);
        }
    };

    const int nmine = (NT96 - bx + GRID2 - 1) / GRID2;
    loadA(bx);
    CP_COMMIT();

    for (int ti = 0; ti < nmine; ti++) {
        const int t = bx + ti * GRID2;
        CP_WAIT0();
        __syncthreads();

        float acc[3][6][4];
        #pragma unroll
        for (int mt = 0; mt < 3; mt++)
            #pragma unroll
            for (int nt = 0; nt < 6; nt++)
                #pragma unroll
                for (int i = 0; i < 4; i++) acc[mt][nt][i] = 0.f;

        #pragma unroll
        for (int kc = 0; kc < 12; kc++) {
            uint32_t a[3][4];
            #pragma unroll
            for (int mt = 0; mt < 3; mt++)
                ldsm_x4(a[mt], a_u32 + swz(wy * 48 + mt * 16 + lane15, kc * 2 + lane16));
            const int krow = kc * 16 + lane15;
            #pragma unroll
            for (int t16 = 0; t16 < 3; t16++) {
                uint32_t B[4];
                ldsm_x4_t(B, b_u32 + swz(krow, wx * 6 + t16 * 2 + lane16));
                #pragma unroll
                for (int mt = 0; mt < 3; mt++) {
                    mma_bf16(acc[mt][2 * t16],     a[mt], B + 0);
                    mma_bf16(acc[mt][2 * t16 + 1], a[mt], B + 2);
                }
            }
        }
        __syncthreads();

        if (ti + 1 < nmine) loadA(bx + (ti + 1) * GRID2);
        CP_COMMIT();

        const int row0 = t * 96;
        #pragma unroll
        for (int mt = 0; mt < 3; mt++)
            #pragma unroll
            for (int half = 0; half < 2; half++) {
                const int row = row0 + wy * 48 + mt * 16 + g + half * 8;
                bf16* cp = C + (size_t)row * 384 + coff;
                #pragma unroll
                for (int t16 = 0; t16 < 3; t16++)
                    #pragma unroll
                    for (int b8 = 0; b8 < 2; b8++) {
                        const int col = wx * 48 + t16 * 16 + b8 * 8 + 2 * l4;
                        float ox = acc[mt][2 * t16 + b8][half * 2 + 0] + __ldg(bias + col);
                        float oy = acc[mt][2 * t16 + b8][half * 2 + 1] + __ldg(bias + col + 1);
                        ox = gelu_tanh(ox); oy = gelu_tanh(oy);
                        __nv_bfloat162 o = __floats2bfloat162_rn(ox, oy);
                        *(__nv_bfloat162*)(cp + col) = o;
                    }
            }
    }
}

// ============ FFN2 (K=384) + residual + LN2 ============
__global__ void __launch_bounds__(384)
gemm_f2ln(const bf16* __restrict__ A,
          const bf16* __restrict__ W0, const bf16* __restrict__ W1,
          const float* __restrict__ bias, const float* __restrict__ xres,
          const float* __restrict__ lnw, const float* __restrict__ lnb,
          float* __restrict__ Out)
{
    extern __shared__ __align__(16) char smem[];
    const uint32_t smem_u32 = (uint32_t)__cvta_generic_to_shared(smem);
    const uint32_t b_u32[2] = { smem_u32, smem_u32 + 73728u };
    const uint32_t a_u32    = smem_u32 + 147456u;
    __shared__ float sbias[192], slnw[192], slnb[192];
    __shared__ float rs[96], rq[96];

    const int tid = threadIdx.x, lane = tid & 31, wid = tid >> 5;
    const int wy = wid >> 2, wx = wid & 3;
    const int lane15 = lane & 15, lane16 = lane >> 4;
    const int g = lane >> 2, l4 = lane & 3;
    const int bx = (int)blockIdx.x;

    if (tid < 192) { sbias[tid] = bias[tid]; slnw[tid] = lnw[tid]; slnb[tid] = lnb[tid]; }

    for (int f = tid; f < 4608; f += 384) {
        int r = f / 24, c = f % 24;
        cp_async16(b_u32[0] + swz(r, c), W0 + (size_t)r * 192 + c * 8);
        cp_async16(b_u32[1] + swz(r, c), W1 + (size_t)r * 192 + c * 8);
    }
    const int pr = tid >> 2, pc0 = (tid & 3) * 6;
    auto loadA = [&](int s, int buf) {
        const int t = bx + (s >> 1) * GRID, kh = s & 1;
        const bf16* src = A + (size_t)(t * 96 + pr) * 384 + kh * 192 + pc0 * 8;
        uint32_t dstb = a_u32 + buf * 36864u;
        #pragma unroll
        for (int u = 0; u < 6; u++)
            cp_async16(dstb + swz(pr, pc0 + u), src + u * 8);
    };

    const int nmine = (NT96 - bx + GRID - 1) / GRID;
    const int nst = nmine * 2;
    loadA(0, 0);
    CP_COMMIT();

    float acc[2][6][4];

    for (int s = 0; s < nst; s++) {
        const int kh = s & 1;
        if (s + 1 < nst) loadA(s + 1, (s + 1) & 1);
        CP_COMMIT();
        CP_WAIT1();
        __syncthreads();
        if (kh == 0) {
            if (tid < 96) { rs[tid] = 0.f; rq[tid] = 0.f; }
            #pragma unroll
            for (int mt = 0; mt < 2; mt++)
                #pragma unroll
                for (int nt = 0; nt < 6; nt++)
                    #pragma unroll
                    for (int i = 0; i < 4; i++) acc[mt][nt][i] = 0.f;
        }

        const uint32_t abuf = a_u32 + (uint32_t)((s & 1) * 36864);
        const uint32_t bb = b_u32[kh];
        #pragma unroll
        for (int kc = 0; kc < 12; kc++) {
            uint32_t a0[4], a1[4];
            ldsm_x4(a0, abuf + swz(wy * 32 + lane15,      kc * 2 + lane16));
            ldsm_x4(a1, abuf + swz(wy * 32 + 16 + lane15, kc * 2 + lane16));
            const int krow = kc * 16 + lane15;
            #pragma unroll
            for (int t16 = 0; t16 < 3; t16++) {
                uint32_t B[4];
                ldsm_x4_t(B, bb + swz(krow, wx * 6 + t16 * 2 + lane16));
                mma_bf16(acc[0][2 * t16],     a0, B + 0);
                mma_bf16(acc[0][2 * t16 + 1], a0, B + 2);
                mma_bf16(acc[1][2 * t16],     a1, B + 0);
                mma_bf16(acc[1][2 * t16 + 1], a1, B + 2);
            }
        }
        __syncthreads();

        if (kh == 1) {
            const int row0 = (bx + (s >> 1) * GRID) * 96;
            #pragma unroll
            for (int mt = 0; mt < 2; mt++)
                #pragma unroll
                for (int half = 0; half < 2; half++) {
                    const int row = row0 + wy * 32 + mt * 16 + g + half * 8;
                    const float* xp = xres + (size_t)row * 192;
                    float sv = 0.f, qv = 0.f;
                    #pragma unroll
                    for (int t16 = 0; t16 < 3; t16++)
                        #pragma unroll
                        for (int b8 = 0; b8 < 2; b8++) {
                            const int col = wx * 48 + t16 * 16 + b8 * 8 + 2 * l4;
                            float2 xv = *(const float2*)(xp + col);
                            float v0 = acc[mt][2 * t16 + b8][half * 2 + 0] + sbias[col] + xv.x;
                            float v1 = acc[mt][2 * t16 + b8][half * 2 + 1] + sbias[col + 1] + xv.y;
                            acc[mt][2 * t16 + b8][half * 2 + 0] = v0;
                            acc[mt][2 * t16 + b8][half * 2 + 1] = v1;
                            sv += v0 + v1; qv += v0 * v0 + v1 * v1;
                        }
                    sv += __shfl_xor_sync(0xffffffffu, sv, 1);
                    qv += __shfl_xor_sync(0xffffffffu, qv, 1);
                    sv += __shfl_xor_sync(0xffffffffu, sv, 2);
                    qv += __shfl_xor_sync(0xffffffffu, qv, 2);
                    if (l4 == 0) {
                        const int rloc = wy * 32 + mt * 16 + g + half * 8;
                        atomicAdd(&rs[rloc], sv);
                        atomicAdd(&rq[rloc], qv);
                    }
                }
            __syncthreads();
            #pragma unroll
            for (int mt = 0; mt < 2; mt++)
                #pragma unroll
                for (int half = 0; half < 2; half++) {
                    const int rloc = wy * 32 + mt * 16 + g + half * 8;
                    const int row = row0 + rloc;
                    const float mean = rs[rloc] * (1.f / 192.f);
                    const float inv  = rsqrtf(rq[rloc] * (1.f / 192.f) - mean * mean + 1e-5f);
                    float* op = Out + (size_t)row * 192;
                    #pragma unroll
                    for (int t16 = 0; t16 < 3; t16++)
                        #pragma unroll
                        for (int b8 = 0; b8 < 2; b8++) {
                            const int col = wx * 48 + t16 * 16 + b8 * 8 + 2 * l4;
                            float v0 = acc[mt][2 * t16 + b8][half * 2 + 0];
                            float v1 = acc[mt][2 * t16 + b8][half * 2 + 1];
                            float2 of;
                            of.x = (v0 - mean) * inv * slnw[col] + slnb[col];
                            of.y = (v1 - mean) * inv * slnw[col + 1] + slnb[col + 1];
                            *(float2*)(op + col) = of;
                        }
                }
        }
    }
}

// ================= tensor-core set attention (v3: Q frags from global, K/V in smem) =================
// 1 set per block, 256 threads = 8 warps = 8 heads.
// K,V staged [8][48][40] bf16 (zero-padded). Q A-fragments loaded directly from
// global via the m16n8k16 lane mapping (rows>=36 read sidx[0]; k>=24 are zero).
#define HBUF 3840            // 48*40*2 bytes per head per buffer
#define AK_OFF 0
#define AV_OFF 30720
#define ATTN_SMEM 61440

__global__ void __launch_bounds__(256, 3)
attn_tc(const bf16* __restrict__ QK, const bf16* __restrict__ V,
        const int* __restrict__ gidx, bf16* __restrict__ O)
{
    extern __shared__ __align__(16) char smem[];
    const uint32_t smem_u32 = (uint32_t)__cvta_generic_to_shared(smem);
    __shared__ int sidx[36];

    const int s = blockIdx.x, tid = threadIdx.x;
    const int lane = tid & 31, h = tid >> 5;
    const int lane15 = lane & 15, lane16 = lane >> 4;
    const int g = lane >> 2, l4 = lane & 3;

    if (tid < 36) sidx[tid] = __ldg(gidx + s * SETS + tid);
    for (int i = tid; i < ATTN_SMEM / 16; i += 256)
        *(uint4*)(smem + i * 16) = make_uint4(0, 0, 0, 0);
    __syncthreads();

    // stage K, V: 864 = 8 heads * 36 keys * 3 chunks
    for (int f = tid; f < 864; f += 256) {
        int hh = f / 108, r = f % 108;
        int key = r / 3, c = r % 3;
        int grow = sidx[key];
        uint4 k = *(const uint4*)(QK + (size_t)grow * 384 + 192 + hh * 24 + c * 8);
        *(uint4*)(smem + AK_OFF + hh * HBUF + (key * 40 + c * 8) * 2) = k;
        uint4 v = *(const uint4*)(V + (size_t)grow * 192 + hh * 24 + c * 8);
        *(uint4*)(smem + AV_OFF + hh * HBUF + (key * 40 + c * 8) * 2) = v;
    }

    // ---- Q A-fragments straight from global ----
    // A0[mt] = k 0..15 frag; A1[mt] = k 16..31 frag (upper half zero: k>=24).
    uint32_t A0[3][4], A1[3][4];
    #pragma unroll
    for (int mt = 0; mt < 3; mt++) {
        const int r0 = mt * 16 + g, r1 = r0 + 8;
        const int gr0 = sidx[(r0 < 36) ? r0 : 0];
        const int gr1 = sidx[(r1 < 36) ? r1 : 0];
        const bf16* q0 = QK + (size_t)gr0 * 384 + h * 24;
        const bf16* q1 = QK + (size_t)gr1 * 384 + h * 24;
        A0[mt][0] = *(const uint32_t*)(q0 + 2 * l4);
        A0[mt][1] = *(const uint32_t*)(q1 + 2 * l4);
        A0[mt][2] = *(const uint32_t*)(q0 + 2 * l4 + 8);
        A0[mt][3] = *(const uint32_t*)(q1 + 2 * l4 + 8);
        A1[mt][0] = *(const uint32_t*)(q0 + 2 * l4 + 16);
        A1[mt][1] = *(const uint32_t*)(q1 + 2 * l4 + 16);
        A1[mt][2] = 0;
        A1[mt][3] = 0;
    }
    __syncthreads();

    const uint32_t kb = smem_u32 + AK_OFF + (uint32_t)(h * HBUF);
    const uint32_t vb = smem_u32 + AV_OFF + (uint32_t)(h * HBUF);

    // ---- S = Q @ K^T (3 m16 x 3 n16, K=32) ----
    float S[3][6][4];
    #pragma unroll
    for (int mt = 0; mt < 3; mt++)
        #pragma unroll
        for (int nt = 0; nt < 6; nt++)
            #pragma unroll
            for (int i = 0; i < 4; i++) S[mt][nt][i] = 0.f;

    #pragma unroll
    for (int kc = 0; kc < 2; kc++) {
        #pragma unroll
        for (int nt2 = 0; nt2 < 3; nt2++) {
            uint32_t Br[4];
            ldsm_x4(Br, kb + (uint32_t)(((nt2 * 16 + lane15) * 40 + kc * 16 + lane16 * 8) * 2));
            #pragma unroll
            for (int mt = 0; mt < 3; mt++) {
                const uint32_t* a = (kc == 0) ? A0[mt] : A1[mt];
                mma_bf16_2(S[mt][2 * nt2],     a, Br[0], Br[2]);   // n-lo
                mma_bf16_2(S[mt][2 * nt2 + 1], a, Br[1], Br[3]);   // n-hi
            }
        }
    }

    // ---- masked softmax on fragments ----
    const float scale = 0.20412414523193154f;   // 1/sqrt(24)
    float inv_[3][2];
    #pragma unroll
    for (int mt = 0; mt < 3; mt++) {
        #pragma unroll
        for (int half = 0; half < 2; half++) {
            float mx = -1e30f;
            #pragma unroll
            for (int nt = 0; nt < 6; nt++) {
                #pragma unroll
                for (int cc = 0; cc < 2; cc++) {
                    const int col = nt * 8 + l4 * 2 + cc;
                    float v = (col < 36) ? S[mt][nt][half * 2 + cc] * scale : -1e30f;
                    S[mt][nt][half * 2 + cc] = v;
                    mx = fmaxf(mx, v);
                }
            }
            mx = fmaxf(mx, __shfl_xor_sync(0xffffffffu, mx, 1));
            mx = fmaxf(mx, __shfl_xor_sync(0xffffffffu, mx, 2));
            float sum = 0.f;
            #pragma unroll
            for (int nt = 0; nt < 6; nt++) {
                #pragma unroll
                for (int cc = 0; cc < 2; cc++) {
                    float e = __expf(S[mt][nt][half * 2 + cc] - mx);
                    S[mt][nt][half * 2 + cc] = e;
                    sum += e;
                }
            }
            sum += __shfl_xor_sync(0xffffffffu, sum, 1);
            sum += __shfl_xor_sync(0xffffffffu, sum, 2);
            inv_[mt][half] = 1.f / sum;
        }
    }

    // ---- pack P to bf16 A-fragments (keys kt*16..+15) ----
    uint32_t P[3][3][4];
    #pragma unroll
    for (int mt = 0; mt < 3; mt++)
        #pragma unroll
        for (int kt = 0; kt < 3; kt++) {
            P[mt][kt][0] = pk2(S[mt][2 * kt][0],     S[mt][2 * kt][1]);
            P[mt][kt][1] = pk2(S[mt][2 * kt][2],     S[mt][2 * kt][3]);
            P[mt][kt][2] = pk2(S[mt][2 * kt + 1][0], S[mt][2 * kt + 1][1]);
            P[mt][kt][3] = pk2(S[mt][2 * kt + 1][2], S[mt][2 * kt + 1][3]);
        }

    // ---- O = P @ V (3 m16 x 2 n16, K=48) ----
    float Oa[3][4][4];
    #pragma unroll
    for (int mt = 0; mt < 3; mt++)
        #pragma unroll
        for (int nt = 0; nt < 4; nt++)
            #pragma unroll
            for (int i = 0; i < 4; i++) Oa[mt][nt][i] = 0.f;

    #pragma unroll
    for (int kt = 0; kt < 3; kt++) {
        #pragma unroll
        for (int nt2 = 0; nt2 < 2; nt2++) {
            uint32_t B[4];
            ldsm_x4_t(B, vb + (uint32_t)(((kt * 16 + lane15) * 40 + nt2 * 16 + lane16 * 8) * 2));
            #pragma unroll
            for (int mt = 0; mt < 3; mt++) {
                mma_bf16(Oa[mt][2 * nt2],     P[mt][kt], B + 0);
                mma_bf16(Oa[mt][2 * nt2 + 1], P[mt][kt], B + 2);
            }
        }
    }

    // ---- store (rows < 36, dims < 24), normalize by rowsum ----
    #pragma unroll
    for (int mt = 0; mt < 3; mt++)
        #pragma unroll
        for (int half = 0; half < 2; half++) {
            const int row = mt * 16 + g + half * 8;
            if (row >= 36) continue;
            const int grow = sidx[row];
            const float inv = inv_[mt][half];
            bf16* op = O + (size_t)grow * 192 + h * 24;
            #pragma unroll
            for (int nt = 0; nt < 3; nt++) {
                const int col = nt * 8 + l4 * 2;
                __nv_bfloat162 o = __floats2bfloat162_rn(
                    Oa[mt][nt][half * 2 + 0] * inv, Oa[mt][nt][half * 2 + 1] * inv);
                *(__nv_bfloat162*)(op + col) = o;
            }
        }
}

// ---------------- host ----------------
extern "C" void kernel_launch(void* const* d_in, const int* in_sizes, int n_in,
                              void* d_out, int out_size)
{
    (void)in_sizes; (void)n_in; (void)out_size;
    const float* src    = (const float*)d_in[0];
    const float* pos    = (const float*)d_in[1];
    const float* qkv_w  = (const float*)d_in[2];
    const float* qkv_b  = (const float*)d_in[3];
    const float* out_w  = (const float*)d_in[4];
    const float* out_b  = (const float*)d_in[5];
    const float* ln_w   = (const float*)d_in[6];
    const float* ln_b   = (const float*)d_in[7];
    const float* w1     = (const float*)d_in[8];
    const float* b1     = (const float*)d_in[9];
    const float* w2     = (const float*)d_in[10];
    const float* b2     = (const float*)d_in[11];
    const int*   inds   = (const int*)d_in[12];
    float*       outp   = (float*)d_out;

    bf16 *QKh, *Vh, *Oh, *Hh, *Xh, *Wh;
    float *Xb;
    cudaGetSymbolAddress((void**)&QKh, g_QKh);
    cudaGetSymbolAddress((void**)&Vh,  g_Vh);
    cudaGetSymbolAddress((void**)&Oh,  g_Oh);
    cudaGetSymbolAddress((void**)&Hh,  g_Hh);
    cudaGetSymbolAddress((void**)&Xh,  g_Xh);
    cudaGetSymbolAddress((void**)&Xb,  g_X);
    cudaGetSymbolAddress((void**)&Wh,  g_Wh);

    cudaFuncSetAttribute(attn_tc, cudaFuncAttributeMaxDynamicSharedMemorySize, ATTN_SMEM);

    const int sm_qk  = 2 * 73728 + 36864;              // 184320 (1 CTA/SM)
    const int sm_one = 73728 + 36864;                  // 110592 (2 CTAs/SM)
    const int sm_f2  = 2 * 73728 + 2 * 36864;          // 221184 (1 CTA/SM)
    cudaFuncSetAttribute((const void*)gemm_qk,
                         cudaFuncAttributeMaxDynamicSharedMemorySize, sm_qk);
    cudaFuncSetAttribute((const void*)gemm_v,
                         cudaFuncAttributeMaxDynamicSharedMemorySize, sm_one);
    cudaFuncSetAttribute((const void*)gemm_oln,
                         cudaFuncAttributeMaxDynamicSharedMemorySize, sm_one);
    cudaFuncSetAttribute((const void*)gemm_ffn1,
                         cudaFuncAttributeMaxDynamicSharedMemorySize, sm_one);
    cudaFuncSetAttribute((const void*)gemm_f2ln,
                         cudaFuncAttributeMaxDynamicSharedMemorySize, sm_f2);

    // pack both layers once
    pack_kernel<<<(2 * 294912 + 255) / 256, 256>>>(qkv_w, out_w, w1, w2);

    for (int l = 0; l < NL; l++) {
        const float* xin = (l == 0) ? src : Xb;
        const int*   idx = inds + (size_t)l * NV;
        const float* pel = pos  + (size_t)l * NV * DM;
        const float* qb  = qkv_b + (size_t)l * 3 * DM;
        bf16* Wl = Wh + (size_t)l * 294912;

        gemm_qk<<<GRID, 384, sm_qk>>>(xin, pel, Wl + 0 * 36864, Wl + 1 * 36864, qb, QKh);
        gemm_v<<<GRID2, 256, sm_one>>>(xin, Wl + 2 * 36864, qb + 384, Vh);

        attn_tc<<<NSET, 256, ATTN_SMEM>>>(QKh, Vh, idx, Oh);

        gemm_oln<<<GRID2, 256, sm_one>>>(Oh, Wl + 3 * 36864, out_b + (size_t)l * DM, xin,
                                         ln_w + (size_t)(l * 2) * DM, ln_b + (size_t)(l * 2) * DM,
                                         Xb, Xh);

        gemm_ffn1<<<GRID2, 256, sm_one>>>(Xh, Wl + 4 * 36864, b1 + (size_t)l * DFF, Hh, 0);
        gemm_ffn1<<<GRID2, 256, sm_one>>>(Xh, Wl + 5 * 36864, b1 + (size_t)l * DFF + 192, Hh, 192);

        float* lnout = (l == NL - 1) ? outp : Xb;
        gemm_f2ln<<<GRID, 384, sm_f2>>>(Hh, Wl + 6 * 36864, Wl + 7 * 36864,
                                        b2 + (size_t)l * DM, Xb,
                                        ln_w + (size_t)(l * 2 + 1) * DM,
                                        ln_b + (size_t)(l * 2 + 1) * DM, lnout);
    }
}

// round 15
// speedup vs baseline: 1.5042x; 1.0117x over previous
#include <cuda_runtime.h>
#include <cuda_bf16.h>
#include <math.h>
#include <stdint.h>

#define NV   262080
#define DM   192
#define DFF  384
#define SETS 36
#define NSET 7280
#define NL   2
#define GRID 148
#define GRID2 296
#define NT96 2730          // NV / 96 exactly

typedef __nv_bfloat16 bf16;

// ---------------- scratch (device globals) ----------------
__device__ bf16 g_QKh[(size_t)NV * 384];   // Q|K natural order
__device__ bf16 g_Vh [(size_t)NV * 192];   // V natural order
__device__ bf16 g_Oh [(size_t)NV * 192];   // bf16(x) during QKV; attention out after
__device__ bf16 g_Hh [(size_t)NV * 384];   // FFN hidden
__device__ bf16 g_Xh [(size_t)NV * 192];   // LN1 bf16 out (FFN1 input)
__device__ float g_X[(size_t)NV * 192];    // running x (fp32)
__device__ bf16 g_Wh[2 * 294912];          // per-layer: 8 blocks of [k:192][n:192]

__device__ __forceinline__ float gelu_tanh(float x) {
    float x3 = x * x * x;
    return 0.5f * x * (1.0f + tanhf(0.7978845608028654f * (x + 0.044715f * x3)));
}
__device__ __forceinline__ uint32_t pk2(float a, float b) {
    __nv_bfloat162 t = __floats2bfloat162_rn(a, b);
    return *(uint32_t*)&t;
}
__device__ __forceinline__ void ldsm_x4(uint32_t r[4], uint32_t addr) {
    asm volatile("ldmatrix.sync.aligned.m8n8.x4.shared.b16 {%0,%1,%2,%3}, [%4];"
                 : "=r"(r[0]), "=r"(r[1]), "=r"(r[2]), "=r"(r[3]) : "r"(addr));
}
__device__ __forceinline__ void ldsm_x4_t(uint32_t r[4], uint32_t addr) {
    asm volatile("ldmatrix.sync.aligned.m8n8.x4.trans.shared.b16 {%0,%1,%2,%3}, [%4];"
                 : "=r"(r[0]), "=r"(r[1]), "=r"(r[2]), "=r"(r[3]) : "r"(addr));
}
__device__ __forceinline__ void mma_bf16(float c[4], const uint32_t a[4], const uint32_t* b) {
    asm volatile(
        "mma.sync.aligned.m16n8k16.row.col.f32.bf16.bf16.f32 "
        "{%0,%1,%2,%3}, {%4,%5,%6,%7}, {%8,%9}, {%0,%1,%2,%3};"
        : "+f"(c[0]), "+f"(c[1]), "+f"(c[2]), "+f"(c[3])
        : "r"(a[0]), "r"(a[1]), "r"(a[2]), "r"(a[3]), "r"(b[0]), "r"(b[1]));
}
__device__ __forceinline__ void mma_bf16_2(float c[4], const uint32_t a[4],
                                           uint32_t b0, uint32_t b1) {
    asm volatile(
        "mma.sync.aligned.m16n8k16.row.col.f32.bf16.bf16.f32 "
        "{%0,%1,%2,%3}, {%4,%5,%6,%7}, {%8,%9}, {%0,%1,%2,%3};"
        : "+f"(c[0]), "+f"(c[1]), "+f"(c[2]), "+f"(c[3])
        : "r"(a[0]), "r"(a[1]), "r"(a[2]), "r"(a[3]), "r"(b0), "r"(b1));
}
__device__ __forceinline__ void cp_async16(uint32_t dst, const void* src) {
    asm volatile("cp.async.ca.shared.global [%0], [%1], 16;" :: "r"(dst), "l"(src));
}
#define CP_COMMIT() asm volatile("cp.async.commit_group;")
#define CP_WAIT0()  asm volatile("cp.async.wait_group 0;" ::: "memory")
#define CP_WAIT1()  asm volatile("cp.async.wait_group 1;" ::: "memory")

// XOR-swizzled smem offset: rows x 192 bf16 cols (384B row), 24 16B-chunks/row
__device__ __forceinline__ uint32_t swz(int row, int chunk) {
    return (uint32_t)(row * 384 + ((chunk ^ (row & 7)) << 4));
}

// ---------------- weight pack: both layers ----------------
__global__ void pack_kernel(const float* __restrict__ qkv_w, const float* __restrict__ out_w,
                            const float* __restrict__ w1, const float* __restrict__ w2) {
    int gi = blockIdx.x * 256 + threadIdx.x;
    if (gi >= 2 * 294912) return;
    int l = gi / 294912, i = gi % 294912;
    int blk = i / 36864, j = i % 36864;
    int k = j / 192, n = j % 192;
    float v;
    if (blk < 3)       v = qkv_w[(size_t)(l * 3 + blk) * 36864 + k * 192 + n];
    else if (blk == 3) v = out_w[(size_t)l * 36864 + k * 192 + n];
    else if (blk == 4) v = w1[(size_t)l * 73728 + k * 384 + n];
    else if (blk == 5) v = w1[(size_t)l * 73728 + k * 384 + 192 + n];
    else if (blk == 6) v = w2[(size_t)l * 73728 + k * 192 + n];
    else               v = w2[(size_t)l * 73728 + (192 + k) * 192 + n];
    g_Wh[gi] = __float2bfloat16(v);
}

// ============ QK dual-B GEMM: also emits bf16(x) to Xout ============
__global__ void __launch_bounds__(384)
gemm_qk(const float* __restrict__ X, const float* __restrict__ POS,
        const bf16* __restrict__ W0, const bf16* __restrict__ W1,
        const float* __restrict__ bias, bf16* __restrict__ C, bf16* __restrict__ Xout)
{
    extern __shared__ __align__(16) char smem[];
    const uint32_t smem_u32 = (uint32_t)__cvta_generic_to_shared(smem);
    const uint32_t b_u32[2] = { smem_u32, smem_u32 + 73728u };
    char* As = smem + 147456;
    __shared__ float sbias[384];

    const int tid = threadIdx.x, lane = tid & 31, wid = tid >> 5;
    const int wy = wid >> 2, wx = wid & 3;
    const int lane15 = lane & 15, lane16 = lane >> 4;
    const int g = lane >> 2, l4 = lane & 3;
    const int bx = (int)blockIdx.x;
    const uint32_t a_u32 = smem_u32 + 147456u;

    if (tid < 384) sbias[tid] = bias[tid];

    for (int f = tid; f < 4608; f += 384) {
        int r = f / 24, c = f % 24;
        cp_async16(b_u32[0] + swz(r, c), W0 + (size_t)r * 192 + c * 8);
        cp_async16(b_u32[1] + swz(r, c), W1 + (size_t)r * 192 + c * 8);
    }
    CP_COMMIT();

    const int nmine = (NT96 - bx + GRID - 1) / GRID;

    for (int ti = 0; ti < nmine; ti++) {
        const int t = bx + ti * GRID;
        #pragma unroll
        for (int u = 0; u < 6; u++) {
            int f = tid + u * 384;
            int r = f / 24, c = f % 24;
            const float4* xp = (const float4*)(X   + (size_t)(t * 96 + r) * 192 + c * 8);
            const float4* pp = (const float4*)(POS + (size_t)(t * 96 + r) * 192 + c * 8);
            float4 a0 = xp[0], a1 = xp[1], p0 = pp[0], p1 = pp[1];
            // bf16(x) -> Xout (consumed by V GEMM; saves a second fp32 X pass)
            uint4 xv;
            xv.x = pk2(a0.x, a0.y); xv.y = pk2(a0.z, a0.w);
            xv.z = pk2(a1.x, a1.y); xv.w = pk2(a1.z, a1.w);
            *((uint4*)(Xout + (size_t)(t * 96 + r) * 192 + c * 8)) = xv;
            a0.x += p0.x; a0.y += p0.y; a0.z += p0.z; a0.w += p0.w;
            a1.x += p1.x; a1.y += p1.y; a1.z += p1.z; a1.w += p1.w;
            uint4 o;
            o.x = pk2(a0.x, a0.y); o.y = pk2(a0.z, a0.w);
            o.z = pk2(a1.x, a1.y); o.w = pk2(a1.z, a1.w);
            *(uint4*)(As + swz(r, c)) = o;
        }
        if (ti == 0) CP_WAIT0();
        __syncthreads();

        float acc[2][2][6][4];
        #pragma unroll
        for (int m = 0; m < 2; m++)
            #pragma unroll
            for (int mt = 0; mt < 2; mt++)
                #pragma unroll
                for (int nt = 0; nt < 6; nt++)
                    #pragma unroll
                    for (int i = 0; i < 4; i++) acc[m][mt][nt][i] = 0.f;

        #pragma unroll
        for (int kc = 0; kc < 12; kc++) {
            uint32_t a0[4], a1[4];
            ldsm_x4(a0, a_u32 + swz(wy * 32 + lane15,      kc * 2 + lane16));
            ldsm_x4(a1, a_u32 + swz(wy * 32 + 16 + lane15, kc * 2 + lane16));
            const int krow = kc * 16 + lane15;
            #pragma unroll
            for (int m = 0; m < 2; m++) {
                #pragma unroll
                for (int t16 = 0; t16 < 3; t16++) {
                    uint32_t B[4];
                    ldsm_x4_t(B, b_u32[m] + swz(krow, wx * 6 + t16 * 2 + lane16));
                    mma_bf16(acc[m][0][2 * t16],     a0, B + 0);
                    mma_bf16(acc[m][0][2 * t16 + 1], a0, B + 2);
                    mma_bf16(acc[m][1][2 * t16],     a1, B + 0);
                    mma_bf16(acc[m][1][2 * t16 + 1], a1, B + 2);
                }
            }
        }
        __syncthreads();

        const int row0 = t * 96;
        #pragma unroll
        for (int m = 0; m < 2; m++)
            #pragma unroll
            for (int mt = 0; mt < 2; mt++)
                #pragma unroll
                for (int half = 0; half < 2; half++) {
                    const int row = row0 + wy * 32 + mt * 16 + g + half * 8;
                    bf16* cp = C + (size_t)row * 384 + m * 192;
                    #pragma unroll
                    for (int t16 = 0; t16 < 3; t16++)
                        #pragma unroll
                        for (int b8 = 0; b8 < 2; b8++) {
                            const int col = wx * 48 + t16 * 16 + b8 * 8 + 2 * l4;
                            float ox = acc[m][mt][2 * t16 + b8][half * 2 + 0] + sbias[m * 192 + col];
                            float oy = acc[m][mt][2 * t16 + b8][half * 2 + 1] + sbias[m * 192 + col + 1];
                            __nv_bfloat162 o = __floats2bfloat162_rn(ox, oy);
                            *(__nv_bfloat162*)(cp + col) = o;
                        }
                }
    }
}

// ============ generic bf16-A GEMM (V projection & FFN1 halves) ============
template<bool GELU>
__global__ void __launch_bounds__(256, 2)
gemm_bf(const bf16* __restrict__ A, const bf16* __restrict__ W,
        const float* __restrict__ bias, bf16* __restrict__ C, int ldc, int coff)
{
    extern __shared__ __align__(16) char smem[];
    const uint32_t smem_u32 = (uint32_t)__cvta_generic_to_shared(smem);
    const uint32_t b_u32 = smem_u32;
    const uint32_t a_u32 = smem_u32 + 73728u;

    const int tid = threadIdx.x, lane = tid & 31, wid = tid >> 5;
    const int wy = wid >> 2, wx = wid & 3;
    const int lane15 = lane & 15, lane16 = lane >> 4;
    const int g = lane >> 2, l4 = lane & 3;
    const int bx = (int)blockIdx.x;

    for (int f = tid; f < 4608; f += 256) {
        int r = f / 24, c = f % 24;
        cp_async16(b_u32 + swz(r, c), W + (size_t)r * 192 + c * 8);
    }
    auto loadA = [&](int t) {
        #pragma unroll
        for (int u = 0; u < 9; u++) {
            int f = tid + u * 256;
            int r = f / 24, c = f % 24;
            cp_async16(a_u32 + swz(r, c), A + (size_t)(t * 96 + r) * 192 + c * 8);
        }
    };

    const int nmine = (NT96 - bx + GRID2 - 1) / GRID2;
    loadA(bx);
    CP_COMMIT();

    for (int ti = 0; ti < nmine; ti++) {
        const int t = bx + ti * GRID2;
        CP_WAIT0();
        __syncthreads();

        float acc[3][6][4];
        #pragma unroll
        for (int mt = 0; mt < 3; mt++)
            #pragma unroll
            for (int nt = 0; nt < 6; nt++)
                #pragma unroll
                for (int i = 0; i < 4; i++) acc[mt][nt][i] = 0.f;

        #pragma unroll
        for (int kc = 0; kc < 12; kc++) {
            uint32_t a[3][4];
            #pragma unroll
            for (int mt = 0; mt < 3; mt++)
                ldsm_x4(a[mt], a_u32 + swz(wy * 48 + mt * 16 + lane15, kc * 2 + lane16));
            const int krow = kc * 16 + lane15;
            #pragma unroll
            for (int t16 = 0; t16 < 3; t16++) {
                uint32_t B[4];
                ldsm_x4_t(B, b_u32 + swz(krow, wx * 6 + t16 * 2 + lane16));
                #pragma unroll
                for (int mt = 0; mt < 3; mt++) {
                    mma_bf16(acc[mt][2 * t16],     a[mt], B + 0);
                    mma_bf16(acc[mt][2 * t16 + 1], a[mt], B + 2);
                }
            }
        }
        __syncthreads();

        if (ti + 1 < nmine) loadA(bx + (ti + 1) * GRID2);
        CP_COMMIT();

        const int row0 = t * 96;
        #pragma unroll
        for (int mt = 0; mt < 3; mt++)
            #pragma unroll
            for (int half = 0; half < 2; half++) {
                const int row = row0 + wy * 48 + mt * 16 + g + half * 8;
                bf16* cp = C + (size_t)row * ldc + coff;
                #pragma unroll
                for (int t16 = 0; t16 < 3; t16++)
                    #pragma unroll
                    for (int b8 = 0; b8 < 2; b8++) {
                        const int col = wx * 48 + t16 * 16 + b8 * 8 + 2 * l4;
                        float ox = acc[mt][2 * t16 + b8][half * 2 + 0] + __ldg(bias + col);
                        float oy = acc[mt][2 * t16 + b8][half * 2 + 1] + __ldg(bias + col + 1);
                        if (GELU) { ox = gelu_tanh(ox); oy = gelu_tanh(oy); }
                        __nv_bfloat162 o = __floats2bfloat162_rn(ox, oy);
                        *(__nv_bfloat162*)(cp + col) = o;
                    }
            }
    }
}

// ============ O-proj + residual + LN1 (natural order) ============
__global__ void __launch_bounds__(256, 2)
gemm_oln(const bf16* __restrict__ A, const bf16* __restrict__ W,
         const float* __restrict__ bias, const float* __restrict__ xres,
         const float* __restrict__ lnw, const float* __restrict__ lnb,
         float* __restrict__ Xf, bf16* __restrict__ Xh)
{
    extern __shared__ __align__(16) char smem[];
    const uint32_t smem_u32 = (uint32_t)__cvta_generic_to_shared(smem);
    const uint32_t b_u32 = smem_u32;
    const uint32_t a_u32 = smem_u32 + 73728u;
    __shared__ float rs[96], rq[96];

    const int tid = threadIdx.x, lane = tid & 31, wid = tid >> 5;
    const int wy = wid >> 2, wx = wid & 3;
    const int lane15 = lane & 15, lane16 = lane >> 4;
    const int g = lane >> 2, l4 = lane & 3;
    const int bx = (int)blockIdx.x;

    for (int f = tid; f < 4608; f += 256) {
        int r = f / 24, c = f % 24;
        cp_async16(b_u32 + swz(r, c), W + (size_t)r * 192 + c * 8);
    }
    auto loadA = [&](int t) {
        #pragma unroll
        for (int u = 0; u < 9; u++) {
            int f = tid + u * 256;
            int r = f / 24, c = f % 24;
            cp_async16(a_u32 + swz(r, c), A + (size_t)(t * 96 + r) * 192 + c * 8);
        }
    };

    const int nmine = (NT96 - bx + GRID2 - 1) / GRID2;
    loadA(bx);
    CP_COMMIT();

    for (int ti = 0; ti < nmine; ti++) {
        const int t = bx + ti * GRID2;
        CP_WAIT0();
        __syncthreads();
        if (tid < 96) { rs[tid] = 0.f; rq[tid] = 0.f; }

        float acc[3][6][4];
        #pragma unroll
        for (int mt = 0; mt < 3; mt++)
            #pragma unroll
            for (int nt = 0; nt < 6; nt++)
                #pragma unroll
                for (int i = 0; i < 4; i++) acc[mt][nt][i] = 0.f;

        #pragma unroll
        for (int kc = 0; kc < 12; kc++) {
            uint32_t a[3][4];
            #pragma unroll
            for (int mt = 0; mt < 3; mt++)
                ldsm_x4(a[mt], a_u32 + swz(wy * 48 + mt * 16 + lane15, kc * 2 + lane16));
            const int krow = kc * 16 + lane15;
            #pragma unroll
            for (int t16 = 0; t16 < 3; t16++) {
                uint32_t B[4];
                ldsm_x4_t(B, b_u32 + swz(krow, wx * 6 + t16 * 2 + lane16));
                #pragma unroll
                for (int mt = 0; mt < 3; mt++) {
                    mma_bf16(acc[mt][2 * t16],     a[mt], B + 0);
                    mma_bf16(acc[mt][2 * t16 + 1], a[mt], B + 2);
                }
            }
        }
        __syncthreads();

        if (ti + 1 < nmine) loadA(bx + (ti + 1) * GRID2);
        CP_COMMIT();

        const int row0 = t * 96;
        #pragma unroll
        for (int mt = 0; mt < 3; mt++)
            #pragma unroll
            for (int half = 0; half < 2; half++) {
                const int row = row0 + wy * 48 + mt * 16 + g + half * 8;
                const float* xp = xres + (size_t)row * 192;
                float sv = 0.f, qv = 0.f;
                #pragma unroll
                for (int t16 = 0; t16 < 3; t16++)
                    #pragma unroll
                    for (int b8 = 0; b8 < 2; b8++) {
                        const int col = wx * 48 + t16 * 16 + b8 * 8 + 2 * l4;
                        float2 xv = *(const float2*)(xp + col);
                        float v0 = acc[mt][2 * t16 + b8][half * 2 + 0] + __ldg(bias + col) + xv.x;
                        float v1 = acc[mt][2 * t16 + b8][half * 2 + 1] + __ldg(bias + col + 1) + xv.y;
                        acc[mt][2 * t16 + b8][half * 2 + 0] = v0;
                        acc[mt][2 * t16 + b8][half * 2 + 1] = v1;
                        sv += v0 + v1;
                        qv += v0 * v0 + v1 * v1;
                    }
                sv += __shfl_xor_sync(0xffffffffu, sv, 1);
                qv += __shfl_xor_sync(0xffffffffu, qv, 1);
                sv += __shfl_xor_sync(0xffffffffu, sv, 2);
                qv += __shfl_xor_sync(0xffffffffu, qv, 2);
                if (l4 == 0) {
                    const int rloc = wy * 48 + mt * 16 + g + half * 8;
                    atomicAdd(&rs[rloc], sv);
                    atomicAdd(&rq[rloc], qv);
                }
            }
        __syncthreads();
        #pragma unroll
        for (int mt = 0; mt < 3; mt++)
            #pragma unroll
            for (int half = 0; half < 2; half++) {
                const int rloc = wy * 48 + mt * 16 + g + half * 8;
                const int row = row0 + rloc;
                const float mean = rs[rloc] * (1.f / 192.f);
                const float inv  = rsqrtf(rq[rloc] * (1.f / 192.f) - mean * mean + 1e-5f);
                float* xo = Xf + (size_t)row * 192;
                bf16*  xh = Xh + (size_t)row * 192;
                #pragma unroll
                for (int t16 = 0; t16 < 3; t16++)
                    #pragma unroll
                    for (int b8 = 0; b8 < 2; b8++) {
                        const int col = wx * 48 + t16 * 16 + b8 * 8 + 2 * l4;
                        float v0 = acc[mt][2 * t16 + b8][half * 2 + 0];
                        float v1 = acc[mt][2 * t16 + b8][half * 2 + 1];
                        float o0 = (v0 - mean) * inv * __ldg(lnw + col) + __ldg(lnb + col);
                        float o1 = (v1 - mean) * inv * __ldg(lnw + col + 1) + __ldg(lnb + col + 1);
                        float2 of; of.x = o0; of.y = o1;
                        *(float2*)(xo + col) = of;
                        __nv_bfloat162 ob = __floats2bfloat162_rn(o0, o1);
                        *(__nv_bfloat162*)(xh + col) = ob;
                    }
            }
    }
}

// ============ FFN2 (K=384) + residual + LN2 ============
__global__ void __launch_bounds__(384)
gemm_f2ln(const bf16* __restrict__ A,
          const bf16* __restrict__ W0, const bf16* __restrict__ W1,
          const float* __restrict__ bias, const float* __restrict__ xres,
          const float* __restrict__ lnw, const float* __restrict__ lnb,
          float* __restrict__ Out)
{
    extern __shared__ __align__(16) char smem[];
    const uint32_t smem_u32 = (uint32_t)__cvta_generic_to_shared(smem);
    const uint32_t b_u32[2] = { smem_u32, smem_u32 + 73728u };
    const uint32_t a_u32    = smem_u32 + 147456u;
    __shared__ float sbias[192], slnw[192], slnb[192];
    __shared__ float rs[96], rq[96];

    const int tid = threadIdx.x, lane = tid & 31, wid = tid >> 5;
    const int wy = wid >> 2, wx = wid & 3;
    const int lane15 = lane & 15, lane16 = lane >> 4;
    const int g = lane >> 2, l4 = lane & 3;
    const int bx = (int)blockIdx.x;

    if (tid < 192) { sbias[tid] = bias[tid]; slnw[tid] = lnw[tid]; slnb[tid] = lnb[tid]; }

    for (int f = tid; f < 4608; f += 384) {
        int r = f / 24, c = f % 24;
        cp_async16(b_u32[0] + swz(r, c), W0 + (size_t)r * 192 + c * 8);
        cp_async16(b_u32[1] + swz(r, c), W1 + (size_t)r * 192 + c * 8);
    }
    const int pr = tid >> 2, pc0 = (tid & 3) * 6;
    auto loadA = [&](int s, int buf) {
        const int t = bx + (s >> 1) * GRID, kh = s & 1;
        const bf16* src = A + (size_t)(t * 96 + pr) * 384 + kh * 192 + pc0 * 8;
        uint32_t dstb = a_u32 + buf * 36864u;
        #pragma unroll
        for (int u = 0; u < 6; u++)
            cp_async16(dstb + swz(pr, pc0 + u), src + u * 8);
    };

    const int nmine = (NT96 - bx + GRID - 1) / GRID;
    const int nst = nmine * 2;
    loadA(0, 0);
    CP_COMMIT();

    float acc[2][6][4];

    for (int s = 0; s < nst; s++) {
        const int kh = s & 1;
        if (s + 1 < nst) loadA(s + 1, (s + 1) & 1);
        CP_COMMIT();
        CP_WAIT1();
        __syncthreads();
        if (kh == 0) {
            if (tid < 96) { rs[tid] = 0.f; rq[tid] = 0.f; }
            #pragma unroll
            for (int mt = 0; mt < 2; mt++)
                #pragma unroll
                for (int nt = 0; nt < 6; nt++)
                    #pragma unroll
                    for (int i = 0; i < 4; i++) acc[mt][nt][i] = 0.f;
        }

        const uint32_t abuf = a_u32 + (uint32_t)((s & 1) * 36864);
        const uint32_t bb = b_u32[kh];
        #pragma unroll
        for (int kc = 0; kc < 12; kc++) {
            uint32_t a0[4], a1[4];
            ldsm_x4(a0, abuf + swz(wy * 32 + lane15,      kc * 2 + lane16));
            ldsm_x4(a1, abuf + swz(wy * 32 + 16 + lane15, kc * 2 + lane16));
            const int krow = kc * 16 + lane15;
            #pragma unroll
            for (int t16 = 0; t16 < 3; t16++) {
                uint32_t B[4];
                ldsm_x4_t(B, bb + swz(krow, wx * 6 + t16 * 2 + lane16));
                mma_bf16(acc[0][2 * t16],     a0, B + 0);
                mma_bf16(acc[0][2 * t16 + 1], a0, B + 2);
                mma_bf16(acc[1][2 * t16],     a1, B + 0);
                mma_bf16(acc[1][2 * t16 + 1], a1, B + 2);
            }
        }
        __syncthreads();

        if (kh == 1) {
            const int row0 = (bx + (s >> 1) * GRID) * 96;
            #pragma unroll
            for (int mt = 0; mt < 2; mt++)
                #pragma unroll
                for (int half = 0; half < 2; half++) {
                    const int row = row0 + wy * 32 + mt * 16 + g + half * 8;
                    const float* xp = xres + (size_t)row * 192;
                    float sv = 0.f, qv = 0.f;
                    #pragma unroll
                    for (int t16 = 0; t16 < 3; t16++)
                        #pragma unroll
                        for (int b8 = 0; b8 < 2; b8++) {
                            const int col = wx * 48 + t16 * 16 + b8 * 8 + 2 * l4;
                            float2 xv = *(const float2*)(xp + col);
                            float v0 = acc[mt][2 * t16 + b8][half * 2 + 0] + sbias[col] + xv.x;
                            float v1 = acc[mt][2 * t16 + b8][half * 2 + 1] + sbias[col + 1] + xv.y;
                            acc[mt][2 * t16 + b8][half * 2 + 0] = v0;
                            acc[mt][2 * t16 + b8][half * 2 + 1] = v1;
                            sv += v0 + v1; qv += v0 * v0 + v1 * v1;
                        }
                    sv += __shfl_xor_sync(0xffffffffu, sv, 1);
                    qv += __shfl_xor_sync(0xffffffffu, qv, 1);
                    sv += __shfl_xor_sync(0xffffffffu, sv, 2);
                    qv += __shfl_xor_sync(0xffffffffu, qv, 2);
                    if (l4 == 0) {
                        const int rloc = wy * 32 + mt * 16 + g + half * 8;
                        atomicAdd(&rs[rloc], sv);
                        atomicAdd(&rq[rloc], qv);
                    }
                }
            __syncthreads();
            #pragma unroll
            for (int mt = 0; mt < 2; mt++)
                #pragma unroll
                for (int half = 0; half < 2; half++) {
                    const int rloc = wy * 32 + mt * 16 + g + half * 8;
                    const int row = row0 + rloc;
                    const float mean = rs[rloc] * (1.f / 192.f);
                    const float inv  = rsqrtf(rq[rloc] * (1.f / 192.f) - mean * mean + 1e-5f);
                    float* op = Out + (size_t)row * 192;
                    #pragma unroll
                    for (int t16 = 0; t16 < 3; t16++)
                        #pragma unroll
                        for (int b8 = 0; b8 < 2; b8++) {
                            const int col = wx * 48 + t16 * 16 + b8 * 8 + 2 * l4;
                            float v0 = acc[mt][2 * t16 + b8][half * 2 + 0];
                            float v1 = acc[mt][2 * t16 + b8][half * 2 + 1];
                            float2 of;
                            of.x = (v0 - mean) * inv * slnw[col] + slnb[col];
                            of.y = (v1 - mean) * inv * slnw[col + 1] + slnb[col + 1];
                            *(float2*)(op + col) = of;
                        }
                }
        }
    }
}

// ================= tensor-core set attention (Q frags from global, K/V in smem) =================
#define HBUF 3840            // 48*40*2 bytes per head per buffer
#define AK_OFF 0
#define AV_OFF 30720
#define ATTN_SMEM 61440

__global__ void __launch_bounds__(256, 3)
attn_tc(const bf16* __restrict__ QK, const bf16* __restrict__ V,
        const int* __restrict__ gidx, bf16* __restrict__ O)
{
    extern __shared__ __align__(16) char smem[];
    const uint32_t smem_u32 = (uint32_t)__cvta_generic_to_shared(smem);
    __shared__ int sidx[36];

    const int s = blockIdx.x, tid = threadIdx.x;
    const int lane = tid & 31, h = tid >> 5;
    const int lane15 = lane & 15, lane16 = lane >> 4;
    const int g = lane >> 2, l4 = lane & 3;

    if (tid < 36) sidx[tid] = __ldg(gidx + s * SETS + tid);
    for (int i = tid; i < ATTN_SMEM / 16; i += 256)
        *(uint4*)(smem + i * 16) = make_uint4(0, 0, 0, 0);
    __syncthreads();

    for (int f = tid; f < 864; f += 256) {
        int hh = f / 108, r = f % 108;
        int key = r / 3, c = r % 3;
        int grow = sidx[key];
        uint4 k = *(const uint4*)(QK + (size_t)grow * 384 + 192 + hh * 24 + c * 8);
        *(uint4*)(smem + AK_OFF + hh * HBUF + (key * 40 + c * 8) * 2) = k;
        uint4 v = *(const uint4*)(V + (size_t)grow * 192 + hh * 24 + c * 8);
        *(uint4*)(smem + AV_OFF + hh * HBUF + (key * 40 + c * 8) * 2) = v;
    }

    // Q A-fragments straight from global
    uint32_t A0[3][4], A1[3][4];
    #pragma unroll
    for (int mt = 0; mt < 3; mt++) {
        const int r0 = mt * 16 + g, r1 = r0 + 8;
        const int gr0 = sidx[(r0 < 36) ? r0 : 0];
        const int gr1 = sidx[(r1 < 36) ? r1 : 0];
        const bf16* q0 = QK + (size_t)gr0 * 384 + h * 24;
        const bf16* q1 = QK + (size_t)gr1 * 384 + h * 24;
        A0[mt][0] = *(const uint32_t*)(q0 + 2 * l4);
        A0[mt][1] = *(const uint32_t*)(q1 + 2 * l4);
        A0[mt][2] = *(const uint32_t*)(q0 + 2 * l4 + 8);
        A0[mt][3] = *(const uint32_t*)(q1 + 2 * l4 + 8);
        A1[mt][0] = *(const uint32_t*)(q0 + 2 * l4 + 16);
        A1[mt][1] = *(const uint32_t*)(q1 + 2 * l4 + 16);
        A1[mt][2] = 0;
        A1[mt][3] = 0;
    }
    __syncthreads();

    const uint32_t kb = smem_u32 + AK_OFF + (uint32_t)(h * HBUF);
    const uint32_t vb = smem_u32 + AV_OFF + (uint32_t)(h * HBUF);

    float S[3][6][4];
    #pragma unroll
    for (int mt = 0; mt < 3; mt++)
        #pragma unroll
        for (int nt = 0; nt < 6; nt++)
            #pragma unroll
            for (int i = 0; i < 4; i++) S[mt][nt][i] = 0.f;

    #pragma unroll
    for (int kc = 0; kc < 2; kc++) {
        #pragma unroll
        for (int nt2 = 0; nt2 < 3; nt2++) {
            uint32_t Br[4];
            ldsm_x4(Br, kb + (uint32_t)(((nt2 * 16 + lane15) * 40 + kc * 16 + lane16 * 8) * 2));
            #pragma unroll
            for (int mt = 0; mt < 3; mt++) {
                const uint32_t* a = (kc == 0) ? A0[mt] : A1[mt];
                mma_bf16_2(S[mt][2 * nt2],     a, Br[0], Br[2]);
                mma_bf16_2(S[mt][2 * nt2 + 1], a, Br[1], Br[3]);
            }
        }
    }

    const float scale = 0.20412414523193154f;
    float inv_[3][2];
    #pragma unroll
    for (int mt = 0; mt < 3; mt++) {
        #pragma unroll
        for (int half = 0; half < 2; half++) {
            float mx = -1e30f;
            #pragma unroll
            for (int nt = 0; nt < 6; nt++) {
                #pragma unroll
                for (int cc = 0; cc < 2; cc++) {
                    const int col = nt * 8 + l4 * 2 + cc;
                    float v = (col < 36) ? S[mt][nt][half * 2 + cc] * scale : -1e30f;
                    S[mt][nt][half * 2 + cc] = v;
                    mx = fmaxf(mx, v);
                }
            }
            mx = fmaxf(mx, __shfl_xor_sync(0xffffffffu, mx, 1));
            mx = fmaxf(mx, __shfl_xor_sync(0xffffffffu, mx, 2));
            float sum = 0.f;
            #pragma unroll
            for (int nt = 0; nt < 6; nt++) {
                #pragma unroll
                for (int cc = 0; cc < 2; cc++) {
                    float e = __expf(S[mt][nt][half * 2 + cc] - mx);
                    S[mt][nt][half * 2 + cc] = e;
                    sum += e;
                }
            }
            sum += __shfl_xor_sync(0xffffffffu, sum, 1);
            sum += __shfl_xor_sync(0xffffffffu, sum, 2);
            inv_[mt][half] = 1.f / sum;
        }
    }

    uint32_t P[3][3][4];
    #pragma unroll
    for (int mt = 0; mt < 3; mt++)
        #pragma unroll
        for (int kt = 0; kt < 3; kt++) {
            P[mt][kt][0] = pk2(S[mt][2 * kt][0],     S[mt][2 * kt][1]);
            P[mt][kt][1] = pk2(S[mt][2 * kt][2],     S[mt][2 * kt][3]);
            P[mt][kt][2] = pk2(S[mt][2 * kt + 1][0], S[mt][2 * kt + 1][1]);
            P[mt][kt][3] = pk2(S[mt][2 * kt + 1][2], S[mt][2 * kt + 1][3]);
        }

    float Oa[3][4][4];
    #pragma unroll
    for (int mt = 0; mt < 3; mt++)
        #pragma unroll
        for (int nt = 0; nt < 4; nt++)
            #pragma unroll
            for (int i = 0; i < 4; i++) Oa[mt][nt][i] = 0.f;

    #pragma unroll
    for (int kt = 0; kt < 3; kt++) {
        #pragma unroll
        for (int nt2 = 0; nt2 < 2; nt2++) {
            uint32_t B[4];
            ldsm_x4_t(B, vb + (uint32_t)(((kt * 16 + lane15) * 40 + nt2 * 16 + lane16 * 8) * 2));
            #pragma unroll
            for (int mt = 0; mt < 3; mt++) {
                mma_bf16(Oa[mt][2 * nt2],     P[mt][kt], B + 0);
                mma_bf16(Oa[mt][2 * nt2 + 1], P[mt][kt], B + 2);
            }
        }
    }

    #pragma unroll
    for (int mt = 0; mt < 3; mt++)
        #pragma unroll
        for (int half = 0; half < 2; half++) {
            const int row = mt * 16 + g + half * 8;
            if (row >= 36) continue;
            const int grow = sidx[row];
            const float inv = inv_[mt][half];
            bf16* op = O + (size_t)grow * 192 + h * 24;
            #pragma unroll
            for (int nt = 0; nt < 3; nt++) {
                const int col = nt * 8 + l4 * 2;
                __nv_bfloat162 o = __floats2bfloat162_rn(
                    Oa[mt][nt][half * 2 + 0] * inv, Oa[mt][nt][half * 2 + 1] * inv);
                *(__nv_bfloat162*)(op + col) = o;
            }
        }
}

// ---------------- host ----------------
extern "C" void kernel_launch(void* const* d_in, const int* in_sizes, int n_in,
                              void* d_out, int out_size)
{
    (void)in_sizes; (void)n_in; (void)out_size;
    const float* src    = (const float*)d_in[0];
    const float* pos    = (const float*)d_in[1];
    const float* qkv_w  = (const float*)d_in[2];
    const float* qkv_b  = (const float*)d_in[3];
    const float* out_w  = (const float*)d_in[4];
    const float* out_b  = (const float*)d_in[5];
    const float* ln_w   = (const float*)d_in[6];
    const float* ln_b   = (const float*)d_in[7];
    const float* w1     = (const float*)d_in[8];
    const float* b1     = (const float*)d_in[9];
    const float* w2     = (const float*)d_in[10];
    const float* b2     = (const float*)d_in[11];
    const int*   inds   = (const int*)d_in[12];
    float*       outp   = (float*)d_out;

    bf16 *QKh, *Vh, *Oh, *Hh, *Xh, *Wh;
    float *Xb;
    cudaGetSymbolAddress((void**)&QKh, g_QKh);
    cudaGetSymbolAddress((void**)&Vh,  g_Vh);
    cudaGetSymbolAddress((void**)&Oh,  g_Oh);
    cudaGetSymbolAddress((void**)&Hh,  g_Hh);
    cudaGetSymbolAddress((void**)&Xh,  g_Xh);
    cudaGetSymbolAddress((void**)&Xb,  g_X);
    cudaGetSymbolAddress((void**)&Wh,  g_Wh);

    cudaFuncSetAttribute(attn_tc, cudaFuncAttributeMaxDynamicSharedMemorySize, ATTN_SMEM);

    const int sm_qk  = 2 * 73728 + 36864;              // 184320 (1 CTA/SM)
    const int sm_one = 73728 + 36864;                  // 110592 (2 CTAs/SM)
    const int sm_f2  = 2 * 73728 + 2 * 36864;          // 221184 (1 CTA/SM)
    cudaFuncSetAttribute((const void*)gemm_qk,
                         cudaFuncAttributeMaxDynamicSharedMemorySize, sm_qk);
    cudaFuncSetAttribute((const void*)gemm_bf<false>,
                         cudaFuncAttributeMaxDynamicSharedMemorySize, sm_one);
    cudaFuncSetAttribute((const void*)gemm_bf<true>,
                         cudaFuncAttributeMaxDynamicSharedMemorySize, sm_one);
    cudaFuncSetAttribute((const void*)gemm_oln,
                         cudaFuncAttributeMaxDynamicSharedMemorySize, sm_one);
    cudaFuncSetAttribute((const void*)gemm_f2ln,
                         cudaFuncAttributeMaxDynamicSharedMemorySize, sm_f2);

    // pack both layers once
    pack_kernel<<<(2 * 294912 + 255) / 256, 256>>>(qkv_w, out_w, w1, w2);

    for (int l = 0; l < NL; l++) {
        const float* xin = (l == 0) ? src : Xb;
        const int*   idx = inds + (size_t)l * NV;
        const float* pel = pos  + (size_t)l * NV * DM;
        const float* qb  = qkv_b + (size_t)l * 3 * DM;
        bf16* Wl = Wh + (size_t)l * 294912;

        // Q|K GEMM; also emits bf16(x) into Oh for the V GEMM
        gemm_qk<<<GRID, 384, sm_qk>>>(xin, pel, Wl + 0 * 36864, Wl + 1 * 36864, qb, QKh, Oh);

        // V = bf16(x) @ Wv + bv   (reads Oh)
        gemm_bf<false><<<GRID2, 256, sm_one>>>(Oh, Wl + 2 * 36864, qb + 384, Vh, 192, 0);

        // attention: gather rows by idx, write O (overwrites Oh) in natural order
        attn_tc<<<NSET, 256, ATTN_SMEM>>>(QKh, Vh, idx, Oh);

        // O-proj + residual + LN1 -> Xb (fp32) and Xh (bf16)
        gemm_oln<<<GRID2, 256, sm_one>>>(Oh, Wl + 3 * 36864, out_b + (size_t)l * DM, xin,
                                         ln_w + (size_t)(l * 2) * DM, ln_b + (size_t)(l * 2) * DM,
                                         Xb, Xh);

        // H = gelu(Xh @ W1 + b1): two halves
        gemm_bf<true><<<GRID2, 256, sm_one>>>(Xh, Wl + 4 * 36864, b1 + (size_t)l * DFF, Hh, 384, 0);
        gemm_bf<true><<<GRID2, 256, sm_one>>>(Xh, Wl + 5 * 36864, b1 + (size_t)l * DFF + 192, Hh, 384, 192);

        // x = LN(x1 + Hh @ W2 + b2)
        float* lnout = (l == NL - 1) ? outp : Xb;
        gemm_f2ln<<<GRID, 384, sm_f2>>>(Hh, Wl + 6 * 36864, Wl + 7 * 36864,
                                        b2 + (size_t)l * DM, Xb,
                                        ln_w + (size_t)(l * 2 + 1) * DM,
                                        ln_b + (size_t)(l * 2 + 1) * DM, lnout);
    }
}

// round 16
// speedup vs baseline: 1.5248x; 1.0137x over previous
#include <cuda_runtime.h>
#include <cuda_bf16.h>
#include <math.h>
#include <stdint.h>

#define NV   262080
#define DM   192
#define DFF  384
#define SETS 36
#define NSET 7280
#define NL   2
#define GRID 148
#define GRID2 296
#define NT96 2730          // NV / 96 exactly

typedef __nv_bfloat16 bf16;

// ---------------- scratch (device globals) ----------------
__device__ bf16 g_QKh[(size_t)NV * 384];   // Q|K natural order
__device__ bf16 g_Vh [(size_t)NV * 192];   // V natural order
__device__ bf16 g_Oh [(size_t)NV * 192];   // bf16(x) during QKV; attention out after
__device__ bf16 g_Hh [(size_t)NV * 384];   // FFN hidden
__device__ bf16 g_Xh [(size_t)NV * 192];   // LN1 bf16 out (FFN1 input)
__device__ float g_X[(size_t)NV * 192];    // running x (fp32)
__device__ bf16 g_Wh[2 * 294912];          // per-layer: 8 blocks of [k:192][n:192]

__device__ __forceinline__ float gelu_tanh(float x) {
    float x3 = x * x * x;
    return 0.5f * x * (1.0f + tanhf(0.7978845608028654f * (x + 0.044715f * x3)));
}
__device__ __forceinline__ uint32_t pk2(float a, float b) {
    __nv_bfloat162 t = __floats2bfloat162_rn(a, b);
    return *(uint32_t*)&t;
}
__device__ __forceinline__ void ldsm_x4(uint32_t r[4], uint32_t addr) {
    asm volatile("ldmatrix.sync.aligned.m8n8.x4.shared.b16 {%0,%1,%2,%3}, [%4];"
                 : "=r"(r[0]), "=r"(r[1]), "=r"(r[2]), "=r"(r[3]) : "r"(addr));
}
__device__ __forceinline__ void ldsm_x4_t(uint32_t r[4], uint32_t addr) {
    asm volatile("ldmatrix.sync.aligned.m8n8.x4.trans.shared.b16 {%0,%1,%2,%3}, [%4];"
                 : "=r"(r[0]), "=r"(r[1]), "=r"(r[2]), "=r"(r[3]) : "r"(addr));
}
__device__ __forceinline__ void mma_bf16(float c[4], const uint32_t a[4], const uint32_t* b) {
    asm volatile(
        "mma.sync.aligned.m16n8k16.row.col.f32.bf16.bf16.f32 "
        "{%0,%1,%2,%3}, {%4,%5,%6,%7}, {%8,%9}, {%0,%1,%2,%3};"
        : "+f"(c[0]), "+f"(c[1]), "+f"(c[2]), "+f"(c[3])
        : "r"(a[0]), "r"(a[1]), "r"(a[2]), "r"(a[3]), "r"(b[0]), "r"(b[1]));
}
__device__ __forceinline__ void mma_bf16_2(float c[4], const uint32_t a[4],
                                           uint32_t b0, uint32_t b1) {
    asm volatile(
        "mma.sync.aligned.m16n8k16.row.col.f32.bf16.bf16.f32 "
        "{%0,%1,%2,%3}, {%4,%5,%6,%7}, {%8,%9}, {%0,%1,%2,%3};"
        : "+f"(c[0]), "+f"(c[1]), "+f"(c[2]), "+f"(c[3])
        : "r"(a[0]), "r"(a[1]), "r"(a[2]), "r"(a[3]), "r"(b0), "r"(b1));
}
__device__ __forceinline__ void cp_async16(uint32_t dst, const void* src) {
    asm volatile("cp.async.ca.shared.global [%0], [%1], 16;" :: "r"(dst), "l"(src));
}
#define CP_COMMIT() asm volatile("cp.async.commit_group;")
#define CP_WAIT0()  asm volatile("cp.async.wait_group 0;" ::: "memory")
#define CP_WAIT1()  asm volatile("cp.async.wait_group 1;" ::: "memory")

// XOR-swizzled smem offset: rows x 192 bf16 cols (384B row), 24 16B-chunks/row
__device__ __forceinline__ uint32_t swz(int row, int chunk) {
    return (uint32_t)(row * 384 + ((chunk ^ (row & 7)) << 4));
}

// ---------------- weight pack: both layers ----------------
__global__ void pack_kernel(const float* __restrict__ qkv_w, const float* __restrict__ out_w,
                            const float* __restrict__ w1, const float* __restrict__ w2) {
    int gi = blockIdx.x * 256 + threadIdx.x;
    if (gi >= 2 * 294912) return;
    int l = gi / 294912, i = gi % 294912;
    int blk = i / 36864, j = i % 36864;
    int k = j / 192, n = j % 192;
    float v;
    if (blk < 3)       v = qkv_w[(size_t)(l * 3 + blk) * 36864 + k * 192 + n];
    else if (blk == 3) v = out_w[(size_t)l * 36864 + k * 192 + n];
    else if (blk == 4) v = w1[(size_t)l * 73728 + k * 384 + n];
    else if (blk == 5) v = w1[(size_t)l * 73728 + k * 384 + 192 + n];
    else if (blk == 6) v = w2[(size_t)l * 73728 + k * 192 + n];
    else               v = w2[(size_t)l * 73728 + (192 + k) * 192 + n];
    g_Wh[gi] = __float2bfloat16(v);
}

// ============ QK dual-B GEMM: also emits bf16(x) to Xout ============
__global__ void __launch_bounds__(384)
gemm_qk(const float* __restrict__ X, const float* __restrict__ POS,
        const bf16* __restrict__ W0, const bf16* __restrict__ W1,
        const float* __restrict__ bias, bf16* __restrict__ C, bf16* __restrict__ Xout)
{
    extern __shared__ __align__(16) char smem[];
    const uint32_t smem_u32 = (uint32_t)__cvta_generic_to_shared(smem);
    const uint32_t b_u32[2] = { smem_u32, smem_u32 + 73728u };
    char* As = smem + 147456;
    __shared__ float sbias[384];

    const int tid = threadIdx.x, lane = tid & 31, wid = tid >> 5;
    const int wy = wid >> 2, wx = wid & 3;
    const int lane15 = lane & 15, lane16 = lane >> 4;
    const int g = lane >> 2, l4 = lane & 3;
    const int bx = (int)blockIdx.x;
    const uint32_t a_u32 = smem_u32 + 147456u;

    if (tid < 384) sbias[tid] = bias[tid];

    for (int f = tid; f < 4608; f += 384) {
        int r = f / 24, c = f % 24;
        cp_async16(b_u32[0] + swz(r, c), W0 + (size_t)r * 192 + c * 8);
        cp_async16(b_u32[1] + swz(r, c), W1 + (size_t)r * 192 + c * 8);
    }
    CP_COMMIT();

    const int nmine = (NT96 - bx + GRID - 1) / GRID;

    for (int ti = 0; ti < nmine; ti++) {
        const int t = bx + ti * GRID;
        #pragma unroll
        for (int u = 0; u < 6; u++) {
            int f = tid + u * 384;
            int r = f / 24, c = f % 24;
            const float4* xp = (const float4*)(X   + (size_t)(t * 96 + r) * 192 + c * 8);
            const float4* pp = (const float4*)(POS + (size_t)(t * 96 + r) * 192 + c * 8);
            float4 a0 = xp[0], a1 = xp[1], p0 = pp[0], p1 = pp[1];
            uint4 xv;
            xv.x = pk2(a0.x, a0.y); xv.y = pk2(a0.z, a0.w);
            xv.z = pk2(a1.x, a1.y); xv.w = pk2(a1.z, a1.w);
            *((uint4*)(Xout + (size_t)(t * 96 + r) * 192 + c * 8)) = xv;
            a0.x += p0.x; a0.y += p0.y; a0.z += p0.z; a0.w += p0.w;
            a1.x += p1.x; a1.y += p1.y; a1.z += p1.z; a1.w += p1.w;
            uint4 o;
            o.x = pk2(a0.x, a0.y); o.y = pk2(a0.z, a0.w);
            o.z = pk2(a1.x, a1.y); o.w = pk2(a1.z, a1.w);
            *(uint4*)(As + swz(r, c)) = o;
        }
        if (ti == 0) CP_WAIT0();
        __syncthreads();

        float acc[2][2][6][4];
        #pragma unroll
        for (int m = 0; m < 2; m++)
            #pragma unroll
            for (int mt = 0; mt < 2; mt++)
                #pragma unroll
                for (int nt = 0; nt < 6; nt++)
                    #pragma unroll
                    for (int i = 0; i < 4; i++) acc[m][mt][nt][i] = 0.f;

        #pragma unroll
        for (int kc = 0; kc < 12; kc++) {
            uint32_t a0[4], a1[4];
            ldsm_x4(a0, a_u32 + swz(wy * 32 + lane15,      kc * 2 + lane16));
            ldsm_x4(a1, a_u32 + swz(wy * 32 + 16 + lane15, kc * 2 + lane16));
            const int krow = kc * 16 + lane15;
            #pragma unroll
            for (int m = 0; m < 2; m++) {
                #pragma unroll
                for (int t16 = 0; t16 < 3; t16++) {
                    uint32_t B[4];
                    ldsm_x4_t(B, b_u32[m] + swz(krow, wx * 6 + t16 * 2 + lane16));
                    mma_bf16(acc[m][0][2 * t16],     a0, B + 0);
                    mma_bf16(acc[m][0][2 * t16 + 1], a0, B + 2);
                    mma_bf16(acc[m][1][2 * t16],     a1, B + 0);
                    mma_bf16(acc[m][1][2 * t16 + 1], a1, B + 2);
                }
            }
        }
        __syncthreads();

        const int row0 = t * 96;
        #pragma unroll
        for (int m = 0; m < 2; m++)
            #pragma unroll
            for (int mt = 0; mt < 2; mt++)
                #pragma unroll
                for (int half = 0; half < 2; half++) {
                    const int row = row0 + wy * 32 + mt * 16 + g + half * 8;
                    bf16* cp = C + (size_t)row * 384 + m * 192;
                    #pragma unroll
                    for (int t16 = 0; t16 < 3; t16++)
                        #pragma unroll
                        for (int b8 = 0; b8 < 2; b8++) {
                            const int col = wx * 48 + t16 * 16 + b8 * 8 + 2 * l4;
                            float ox = acc[m][mt][2 * t16 + b8][half * 2 + 0] + sbias[m * 192 + col];
                            float oy = acc[m][mt][2 * t16 + b8][half * 2 + 1] + sbias[m * 192 + col + 1];
                            __nv_bfloat162 o = __floats2bfloat162_rn(ox, oy);
                            *(__nv_bfloat162*)(cp + col) = o;
                        }
                }
    }
}

// ============ generic bf16-A GEMM (V projection & FFN1 halves) ============
template<bool GELU>
__global__ void __launch_bounds__(256, 2)
gemm_bf(const bf16* __restrict__ A, const bf16* __restrict__ W,
        const float* __restrict__ bias, bf16* __restrict__ C, int ldc, int coff)
{
    extern __shared__ __align__(16) char smem[];
    const uint32_t smem_u32 = (uint32_t)__cvta_generic_to_shared(smem);
    const uint32_t b_u32 = smem_u32;
    const uint32_t a_u32 = smem_u32 + 73728u;

    const int tid = threadIdx.x, lane = tid & 31, wid = tid >> 5;
    const int wy = wid >> 2, wx = wid & 3;
    const int lane15 = lane & 15, lane16 = lane >> 4;
    const int g = lane >> 2, l4 = lane & 3;
    const int bx = (int)blockIdx.x;

    for (int f = tid; f < 4608; f += 256) {
        int r = f / 24, c = f % 24;
        cp_async16(b_u32 + swz(r, c), W + (size_t)r * 192 + c * 8);
    }
    auto loadA = [&](int t) {
        #pragma unroll
        for (int u = 0; u < 9; u++) {
            int f = tid + u * 256;
            int r = f / 24, c = f % 24;
            cp_async16(a_u32 + swz(r, c), A + (size_t)(t * 96 + r) * 192 + c * 8);
        }
    };

    const int nmine = (NT96 - bx + GRID2 - 1) / GRID2;
    loadA(bx);
    CP_COMMIT();

    for (int ti = 0; ti < nmine; ti++) {
        const int t = bx + ti * GRID2;
        CP_WAIT0();
        __syncthreads();

        float acc[3][6][4];
        #pragma unroll
        for (int mt = 0; mt < 3; mt++)
            #pragma unroll
            for (int nt = 0; nt < 6; nt++)
                #pragma unroll
                for (int i = 0; i < 4; i++) acc[mt][nt][i] = 0.f;

        #pragma unroll
        for (int kc = 0; kc < 12; kc++) {
            uint32_t a[3][4];
            #pragma unroll
            for (int mt = 0; mt < 3; mt++)
                ldsm_x4(a[mt], a_u32 + swz(wy * 48 + mt * 16 + lane15, kc * 2 + lane16));
            const int krow = kc * 16 + lane15;
            #pragma unroll
            for (int t16 = 0; t16 < 3; t16++) {
                uint32_t B[4];
                ldsm_x4_t(B, b_u32 + swz(krow, wx * 6 + t16 * 2 + lane16));
                #pragma unroll
                for (int mt = 0; mt < 3; mt++) {
                    mma_bf16(acc[mt][2 * t16],     a[mt], B + 0);
                    mma_bf16(acc[mt][2 * t16 + 1], a[mt], B + 2);
                }
            }
        }
        __syncthreads();

        if (ti + 1 < nmine) loadA(bx + (ti + 1) * GRID2);
        CP_COMMIT();

        const int row0 = t * 96;
        #pragma unroll
        for (int mt = 0; mt < 3; mt++)
            #pragma unroll
            for (int half = 0; half < 2; half++) {
                const int row = row0 + wy * 48 + mt * 16 + g + half * 8;
                bf16* cp = C + (size_t)row * ldc + coff;
                #pragma unroll
                for (int t16 = 0; t16 < 3; t16++)
                    #pragma unroll
                    for (int b8 = 0; b8 < 2; b8++) {
                        const int col = wx * 48 + t16 * 16 + b8 * 8 + 2 * l4;
                        float ox = acc[mt][2 * t16 + b8][half * 2 + 0] + __ldg(bias + col);
                        float oy = acc[mt][2 * t16 + b8][half * 2 + 1] + __ldg(bias + col + 1);
                        if (GELU) { ox = gelu_tanh(ox); oy = gelu_tanh(oy); }
                        __nv_bfloat162 o = __floats2bfloat162_rn(ox, oy);
                        *(__nv_bfloat162*)(cp + col) = o;
                    }
            }
    }
}

// ============ O-proj + residual + LN1 (natural order) ============
__global__ void __launch_bounds__(256, 2)
gemm_oln(const bf16* __restrict__ A, const bf16* __restrict__ W,
         const float* __restrict__ bias, const float* __restrict__ xres,
         const float* __restrict__ lnw, const float* __restrict__ lnb,
         float* __restrict__ Xf, bf16* __restrict__ Xh)
{
    extern __shared__ __align__(16) char smem[];
    const uint32_t smem_u32 = (uint32_t)__cvta_generic_to_shared(smem);
    const uint32_t b_u32 = smem_u32;
    const uint32_t a_u32 = smem_u32 + 73728u;
    __shared__ float rs[96], rq[96];

    const int tid = threadIdx.x, lane = tid & 31, wid = tid >> 5;
    const int wy = wid >> 2, wx = wid & 3;
    const int lane15 = lane & 15, lane16 = lane >> 4;
    const int g = lane >> 2, l4 = lane & 3;
    const int bx = (int)blockIdx.x;

    for (int f = tid; f < 4608; f += 256) {
        int r = f / 24, c = f % 24;
        cp_async16(b_u32 + swz(r, c), W + (size_t)r * 192 + c * 8);
    }
    auto loadA = [&](int t) {
        #pragma unroll
        for (int u = 0; u < 9; u++) {
            int f = tid + u * 256;
            int r = f / 24, c = f % 24;
            cp_async16(a_u32 + swz(r, c), A + (size_t)(t * 96 + r) * 192 + c * 8);
        }
    };

    const int nmine = (NT96 - bx + GRID2 - 1) / GRID2;
    loadA(bx);
    CP_COMMIT();

    for (int ti = 0; ti < nmine; ti++) {
        const int t = bx + ti * GRID2;
        CP_WAIT0();
        __syncthreads();
        if (tid < 96) { rs[tid] = 0.f; rq[tid] = 0.f; }

        float acc[3][6][4];
        #pragma unroll
        for (int mt = 0; mt < 3; mt++)
            #pragma unroll
            for (int nt = 0; nt < 6; nt++)
                #pragma unroll
                for (int i = 0; i < 4; i++) acc[mt][nt][i] = 0.f;

        #pragma unroll
        for (int kc = 0; kc < 12; kc++) {
            uint32_t a[3][4];
            #pragma unroll
            for (int mt = 0; mt < 3; mt++)
                ldsm_x4(a[mt], a_u32 + swz(wy * 48 + mt * 16 + lane15, kc * 2 + lane16));
            const int krow = kc * 16 + lane15;
            #pragma unroll
            for (int t16 = 0; t16 < 3; t16++) {
                uint32_t B[4];
                ldsm_x4_t(B, b_u32 + swz(krow, wx * 6 + t16 * 2 + lane16));
                #pragma unroll
                for (int mt = 0; mt < 3; mt++) {
                    mma_bf16(acc[mt][2 * t16],     a[mt], B + 0);
                    mma_bf16(acc[mt][2 * t16 + 1], a[mt], B + 2);
                }
            }
        }
        __syncthreads();

        if (ti + 1 < nmine) loadA(bx + (ti + 1) * GRID2);
        CP_COMMIT();

        const int row0 = t * 96;
        #pragma unroll
        for (int mt = 0; mt < 3; mt++)
            #pragma unroll
            for (int half = 0; half < 2; half++) {
                const int row = row0 + wy * 48 + mt * 16 + g + half * 8;
                const float* xp = xres + (size_t)row * 192;
                float sv = 0.f, qv = 0.f;
                #pragma unroll
                for (int t16 = 0; t16 < 3; t16++)
                    #pragma unroll
                    for (int b8 = 0; b8 < 2; b8++) {
                        const int col = wx * 48 + t16 * 16 + b8 * 8 + 2 * l4;
                        float2 xv = *(const float2*)(xp + col);
                        float v0 = acc[mt][2 * t16 + b8][half * 2 + 0] + __ldg(bias + col) + xv.x;
                        float v1 = acc[mt][2 * t16 + b8][half * 2 + 1] + __ldg(bias + col + 1) + xv.y;
                        acc[mt][2 * t16 + b8][half * 2 + 0] = v0;
                        acc[mt][2 * t16 + b8][half * 2 + 1] = v1;
                        sv += v0 + v1;
                        qv += v0 * v0 + v1 * v1;
                    }
                sv += __shfl_xor_sync(0xffffffffu, sv, 1);
                qv += __shfl_xor_sync(0xffffffffu, qv, 1);
                sv += __shfl_xor_sync(0xffffffffu, sv, 2);
                qv += __shfl_xor_sync(0xffffffffu, qv, 2);
                if (l4 == 0) {
                    const int rloc = wy * 48 + mt * 16 + g + half * 8;
                    atomicAdd(&rs[rloc], sv);
                    atomicAdd(&rq[rloc], qv);
                }
            }
        __syncthreads();
        #pragma unroll
        for (int mt = 0; mt < 3; mt++)
            #pragma unroll
            for (int half = 0; half < 2; half++) {
                const int rloc = wy * 48 + mt * 16 + g + half * 8;
                const int row = row0 + rloc;
                const float mean = rs[rloc] * (1.f / 192.f);
                const float inv  = rsqrtf(rq[rloc] * (1.f / 192.f) - mean * mean + 1e-5f);
                float* xo = Xf + (size_t)row * 192;
                bf16*  xh = Xh + (size_t)row * 192;
                #pragma unroll
                for (int t16 = 0; t16 < 3; t16++)
                    #pragma unroll
                    for (int b8 = 0; b8 < 2; b8++) {
                        const int col = wx * 48 + t16 * 16 + b8 * 8 + 2 * l4;
                        float v0 = acc[mt][2 * t16 + b8][half * 2 + 0];
                        float v1 = acc[mt][2 * t16 + b8][half * 2 + 1];
                        float o0 = (v0 - mean) * inv * __ldg(lnw + col) + __ldg(lnb + col);
                        float o1 = (v1 - mean) * inv * __ldg(lnw + col + 1) + __ldg(lnb + col + 1);
                        float2 of; of.x = o0; of.y = o1;
                        *(float2*)(xo + col) = of;
                        __nv_bfloat162 ob = __floats2bfloat162_rn(o0, o1);
                        *(__nv_bfloat162*)(xh + col) = ob;
                    }
            }
    }
}

// ============ FFN2 (K=384) + residual + LN2 ============
__global__ void __launch_bounds__(384)
gemm_f2ln(const bf16* __restrict__ A,
          const bf16* __restrict__ W0, const bf16* __restrict__ W1,
          const float* __restrict__ bias, const float* __restrict__ xres,
          const float* __restrict__ lnw, const float* __restrict__ lnb,
          float* __restrict__ Out)
{
    extern __shared__ __align__(16) char smem[];
    const uint32_t smem_u32 = (uint32_t)__cvta_generic_to_shared(smem);
    const uint32_t b_u32[2] = { smem_u32, smem_u32 + 73728u };
    const uint32_t a_u32    = smem_u32 + 147456u;
    __shared__ float sbias[192], slnw[192], slnb[192];
    __shared__ float rs[96], rq[96];

    const int tid = threadIdx.x, lane = tid & 31, wid = tid >> 5;
    const int wy = wid >> 2, wx = wid & 3;
    const int lane15 = lane & 15, lane16 = lane >> 4;
    const int g = lane >> 2, l4 = lane & 3;
    const int bx = (int)blockIdx.x;

    if (tid < 192) { sbias[tid] = bias[tid]; slnw[tid] = lnw[tid]; slnb[tid] = lnb[tid]; }

    for (int f = tid; f < 4608; f += 384) {
        int r = f / 24, c = f % 24;
        cp_async16(b_u32[0] + swz(r, c), W0 + (size_t)r * 192 + c * 8);
        cp_async16(b_u32[1] + swz(r, c), W1 + (size_t)r * 192 + c * 8);
    }
    const int pr = tid >> 2, pc0 = (tid & 3) * 6;
    auto loadA = [&](int s, int buf) {
        const int t = bx + (s >> 1) * GRID, kh = s & 1;
        const bf16* src = A + (size_t)(t * 96 + pr) * 384 + kh * 192 + pc0 * 8;
        uint32_t dstb = a_u32 + buf * 36864u;
        #pragma unroll
        for (int u = 0; u < 6; u++)
            cp_async16(dstb + swz(pr, pc0 + u), src + u * 8);
    };

    const int nmine = (NT96 - bx + GRID - 1) / GRID;
    const int nst = nmine * 2;
    loadA(0, 0);
    CP_COMMIT();

    float acc[2][6][4];

    for (int s = 0; s < nst; s++) {
        const int kh = s & 1;
        if (s + 1 < nst) loadA(s + 1, (s + 1) & 1);
        CP_COMMIT();
        CP_WAIT1();
        __syncthreads();
        if (kh == 0) {
            if (tid < 96) { rs[tid] = 0.f; rq[tid] = 0.f; }
            #pragma unroll
            for (int mt = 0; mt < 2; mt++)
                #pragma unroll
                for (int nt = 0; nt < 6; nt++)
                    #pragma unroll
                    for (int i = 0; i < 4; i++) acc[mt][nt][i] = 0.f;
        }

        const uint32_t abuf = a_u32 + (uint32_t)((s & 1) * 36864);
        const uint32_t bb = b_u32[kh];
        #pragma unroll
        for (int kc = 0; kc < 12; kc++) {
            uint32_t a0[4], a1[4];
            ldsm_x4(a0, abuf + swz(wy * 32 + lane15,      kc * 2 + lane16));
            ldsm_x4(a1, abuf + swz(wy * 32 + 16 + lane15, kc * 2 + lane16));
            const int krow = kc * 16 + lane15;
            #pragma unroll
            for (int t16 = 0; t16 < 3; t16++) {
                uint32_t B[4];
                ldsm_x4_t(B, bb + swz(krow, wx * 6 + t16 * 2 + lane16));
                mma_bf16(acc[0][2 * t16],     a0, B + 0);
                mma_bf16(acc[0][2 * t16 + 1], a0, B + 2);
                mma_bf16(acc[1][2 * t16],     a1, B + 0);
                mma_bf16(acc[1][2 * t16 + 1], a1, B + 2);
            }
        }
        __syncthreads();

        if (kh == 1) {
            const int row0 = (bx + (s >> 1) * GRID) * 96;
            #pragma unroll
            for (int mt = 0; mt < 2; mt++)
                #pragma unroll
                for (int half = 0; half < 2; half++) {
                    const int row = row0 + wy * 32 + mt * 16 + g + half * 8;
                    const float* xp = xres + (size_t)row * 192;
                    float sv = 0.f, qv = 0.f;
                    #pragma unroll
                    for (int t16 = 0; t16 < 3; t16++)
                        #pragma unroll
                        for (int b8 = 0; b8 < 2; b8++) {
                            const int col = wx * 48 + t16 * 16 + b8 * 8 + 2 * l4;
                            float2 xv = *(const float2*)(xp + col);
                            float v0 = acc[mt][2 * t16 + b8][half * 2 + 0] + sbias[col] + xv.x;
                            float v1 = acc[mt][2 * t16 + b8][half * 2 + 1] + sbias[col + 1] + xv.y;
                            acc[mt][2 * t16 + b8][half * 2 + 0] = v0;
                            acc[mt][2 * t16 + b8][half * 2 + 1] = v1;
                            sv += v0 + v1; qv += v0 * v0 + v1 * v1;
                        }
                    sv += __shfl_xor_sync(0xffffffffu, sv, 1);
                    qv += __shfl_xor_sync(0xffffffffu, qv, 1);
                    sv += __shfl_xor_sync(0xffffffffu, sv, 2);
                    qv += __shfl_xor_sync(0xffffffffu, qv, 2);
                    if (l4 == 0) {
                        const int rloc = wy * 32 + mt * 16 + g + half * 8;
                        atomicAdd(&rs[rloc], sv);
                        atomicAdd(&rq[rloc], qv);
                    }
                }
            __syncthreads();
            #pragma unroll
            for (int mt = 0; mt < 2; mt++)
                #pragma unroll
                for (int half = 0; half < 2; half++) {
                    const int rloc = wy * 32 + mt * 16 + g + half * 8;
                    const int row = row0 + rloc;
                    const float mean = rs[rloc] * (1.f / 192.f);
                    const float inv  = rsqrtf(rq[rloc] * (1.f / 192.f) - mean * mean + 1e-5f);
                    float* op = Out + (size_t)row * 192;
                    #pragma unroll
                    for (int t16 = 0; t16 < 3; t16++)
                        #pragma unroll
                        for (int b8 = 0; b8 < 2; b8++) {
                            const int col = wx * 48 + t16 * 16 + b8 * 8 + 2 * l4;
                            float v0 = acc[mt][2 * t16 + b8][half * 2 + 0];
                            float v1 = acc[mt][2 * t16 + b8][half * 2 + 1];
                            float2 of;
                            of.x = (v0 - mean) * inv * slnw[col] + slnb[col];
                            of.y = (v1 - mean) * inv * slnw[col + 1] + slnb[col + 1];
                            *(float2*)(op + col) = of;
                        }
                }
        }
    }
}

// ================= tensor-core set attention (Q frags from global, K/V in smem) =================
// Softmax computed only for live fragments: rows 40..47 (mt=2,half=1) and
// cols 40..47 (nt=5) are padding -> their exps are skipped and P set to 0.
#define HBUF 3840            // 48*40*2 bytes per head per buffer
#define AK_OFF 0
#define AV_OFF 30720
#define ATTN_SMEM 61440

__global__ void __launch_bounds__(256, 3)
attn_tc(const bf16* __restrict__ QK, const bf16* __restrict__ V,
        const int* __restrict__ gidx, bf16* __restrict__ O)
{
    extern __shared__ __align__(16) char smem[];
    const uint32_t smem_u32 = (uint32_t)__cvta_generic_to_shared(smem);
    __shared__ int sidx[36];

    const int s = blockIdx.x, tid = threadIdx.x;
    const int lane = tid & 31, h = tid >> 5;
    const int lane15 = lane & 15, lane16 = lane >> 4;
    const int g = lane >> 2, l4 = lane & 3;

    if (tid < 36) sidx[tid] = __ldg(gidx + s * SETS + tid);
    for (int i = tid; i < ATTN_SMEM / 16; i += 256)
        *(uint4*)(smem + i * 16) = make_uint4(0, 0, 0, 0);
    __syncthreads();

    for (int f = tid; f < 864; f += 256) {
        int hh = f / 108, r = f % 108;
        int key = r / 3, c = r % 3;
        int grow = sidx[key];
        uint4 k = *(const uint4*)(QK + (size_t)grow * 384 + 192 + hh * 24 + c * 8);
        *(uint4*)(smem + AK_OFF + hh * HBUF + (key * 40 + c * 8) * 2) = k;
        uint4 v = *(const uint4*)(V + (size_t)grow * 192 + hh * 24 + c * 8);
        *(uint4*)(smem + AV_OFF + hh * HBUF + (key * 40 + c * 8) * 2) = v;
    }

    // Q A-fragments straight from global
    uint32_t A0[3][4], A1[3][4];
    #pragma unroll
    for (int mt = 0; mt < 3; mt++) {
        const int r0 = mt * 16 + g, r1 = r0 + 8;
        const int gr0 = sidx[(r0 < 36) ? r0 : 0];
        const int gr1 = sidx[(r1 < 36) ? r1 : 0];
        const bf16* q0 = QK + (size_t)gr0 * 384 + h * 24;
        const bf16* q1 = QK + (size_t)gr1 * 384 + h * 24;
        A0[mt][0] = *(const uint32_t*)(q0 + 2 * l4);
        A0[mt][1] = *(const uint32_t*)(q1 + 2 * l4);
        A0[mt][2] = *(const uint32_t*)(q0 + 2 * l4 + 8);
        A0[mt][3] = *(const uint32_t*)(q1 + 2 * l4 + 8);
        A1[mt][0] = *(const uint32_t*)(q0 + 2 * l4 + 16);
        A1[mt][1] = *(const uint32_t*)(q1 + 2 * l4 + 16);
        A1[mt][2] = 0;
        A1[mt][3] = 0;
    }
    __syncthreads();

    const uint32_t kb = smem_u32 + AK_OFF + (uint32_t)(h * HBUF);
    const uint32_t vb = smem_u32 + AV_OFF + (uint32_t)(h * HBUF);

    float S[3][6][4];
    #pragma unroll
    for (int mt = 0; mt < 3; mt++)
        #pragma unroll
        for (int nt = 0; nt < 6; nt++)
            #pragma unroll
            for (int i = 0; i < 4; i++) S[mt][nt][i] = 0.f;

    #pragma unroll
    for (int kc = 0; kc < 2; kc++) {
        #pragma unroll
        for (int nt2 = 0; nt2 < 3; nt2++) {
            uint32_t Br[4];
            ldsm_x4(Br, kb + (uint32_t)(((nt2 * 16 + lane15) * 40 + kc * 16 + lane16 * 8) * 2));
            #pragma unroll
            for (int mt = 0; mt < 3; mt++) {
                const uint32_t* a = (kc == 0) ? A0[mt] : A1[mt];
                mma_bf16_2(S[mt][2 * nt2],     a, Br[0], Br[2]);
                mma_bf16_2(S[mt][2 * nt2 + 1], a, Br[1], Br[3]);
            }
        }
    }

    // ---- masked softmax on live fragments only ----
    const float scale = 0.20412414523193154f;   // 1/sqrt(24)
    float inv_[3][2];
    #pragma unroll
    for (int mt = 0; mt < 3; mt++) {
        #pragma unroll
        for (int half = 0; half < 2; half++) {
            if (mt == 2 && half == 1) {
                // rows 40..47: never stored; zero their P contribution, skip exps
                #pragma unroll
                for (int nt = 0; nt < 6; nt++) { S[2][nt][2] = 0.f; S[2][nt][3] = 0.f; }
                inv_[2][1] = 0.f;
                continue;
            }
            float mx = -1e30f;
            #pragma unroll
            for (int nt = 0; nt < 5; nt++) {      // nt=5 (cols 40..47) always masked
                #pragma unroll
                for (int cc = 0; cc < 2; cc++) {
                    const int col = nt * 8 + l4 * 2 + cc;
                    float v = (col < 36) ? S[mt][nt][half * 2 + cc] * scale : -1e30f;
                    S[mt][nt][half * 2 + cc] = v;
                    mx = fmaxf(mx, v);
                }
            }
            mx = fmaxf(mx, __shfl_xor_sync(0xffffffffu, mx, 1));
            mx = fmaxf(mx, __shfl_xor_sync(0xffffffffu, mx, 2));
            float sum = 0.f;
            #pragma unroll
            for (int nt = 0; nt < 5; nt++) {
                #pragma unroll
                for (int cc = 0; cc < 2; cc++) {
                    float e = __expf(S[mt][nt][half * 2 + cc] - mx);
                    S[mt][nt][half * 2 + cc] = e;
                    sum += e;
                }
            }
            S[mt][5][half * 2 + 0] = 0.f;         // cols 40..47 -> P = 0
            S[mt][5][half * 2 + 1] = 0.f;
            sum += __shfl_xor_sync(0xffffffffu, sum, 1);
            sum += __shfl_xor_sync(0xffffffffu, sum, 2);
            inv_[mt][half] = 1.f / sum;
        }
    }

    uint32_t P[3][3][4];
    #pragma unroll
    for (int mt = 0; mt < 3; mt++)
        #pragma unroll
        for (int kt = 0; kt < 3; kt++) {
            P[mt][kt][0] = pk2(S[mt][2 * kt][0],     S[mt][2 * kt][1]);
            P[mt][kt][1] = pk2(S[mt][2 * kt][2],     S[mt][2 * kt][3]);
            P[mt][kt][2] = pk2(S[mt][2 * kt + 1][0], S[mt][2 * kt + 1][1]);
            P[mt][kt][3] = pk2(S[mt][2 * kt + 1][2], S[mt][2 * kt + 1][3]);
        }

    float Oa[3][4][4];
    #pragma unroll
    for (int mt = 0; mt < 3; mt++)
        #pragma unroll
        for (int nt = 0; nt < 4; nt++)
            #pragma unroll
            for (int i = 0; i < 4; i++) Oa[mt][nt][i] = 0.f;

    #pragma unroll
    for (int kt = 0; kt < 3; kt++) {
        #pragma unroll
        for (int nt2 = 0; nt2 < 2; nt2++) {
            uint32_t B[4];
            ldsm_x4_t(B, vb + (uint32_t)(((kt * 16 + lane15) * 40 + nt2 * 16 + lane16 * 8) * 2));
            #pragma unroll
            for (int mt = 0; mt < 3; mt++) {
                mma_bf16(Oa[mt][2 * nt2],     P[mt][kt], B + 0);
                mma_bf16(Oa[mt][2 * nt2 + 1], P[mt][kt], B + 2);
            }
        }
    }

    #pragma unroll
    for (int mt = 0; mt < 3; mt++)
        #pragma unroll
        for (int half = 0; half < 2; half++) {
            const int row = mt * 16 + g + half * 8;
            if (row >= 36) continue;
            const int grow = sidx[row];
            const float inv = inv_[mt][half];
            bf16* op = O + (size_t)grow * 192 + h * 24;
            #pragma unroll
            for (int nt = 0; nt < 3; nt++) {
                const int col = nt * 8 + l4 * 2;
                __nv_bfloat162 o = __floats2bfloat162_rn(
                    Oa[mt][nt][half * 2 + 0] * inv, Oa[mt][nt][half * 2 + 1] * inv);
                *(__nv_bfloat162*)(op + col) = o;
            }
        }
}

// ---------------- host ----------------
extern "C" void kernel_launch(void* const* d_in, const int* in_sizes, int n_in,
                              void* d_out, int out_size)
{
    (void)in_sizes; (void)n_in; (void)out_size;
    const float* src    = (const float*)d_in[0];
    const float* pos    = (const float*)d_in[1];
    const float* qkv_w  = (const float*)d_in[2];
    const float* qkv_b  = (const float*)d_in[3];
    const float* out_w  = (const float*)d_in[4];
    const float* out_b  = (const float*)d_in[5];
    const float* ln_w   = (const float*)d_in[6];
    const float* ln_b   = (const float*)d_in[7];
    const float* w1     = (const float*)d_in[8];
    const float* b1     = (const float*)d_in[9];
    const float* w2     = (const float*)d_in[10];
    const float* b2     = (const float*)d_in[11];
    const int*   inds   = (const int*)d_in[12];
    float*       outp   = (float*)d_out;

    bf16 *QKh, *Vh, *Oh, *Hh, *Xh, *Wh;
    float *Xb;
    cudaGetSymbolAddress((void**)&QKh, g_QKh);
    cudaGetSymbolAddress((void**)&Vh,  g_Vh);
    cudaGetSymbolAddress((void**)&Oh,  g_Oh);
    cudaGetSymbolAddress((void**)&Hh,  g_Hh);
    cudaGetSymbolAddress((void**)&Xh,  g_Xh);
    cudaGetSymbolAddress((void**)&Xb,  g_X);
    cudaGetSymbolAddress((void**)&Wh,  g_Wh);

    cudaFuncSetAttribute(attn_tc, cudaFuncAttributeMaxDynamicSharedMemorySize, ATTN_SMEM);

    const int sm_qk  = 2 * 73728 + 36864;              // 184320 (1 CTA/SM)
    const int sm_one = 73728 + 36864;                  // 110592 (2 CTAs/SM)
    const int sm_f2  = 2 * 73728 + 2 * 36864;          // 221184 (1 CTA/SM)
    cudaFuncSetAttribute((const void*)gemm_qk,
                         cudaFuncAttributeMaxDynamicSharedMemorySize, sm_qk);
    cudaFuncSetAttribute((const void*)gemm_bf<false>,
                         cudaFuncAttributeMaxDynamicSharedMemorySize, sm_one);
    cudaFuncSetAttribute((const void*)gemm_bf<true>,
                         cudaFuncAttributeMaxDynamicSharedMemorySize, sm_one);
    cudaFuncSetAttribute((const void*)gemm_oln,
                         cudaFuncAttributeMaxDynamicSharedMemorySize, sm_one);
    cudaFuncSetAttribute((const void*)gemm_f2ln,
                         cudaFuncAttributeMaxDynamicSharedMemorySize, sm_f2);

    // pack both layers once
    pack_kernel<<<(2 * 294912 + 255) / 256, 256>>>(qkv_w, out_w, w1, w2);

    for (int l = 0; l < NL; l++) {
        const float* xin = (l == 0) ? src : Xb;
        const int*   idx = inds + (size_t)l * NV;
        const float* pel = pos  + (size_t)l * NV * DM;
        const float* qb  = qkv_b + (size_t)l * 3 * DM;
        bf16* Wl = Wh + (size_t)l * 294912;

        // Q|K GEMM; also emits bf16(x) into Oh for the V GEMM
        gemm_qk<<<GRID, 384, sm_qk>>>(xin, pel, Wl + 0 * 36864, Wl + 1 * 36864, qb, QKh, Oh);

        // V = bf16(x) @ Wv + bv   (reads Oh)
        gemm_bf<false><<<GRID2, 256, sm_one>>>(Oh, Wl + 2 * 36864, qb + 384, Vh, 192, 0);

        // attention: gather rows by idx, write O (overwrites Oh) in natural order
        attn_tc<<<NSET, 256, ATTN_SMEM>>>(QKh, Vh, idx, Oh);

        // O-proj + residual + LN1 -> Xb (fp32) and Xh (bf16)
        gemm_oln<<<GRID2, 256, sm_one>>>(Oh, Wl + 3 * 36864, out_b + (size_t)l * DM, xin,
                                         ln_w + (size_t)(l * 2) * DM, ln_b + (size_t)(l * 2) * DM,
                                         Xb, Xh);

        // H = gelu(Xh @ W1 + b1): two halves
        gemm_bf<true><<<GRID2, 256, sm_one>>>(Xh, Wl + 4 * 36864, b1 + (size_t)l * DFF, Hh, 384, 0);
        gemm_bf<true><<<GRID2, 256, sm_one>>>(Xh, Wl + 5 * 36864, b1 + (size_t)l * DFF + 192, Hh, 384, 192);

        // x = LN(x1 + Hh @ W2 + b2)
        float* lnout = (l == NL - 1) ? outp : Xb;
        gemm_f2ln<<<GRID, 384, sm_f2>>>(Hh, Wl + 6 * 36864, Wl + 7 * 36864,
                                        b2 + (size_t)l * DM, Xb,
                                        ln_w + (size_t)(l * 2 + 1) * DM,
                                        ln_b + (size_t)(l * 2 + 1) * DM, lnout);
    }
}

// round 17
// speedup vs baseline: 1.5541x; 1.0193x over previous
#include <cuda_runtime.h>
#include <cuda_bf16.h>
#include <math.h>
#include <stdint.h>

#define NV   262080
#define DM   192
#define DFF  384
#define SETS 36
#define NSET 7280
#define NL   2
#define GRID 148
#define GRID2 296
#define NT96 2730          // NV / 96 exactly

typedef __nv_bfloat16 bf16;

// ---------------- scratch (device globals) ----------------
__device__ bf16 g_QKh[(size_t)NV * 384];   // Q|K natural order
__device__ bf16 g_Vh [(size_t)NV * 192];   // V natural order
__device__ bf16 g_Oh [(size_t)NV * 192];   // bf16(x) during QKV; attention out after
__device__ bf16 g_Hh [(size_t)NV * 384];   // FFN hidden
__device__ bf16 g_Xh [(size_t)NV * 192];   // LN1 bf16 out (FFN1 input)
__device__ float g_X[(size_t)NV * 192];    // running x (fp32)
__device__ bf16 g_Wh[2 * 294912];          // per-layer: 8 blocks of [k:192][n:192]

__device__ __forceinline__ float gelu_tanh(float x) {
    float x3 = x * x * x;
    return 0.5f * x * (1.0f + tanhf(0.7978845608028654f * (x + 0.044715f * x3)));
}
__device__ __forceinline__ uint32_t pk2(float a, float b) {
    __nv_bfloat162 t = __floats2bfloat162_rn(a, b);
    return *(uint32_t*)&t;
}
__device__ __forceinline__ void ldsm_x4(uint32_t r[4], uint32_t addr) {
    asm volatile("ldmatrix.sync.aligned.m8n8.x4.shared.b16 {%0,%1,%2,%3}, [%4];"
                 : "=r"(r[0]), "=r"(r[1]), "=r"(r[2]), "=r"(r[3]) : "r"(addr));
}
__device__ __forceinline__ void ldsm_x4_t(uint32_t r[4], uint32_t addr) {
    asm volatile("ldmatrix.sync.aligned.m8n8.x4.trans.shared.b16 {%0,%1,%2,%3}, [%4];"
                 : "=r"(r[0]), "=r"(r[1]), "=r"(r[2]), "=r"(r[3]) : "r"(addr));
}
__device__ __forceinline__ void mma_bf16(float c[4], const uint32_t a[4], const uint32_t* b) {
    asm volatile(
        "mma.sync.aligned.m16n8k16.row.col.f32.bf16.bf16.f32 "
        "{%0,%1,%2,%3}, {%4,%5,%6,%7}, {%8,%9}, {%0,%1,%2,%3};"
        : "+f"(c[0]), "+f"(c[1]), "+f"(c[2]), "+f"(c[3])
        : "r"(a[0]), "r"(a[1]), "r"(a[2]), "r"(a[3]), "r"(b[0]), "r"(b[1]));
}
__device__ __forceinline__ void mma_bf16_2(float c[4], const uint32_t a[4],
                                           uint32_t b0, uint32_t b1) {
    asm volatile(
        "mma.sync.aligned.m16n8k16.row.col.f32.bf16.bf16.f32 "
        "{%0,%1,%2,%3}, {%4,%5,%6,%7}, {%8,%9}, {%0,%1,%2,%3};"
        : "+f"(c[0]), "+f"(c[1]), "+f"(c[2]), "+f"(c[3])
        : "r"(a[0]), "r"(a[1]), "r"(a[2]), "r"(a[3]), "r"(b0), "r"(b1));
}
__device__ __forceinline__ void cp_async16(uint32_t dst, const void* src) {
    asm volatile("cp.async.ca.shared.global [%0], [%1], 16;" :: "r"(dst), "l"(src));
}
#define CP_COMMIT() asm volatile("cp.async.commit_group;")
#define CP_WAIT0()  asm volatile("cp.async.wait_group 0;" ::: "memory")
#define CP_WAIT1()  asm volatile("cp.async.wait_group 1;" ::: "memory")

// XOR-swizzled smem offset: rows x 192 bf16 cols (384B row), 24 16B-chunks/row
__device__ __forceinline__ uint32_t swz(int row, int chunk) {
    return (uint32_t)(row * 384 + ((chunk ^ (row & 7)) << 4));
}

// ---------------- weight pack: both layers ----------------
__global__ void pack_kernel(const float* __restrict__ qkv_w, const float* __restrict__ out_w,
                            const float* __restrict__ w1, const float* __restrict__ w2) {
    int gi = blockIdx.x * 256 + threadIdx.x;
    if (gi >= 2 * 294912) return;
    int l = gi / 294912, i = gi % 294912;
    int blk = i / 36864, j = i % 36864;
    int k = j / 192, n = j % 192;
    float v;
    if (blk < 3)       v = qkv_w[(size_t)(l * 3 + blk) * 36864 + k * 192 + n];
    else if (blk == 3) v = out_w[(size_t)l * 36864 + k * 192 + n];
    else if (blk == 4) v = w1[(size_t)l * 73728 + k * 384 + n];
    else if (blk == 5) v = w1[(size_t)l * 73728 + k * 384 + 192 + n];
    else if (blk == 6) v = w2[(size_t)l * 73728 + k * 192 + n];
    else               v = w2[(size_t)l * 73728 + (192 + k) * 192 + n];
    g_Wh[gi] = __float2bfloat16(v);
}

// ============ QK dual-B GEMM: also emits bf16(x) to Xout ============
__global__ void __launch_bounds__(384)
gemm_qk(const float* __restrict__ X, const float* __restrict__ POS,
        const bf16* __restrict__ W0, const bf16* __restrict__ W1,
        const float* __restrict__ bias, bf16* __restrict__ C, bf16* __restrict__ Xout)
{
    extern __shared__ __align__(16) char smem[];
    const uint32_t smem_u32 = (uint32_t)__cvta_generic_to_shared(smem);
    const uint32_t b_u32[2] = { smem_u32, smem_u32 + 73728u };
    char* As = smem + 147456;
    __shared__ float sbias[384];

    const int tid = threadIdx.x, lane = tid & 31, wid = tid >> 5;
    const int wy = wid >> 2, wx = wid & 3;
    const int lane15 = lane & 15, lane16 = lane >> 4;
    const int g = lane >> 2, l4 = lane & 3;
    const int bx = (int)blockIdx.x;
    const uint32_t a_u32 = smem_u32 + 147456u;

    if (tid < 384) sbias[tid] = bias[tid];

    for (int f = tid; f < 4608; f += 384) {
        int r = f / 24, c = f % 24;
        cp_async16(b_u32[0] + swz(r, c), W0 + (size_t)r * 192 + c * 8);
        cp_async16(b_u32[1] + swz(r, c), W1 + (size_t)r * 192 + c * 8);
    }
    CP_COMMIT();

    const int nmine = (NT96 - bx + GRID - 1) / GRID;

    for (int ti = 0; ti < nmine; ti++) {
        const int t = bx + ti * GRID;
        #pragma unroll
        for (int u = 0; u < 6; u++) {
            int f = tid + u * 384;
            int r = f / 24, c = f % 24;
            const float4* xp = (const float4*)(X   + (size_t)(t * 96 + r) * 192 + c * 8);
            const float4* pp = (const float4*)(POS + (size_t)(t * 96 + r) * 192 + c * 8);
            float4 a0 = xp[0], a1 = xp[1], p0 = pp[0], p1 = pp[1];
            uint4 xv;
            xv.x = pk2(a0.x, a0.y); xv.y = pk2(a0.z, a0.w);
            xv.z = pk2(a1.x, a1.y); xv.w = pk2(a1.z, a1.w);
            *((uint4*)(Xout + (size_t)(t * 96 + r) * 192 + c * 8)) = xv;
            a0.x += p0.x; a0.y += p0.y; a0.z += p0.z; a0.w += p0.w;
            a1.x += p1.x; a1.y += p1.y; a1.z += p1.z; a1.w += p1.w;
            uint4 o;
            o.x = pk2(a0.x, a0.y); o.y = pk2(a0.z, a0.w);
            o.z = pk2(a1.x, a1.y); o.w = pk2(a1.z, a1.w);
            *(uint4*)(As + swz(r, c)) = o;
        }
        if (ti == 0) CP_WAIT0();
        __syncthreads();

        float acc[2][2][6][4];
        #pragma unroll
        for (int m = 0; m < 2; m++)
            #pragma unroll
            for (int mt = 0; mt < 2; mt++)
                #pragma unroll
                for (int nt = 0; nt < 6; nt++)
                    #pragma unroll
                    for (int i = 0; i < 4; i++) acc[m][mt][nt][i] = 0.f;

        #pragma unroll
        for (int kc = 0; kc < 12; kc++) {
            uint32_t a0[4], a1[4];
            ldsm_x4(a0, a_u32 + swz(wy * 32 + lane15,      kc * 2 + lane16));
            ldsm_x4(a1, a_u32 + swz(wy * 32 + 16 + lane15, kc * 2 + lane16));
            const int krow = kc * 16 + lane15;
            #pragma unroll
            for (int m = 0; m < 2; m++) {
                #pragma unroll
                for (int t16 = 0; t16 < 3; t16++) {
                    uint32_t B[4];
                    ldsm_x4_t(B, b_u32[m] + swz(krow, wx * 6 + t16 * 2 + lane16));
                    mma_bf16(acc[m][0][2 * t16],     a0, B + 0);
                    mma_bf16(acc[m][0][2 * t16 + 1], a0, B + 2);
                    mma_bf16(acc[m][1][2 * t16],     a1, B + 0);
                    mma_bf16(acc[m][1][2 * t16 + 1], a1, B + 2);
                }
            }
        }
        __syncthreads();

        const int row0 = t * 96;
        #pragma unroll
        for (int m = 0; m < 2; m++)
            #pragma unroll
            for (int mt = 0; mt < 2; mt++)
                #pragma unroll
                for (int half = 0; half < 2; half++) {
                    const int row = row0 + wy * 32 + mt * 16 + g + half * 8;
                    bf16* cp = C + (size_t)row * 384 + m * 192;
                    #pragma unroll
                    for (int t16 = 0; t16 < 3; t16++)
                        #pragma unroll
                        for (int b8 = 0; b8 < 2; b8++) {
                            const int col = wx * 48 + t16 * 16 + b8 * 8 + 2 * l4;
                            float ox = acc[m][mt][2 * t16 + b8][half * 2 + 0] + sbias[m * 192 + col];
                            float oy = acc[m][mt][2 * t16 + b8][half * 2 + 1] + sbias[m * 192 + col + 1];
                            __nv_bfloat162 o = __floats2bfloat162_rn(ox, oy);
                            *(__nv_bfloat162*)(cp + col) = o;
                        }
                }
    }
}

// ============ FFN1 dual-B GEMM: H[:,0:192]=gelu(A@W0+b0), H[:,192:384]=gelu(A@W1+b1) ============
// bf16 A double-buffered via cp.async; 384 threads, 1 CTA/SM. A read ONCE.
__global__ void __launch_bounds__(384)
gemm_ffn1d(const bf16* __restrict__ A,
           const bf16* __restrict__ W0, const bf16* __restrict__ W1,
           const float* __restrict__ bias /*384*/, bf16* __restrict__ C /*ldc 384*/)
{
    extern __shared__ __align__(16) char smem[];
    const uint32_t smem_u32 = (uint32_t)__cvta_generic_to_shared(smem);
    const uint32_t b_u32[2] = { smem_u32, smem_u32 + 73728u };
    const uint32_t a_u32 = smem_u32 + 147456u;      // 2 x 36864
    __shared__ float sbias[384];

    const int tid = threadIdx.x, lane = tid & 31, wid = tid >> 5;
    const int wy = wid >> 2, wx = wid & 3;
    const int lane15 = lane & 15, lane16 = lane >> 4;
    const int g = lane >> 2, l4 = lane & 3;
    const int bx = (int)blockIdx.x;

    if (tid < 384) sbias[tid] = bias[tid];

    for (int f = tid; f < 4608; f += 384) {
        int r = f / 24, c = f % 24;
        cp_async16(b_u32[0] + swz(r, c), W0 + (size_t)r * 192 + c * 8);
        cp_async16(b_u32[1] + swz(r, c), W1 + (size_t)r * 192 + c * 8);
    }
    auto loadA = [&](int t, int buf) {
        #pragma unroll
        for (int u = 0; u < 6; u++) {
            int f = tid + u * 384;
            int r = f / 24, c = f % 24;
            cp_async16(a_u32 + buf * 36864u + swz(r, c), A + (size_t)(t * 96 + r) * 192 + c * 8);
        }
    };

    const int nmine = (NT96 - bx + GRID - 1) / GRID;
    loadA(bx, 0);
    CP_COMMIT();            // group 0: B + A0

    for (int ti = 0; ti < nmine; ti++) {
        const int t = bx + ti * GRID;
        if (ti + 1 < nmine) loadA(bx + (ti + 1) * GRID, (ti + 1) & 1);
        CP_COMMIT();
        CP_WAIT1();
        __syncthreads();

        float acc[2][2][6][4];
        #pragma unroll
        for (int m = 0; m < 2; m++)
            #pragma unroll
            for (int mt = 0; mt < 2; mt++)
                #pragma unroll
                for (int nt = 0; nt < 6; nt++)
                    #pragma unroll
                    for (int i = 0; i < 4; i++) acc[m][mt][nt][i] = 0.f;

        const uint32_t abuf = a_u32 + (uint32_t)((ti & 1) * 36864);
        #pragma unroll
        for (int kc = 0; kc < 12; kc++) {
            uint32_t a0[4], a1[4];
            ldsm_x4(a0, abuf + swz(wy * 32 + lane15,      kc * 2 + lane16));
            ldsm_x4(a1, abuf + swz(wy * 32 + 16 + lane15, kc * 2 + lane16));
            const int krow = kc * 16 + lane15;
            #pragma unroll
            for (int m = 0; m < 2; m++) {
                #pragma unroll
                for (int t16 = 0; t16 < 3; t16++) {
                    uint32_t B[4];
                    ldsm_x4_t(B, b_u32[m] + swz(krow, wx * 6 + t16 * 2 + lane16));
                    mma_bf16(acc[m][0][2 * t16],     a0, B + 0);
                    mma_bf16(acc[m][0][2 * t16 + 1], a0, B + 2);
                    mma_bf16(acc[m][1][2 * t16],     a1, B + 0);
                    mma_bf16(acc[m][1][2 * t16 + 1], a1, B + 2);
                }
            }
        }
        __syncthreads();   // A buffer fully consumed before ti+2 overwrites it

        const int row0 = t * 96;
        #pragma unroll
        for (int m = 0; m < 2; m++)
            #pragma unroll
            for (int mt = 0; mt < 2; mt++)
                #pragma unroll
                for (int half = 0; half < 2; half++) {
                    const int row = row0 + wy * 32 + mt * 16 + g + half * 8;
                    bf16* cp = C + (size_t)row * 384 + m * 192;
                    #pragma unroll
                    for (int t16 = 0; t16 < 3; t16++)
                        #pragma unroll
                        for (int b8 = 0; b8 < 2; b8++) {
                            const int col = wx * 48 + t16 * 16 + b8 * 8 + 2 * l4;
                            float ox = acc[m][mt][2 * t16 + b8][half * 2 + 0] + sbias[m * 192 + col];
                            float oy = acc[m][mt][2 * t16 + b8][half * 2 + 1] + sbias[m * 192 + col + 1];
                            ox = gelu_tanh(ox); oy = gelu_tanh(oy);
                            __nv_bfloat162 o = __floats2bfloat162_rn(ox, oy);
                            *(__nv_bfloat162*)(cp + col) = o;
                        }
                }
    }
}

// ============ generic bf16-A GEMM (V projection) ============
template<bool GELU>
__global__ void __launch_bounds__(256, 2)
gemm_bf(const bf16* __restrict__ A, const bf16* __restrict__ W,
        const float* __restrict__ bias, bf16* __restrict__ C, int ldc, int coff)
{
    extern __shared__ __align__(16) char smem[];
    const uint32_t smem_u32 = (uint32_t)__cvta_generic_to_shared(smem);
    const uint32_t b_u32 = smem_u32;
    const uint32_t a_u32 = smem_u32 + 73728u;

    const int tid = threadIdx.x, lane = tid & 31, wid = tid >> 5;
    const int wy = wid >> 2, wx = wid & 3;
    const int lane15 = lane & 15, lane16 = lane >> 4;
    const int g = lane >> 2, l4 = lane & 3;
    const int bx = (int)blockIdx.x;

    for (int f = tid; f < 4608; f += 256) {
        int r = f / 24, c = f % 24;
        cp_async16(b_u32 + swz(r, c), W + (size_t)r * 192 + c * 8);
    }
    auto loadA = [&](int t) {
        #pragma unroll
        for (int u = 0; u < 9; u++) {
            int f = tid + u * 256;
            int r = f / 24, c = f % 24;
            cp_async16(a_u32 + swz(r, c), A + (size_t)(t * 96 + r) * 192 + c * 8);
        }
    };

    const int nmine = (NT96 - bx + GRID2 - 1) / GRID2;
    loadA(bx);
    CP_COMMIT();

    for (int ti = 0; ti < nmine; ti++) {
        const int t = bx + ti * GRID2;
        CP_WAIT0();
        __syncthreads();

        float acc[3][6][4];
        #pragma unroll
        for (int mt = 0; mt < 3; mt++)
            #pragma unroll
            for (int nt = 0; nt < 6; nt++)
                #pragma unroll
                for (int i = 0; i < 4; i++) acc[mt][nt][i] = 0.f;

        #pragma unroll
        for (int kc = 0; kc < 12; kc++) {
            uint32_t a[3][4];
            #pragma unroll
            for (int mt = 0; mt < 3; mt++)
                ldsm_x4(a[mt], a_u32 + swz(wy * 48 + mt * 16 + lane15, kc * 2 + lane16));
            const int krow = kc * 16 + lane15;
            #pragma unroll
            for (int t16 = 0; t16 < 3; t16++) {
                uint32_t B[4];
                ldsm_x4_t(B, b_u32 + swz(krow, wx * 6 + t16 * 2 + lane16));
                #pragma unroll
                for (int mt = 0; mt < 3; mt++) {
                    mma_bf16(acc[mt][2 * t16],     a[mt], B + 0);
                    mma_bf16(acc[mt][2 * t16 + 1], a[mt], B + 2);
                }
            }
        }
        __syncthreads();

        if (ti + 1 < nmine) loadA(bx + (ti + 1) * GRID2);
        CP_COMMIT();

        const int row0 = t * 96;
        #pragma unroll
        for (int mt = 0; mt < 3; mt++)
            #pragma unroll
            for (int half = 0; half < 2; half++) {
                const int row = row0 + wy * 48 + mt * 16 + g + half * 8;
                bf16* cp = C + (size_t)row * ldc + coff;
                #pragma unroll
                for (int t16 = 0; t16 < 3; t16++)
                    #pragma unroll
                    for (int b8 = 0; b8 < 2; b8++) {
                        const int col = wx * 48 + t16 * 16 + b8 * 8 + 2 * l4;
                        float ox = acc[mt][2 * t16 + b8][half * 2 + 0] + __ldg(bias + col);
                        float oy = acc[mt][2 * t16 + b8][half * 2 + 1] + __ldg(bias + col + 1);
                        if (GELU) { ox = gelu_tanh(ox); oy = gelu_tanh(oy); }
                        __nv_bfloat162 o = __floats2bfloat162_rn(ox, oy);
                        *(__nv_bfloat162*)(cp + col) = o;
                    }
            }
    }
}

// ============ O-proj + residual + LN1 (natural order) ============
__global__ void __launch_bounds__(256, 2)
gemm_oln(const bf16* __restrict__ A, const bf16* __restrict__ W,
         const float* __restrict__ bias, const float* __restrict__ xres,
         const float* __restrict__ lnw, const float* __restrict__ lnb,
         float* __restrict__ Xf, bf16* __restrict__ Xh)
{
    extern __shared__ __align__(16) char smem[];
    const uint32_t smem_u32 = (uint32_t)__cvta_generic_to_shared(smem);
    const uint32_t b_u32 = smem_u32;
    const uint32_t a_u32 = smem_u32 + 73728u;
    __shared__ float rs[96], rq[96];

    const int tid = threadIdx.x, lane = tid & 31, wid = tid >> 5;
    const int wy = wid >> 2, wx = wid & 3;
    const int lane15 = lane & 15, lane16 = lane >> 4;
    const int g = lane >> 2, l4 = lane & 3;
    const int bx = (int)blockIdx.x;

    for (int f = tid; f < 4608; f += 256) {
        int r = f / 24, c = f % 24;
        cp_async16(b_u32 + swz(r, c), W + (size_t)r * 192 + c * 8);
    }
    auto loadA = [&](int t) {
        #pragma unroll
        for (int u = 0; u < 9; u++) {
            int f = tid + u * 256;
            int r = f / 24, c = f % 24;
            cp_async16(a_u32 + swz(r, c), A + (size_t)(t * 96 + r) * 192 + c * 8);
        }
    };

    const int nmine = (NT96 - bx + GRID2 - 1) / GRID2;
    loadA(bx);
    CP_COMMIT();

    for (int ti = 0; ti < nmine; ti++) {
        const int t = bx + ti * GRID2;
        CP_WAIT0();
        __syncthreads();
        if (tid < 96) { rs[tid] = 0.f; rq[tid] = 0.f; }

        float acc[3][6][4];
        #pragma unroll
        for (int mt = 0; mt < 3; mt++)
            #pragma unroll
            for (int nt = 0; nt < 6; nt++)
                #pragma unroll
                for (int i = 0; i < 4; i++) acc[mt][nt][i] = 0.f;

        #pragma unroll
        for (int kc = 0; kc < 12; kc++) {
            uint32_t a[3][4];
            #pragma unroll
            for (int mt = 0; mt < 3; mt++)
                ldsm_x4(a[mt], a_u32 + swz(wy * 48 + mt * 16 + lane15, kc * 2 + lane16));
            const int krow = kc * 16 + lane15;
            #pragma unroll
            for (int t16 = 0; t16 < 3; t16++) {
                uint32_t B[4];
                ldsm_x4_t(B, b_u32 + swz(krow, wx * 6 + t16 * 2 + lane16));
                #pragma unroll
                for (int mt = 0; mt < 3; mt++) {
                    mma_bf16(acc[mt][2 * t16],     a[mt], B + 0);
                    mma_bf16(acc[mt][2 * t16 + 1], a[mt], B + 2);
                }
            }
        }
        __syncthreads();

        if (ti + 1 < nmine) loadA(bx + (ti + 1) * GRID2);
        CP_COMMIT();

        const int row0 = t * 96;
        #pragma unroll
        for (int mt = 0; mt < 3; mt++)
            #pragma unroll
            for (int half = 0; half < 2; half++) {
                const int row = row0 + wy * 48 + mt * 16 + g + half * 8;
                const float* xp = xres + (size_t)row * 192;
                float sv = 0.f, qv = 0.f;
                #pragma unroll
                for (int t16 = 0; t16 < 3; t16++)
                    #pragma unroll
                    for (int b8 = 0; b8 < 2; b8++) {
                        const int col = wx * 48 + t16 * 16 + b8 * 8 + 2 * l4;
                        float2 xv = *(const float2*)(xp + col);
                        float v0 = acc[mt][2 * t16 + b8][half * 2 + 0] + __ldg(bias + col) + xv.x;
                        float v1 = acc[mt][2 * t16 + b8][half * 2 + 1] + __ldg(bias + col + 1) + xv.y;
                        acc[mt][2 * t16 + b8][half * 2 + 0] = v0;
                        acc[mt][2 * t16 + b8][half * 2 + 1] = v1;
                        sv += v0 + v1;
                        qv += v0 * v0 + v1 * v1;
                    }
                sv += __shfl_xor_sync(0xffffffffu, sv, 1);
                qv += __shfl_xor_sync(0xffffffffu, qv, 1);
                sv += __shfl_xor_sync(0xffffffffu, sv, 2);
                qv += __shfl_xor_sync(0xffffffffu, qv, 2);
                if (l4 == 0) {
                    const int rloc = wy * 48 + mt * 16 + g + half * 8;
                    atomicAdd(&rs[rloc], sv);
                    atomicAdd(&rq[rloc], qv);
                }
            }
        __syncthreads();
        #pragma unroll
        for (int mt = 0; mt < 3; mt++)
            #pragma unroll
            for (int half = 0; half < 2; half++) {
                const int rloc = wy * 48 + mt * 16 + g + half * 8;
                const int row = row0 + rloc;
                const float mean = rs[rloc] * (1.f / 192.f);
                const float inv  = rsqrtf(rq[rloc] * (1.f / 192.f) - mean * mean + 1e-5f);
                float* xo = Xf + (size_t)row * 192;
                bf16*  xh = Xh + (size_t)row * 192;
                #pragma unroll
                for (int t16 = 0; t16 < 3; t16++)
                    #pragma unroll
                    for (int b8 = 0; b8 < 2; b8++) {
                        const int col = wx * 48 + t16 * 16 + b8 * 8 + 2 * l4;
                        float v0 = acc[mt][2 * t16 + b8][half * 2 + 0];
                        float v1 = acc[mt][2 * t16 + b8][half * 2 + 1];
                        float o0 = (v0 - mean) * inv * __ldg(lnw + col) + __ldg(lnb + col);
                        float o1 = (v1 - mean) * inv * __ldg(lnw + col + 1) + __ldg(lnb + col + 1);
                        float2 of; of.x = o0; of.y = o1;
                        *(float2*)(xo + col) = of;
                        __nv_bfloat162 ob = __floats2bfloat162_rn(o0, o1);
                        *(__nv_bfloat162*)(xh + col) = ob;
                    }
            }
    }
}

// ============ FFN2 (K=384) + residual + LN2 ============
__global__ void __launch_bounds__(384)
gemm_f2ln(const bf16* __restrict__ A,
          const bf16* __restrict__ W0, const bf16* __restrict__ W1,
          const float* __restrict__ bias, const float* __restrict__ xres,
          const float* __restrict__ lnw, const float* __restrict__ lnb,
          float* __restrict__ Out)
{
    extern __shared__ __align__(16) char smem[];
    const uint32_t smem_u32 = (uint32_t)__cvta_generic_to_shared(smem);
    const uint32_t b_u32[2] = { smem_u32, smem_u32 + 73728u };
    const uint32_t a_u32    = smem_u32 + 147456u;
    __shared__ float sbias[192], slnw[192], slnb[192];
    __shared__ float rs[96], rq[96];

    const int tid = threadIdx.x, lane = tid & 31, wid = tid >> 5;
    const int wy = wid >> 2, wx = wid & 3;
    const int lane15 = lane & 15, lane16 = lane >> 4;
    const int g = lane >> 2, l4 = lane & 3;
    const int bx = (int)blockIdx.x;

    if (tid < 192) { sbias[tid] = bias[tid]; slnw[tid] = lnw[tid]; slnb[tid] = lnb[tid]; }

    for (int f = tid; f < 4608; f += 384) {
        int r = f / 24, c = f % 24;
        cp_async16(b_u32[0] + swz(r, c), W0 + (size_t)r * 192 + c * 8);
        cp_async16(b_u32[1] + swz(r, c), W1 + (size_t)r * 192 + c * 8);
    }
    const int pr = tid >> 2, pc0 = (tid & 3) * 6;
    auto loadA = [&](int s, int buf) {
        const int t = bx + (s >> 1) * GRID, kh = s & 1;
        const bf16* src = A + (size_t)(t * 96 + pr) * 384 + kh * 192 + pc0 * 8;
        uint32_t dstb = a_u32 + buf * 36864u;
        #pragma unroll
        for (int u = 0; u < 6; u++)
            cp_async16(dstb + swz(pr, pc0 + u), src + u * 8);
    };

    const int nmine = (NT96 - bx + GRID - 1) / GRID;
    const int nst = nmine * 2;
    loadA(0, 0);
    CP_COMMIT();

    float acc[2][6][4];

    for (int s = 0; s < nst; s++) {
        const int kh = s & 1;
        if (s + 1 < nst) loadA(s + 1, (s + 1) & 1);
        CP_COMMIT();
        CP_WAIT1();
        __syncthreads();
        if (kh == 0) {
            if (tid < 96) { rs[tid] = 0.f; rq[tid] = 0.f; }
            #pragma unroll
            for (int mt = 0; mt < 2; mt++)
                #pragma unroll
                for (int nt = 0; nt < 6; nt++)
                    #pragma unroll
                    for (int i = 0; i < 4; i++) acc[mt][nt][i] = 0.f;
        }

        const uint32_t abuf = a_u32 + (uint32_t)((s & 1) * 36864);
        const uint32_t bb = b_u32[kh];
        #pragma unroll
        for (int kc = 0; kc < 12; kc++) {
            uint32_t a0[4], a1[4];
            ldsm_x4(a0, abuf + swz(wy * 32 + lane15,      kc * 2 + lane16));
            ldsm_x4(a1, abuf + swz(wy * 32 + 16 + lane15, kc * 2 + lane16));
            const int krow = kc * 16 + lane15;
            #pragma unroll
            for (int t16 = 0; t16 < 3; t16++) {
                uint32_t B[4];
                ldsm_x4_t(B, bb + swz(krow, wx * 6 + t16 * 2 + lane16));
                mma_bf16(acc[0][2 * t16],     a0, B + 0);
                mma_bf16(acc[0][2 * t16 + 1], a0, B + 2);
                mma_bf16(acc[1][2 * t16],     a1, B + 0);
                mma_bf16(acc[1][2 * t16 + 1], a1, B + 2);
            }
        }
        __syncthreads();

        if (kh == 1) {
            const int row0 = (bx + (s >> 1) * GRID) * 96;
            #pragma unroll
            for (int mt = 0; mt < 2; mt++)
                #pragma unroll
                for (int half = 0; half < 2; half++) {
                    const int row = row0 + wy * 32 + mt * 16 + g + half * 8;
                    const float* xp = xres + (size_t)row * 192;
                    float sv = 0.f, qv = 0.f;
                    #pragma unroll
                    for (int t16 = 0; t16 < 3; t16++)
                        #pragma unroll
                        for (int b8 = 0; b8 < 2; b8++) {
                            const int col = wx * 48 + t16 * 16 + b8 * 8 + 2 * l4;
                            float2 xv = *(const float2*)(xp + col);
                            float v0 = acc[mt][2 * t16 + b8][half * 2 + 0] + sbias[col] + xv.x;
                            float v1 = acc[mt][2 * t16 + b8][half * 2 + 1] + sbias[col + 1] + xv.y;
                            acc[mt][2 * t16 + b8][half * 2 + 0] = v0;
                            acc[mt][2 * t16 + b8][half * 2 + 1] = v1;
                            sv += v0 + v1; qv += v0 * v0 + v1 * v1;
                        }
                    sv += __shfl_xor_sync(0xffffffffu, sv, 1);
                    qv += __shfl_xor_sync(0xffffffffu, qv, 1);
                    sv += __shfl_xor_sync(0xffffffffu, sv, 2);
                    qv += __shfl_xor_sync(0xffffffffu, qv, 2);
                    if (l4 == 0) {
                        const int rloc = wy * 32 + mt * 16 + g + half * 8;
                        atomicAdd(&rs[rloc], sv);
                        atomicAdd(&rq[rloc], qv);
                    }
                }
            __syncthreads();
            #pragma unroll
            for (int mt = 0; mt < 2; mt++)
                #pragma unroll
                for (int half = 0; half < 2; half++) {
                    const int rloc = wy * 32 + mt * 16 + g + half * 8;
                    const int row = row0 + rloc;
                    const float mean = rs[rloc] * (1.f / 192.f);
                    const float inv  = rsqrtf(rq[rloc] * (1.f / 192.f) - mean * mean + 1e-5f);
                    float* op = Out + (size_t)row * 192;
                    #pragma unroll
                    for (int t16 = 0; t16 < 3; t16++)
                        #pragma unroll
                        for (int b8 = 0; b8 < 2; b8++) {
                            const int col = wx * 48 + t16 * 16 + b8 * 8 + 2 * l4;
                            float v0 = acc[mt][2 * t16 + b8][half * 2 + 0];
                            float v1 = acc[mt][2 * t16 + b8][half * 2 + 1];
                            float2 of;
                            of.x = (v0 - mean) * inv * slnw[col] + slnb[col];
                            of.y = (v1 - mean) * inv * slnw[col + 1] + slnb[col + 1];
                            *(float2*)(op + col) = of;
                        }
                }
        }
    }
}

// ================= tensor-core set attention (Q frags from global, K/V in smem) =================
#define HBUF 3840            // 48*40*2 bytes per head per buffer
#define AK_OFF 0
#define AV_OFF 30720
#define ATTN_SMEM 61440

__global__ void __launch_bounds__(256, 3)
attn_tc(const bf16* __restrict__ QK, const bf16* __restrict__ V,
        const int* __restrict__ gidx, bf16* __restrict__ O)
{
    extern __shared__ __align__(16) char smem[];
    const uint32_t smem_u32 = (uint32_t)__cvta_generic_to_shared(smem);
    __shared__ int sidx[36];

    const int s = blockIdx.x, tid = threadIdx.x;
    const int lane = tid & 31, h = tid >> 5;
    const int lane15 = lane & 15, lane16 = lane >> 4;
    const int g = lane >> 2, l4 = lane & 3;

    if (tid < 36) sidx[tid] = __ldg(gidx + s * SETS + tid);
    for (int i = tid; i < ATTN_SMEM / 16; i += 256)
        *(uint4*)(smem + i * 16) = make_uint4(0, 0, 0, 0);
    __syncthreads();

    for (int f = tid; f < 864; f += 256) {
        int hh = f / 108, r = f % 108;
        int key = r / 3, c = r % 3;
        int grow = sidx[key];
        uint4 k = *(const uint4*)(QK + (size_t)grow * 384 + 192 + hh * 24 + c * 8);
        *(uint4*)(smem + AK_OFF + hh * HBUF + (key * 40 + c * 8) * 2) = k;
        uint4 v = *(const uint4*)(V + (size_t)grow * 192 + hh * 24 + c * 8);
        *(uint4*)(smem + AV_OFF + hh * HBUF + (key * 40 + c * 8) * 2) = v;
    }

    uint32_t A0[3][4], A1[3][4];
    #pragma unroll
    for (int mt = 0; mt < 3; mt++) {
        const int r0 = mt * 16 + g, r1 = r0 + 8;
        const int gr0 = sidx[(r0 < 36) ? r0 : 0];
        const int gr1 = sidx[(r1 < 36) ? r1 : 0];
        const bf16* q0 = QK + (size_t)gr0 * 384 + h * 24;
        const bf16* q1 = QK + (size_t)gr1 * 384 + h * 24;
        A0[mt][0] = *(const uint32_t*)(q0 + 2 * l4);
        A0[mt][1] = *(const uint32_t*)(q1 + 2 * l4);
        A0[mt][2] = *(const uint32_t*)(q0 + 2 * l4 + 8);
        A0[mt][3] = *(const uint32_t*)(q1 + 2 * l4 + 8);
        A1[mt][0] = *(const uint32_t*)(q0 + 2 * l4 + 16);
        A1[mt][1] = *(const uint32_t*)(q1 + 2 * l4 + 16);
        A1[mt][2] = 0;
        A1[mt][3] = 0;
    }
    __syncthreads();

    const uint32_t kb = smem_u32 + AK_OFF + (uint32_t)(h * HBUF);
    const uint32_t vb = smem_u32 + AV_OFF + (uint32_t)(h * HBUF);

    float S[3][6][4];
    #pragma unroll
    for (int mt = 0; mt < 3; mt++)
        #pragma unroll
        for (int nt = 0; nt < 6; nt++)
            #pragma unroll
            for (int i = 0; i < 4; i++) S[mt][nt][i] = 0.f;

    #pragma unroll
    for (int kc = 0; kc < 2; kc++) {
        #pragma unroll
        for (int nt2 = 0; nt2 < 3; nt2++) {
            uint32_t Br[4];
            ldsm_x4(Br, kb + (uint32_t)(((nt2 * 16 + lane15) * 40 + kc * 16 + lane16 * 8) * 2));
            #pragma unroll
            for (int mt = 0; mt < 3; mt++) {
                const uint32_t* a = (kc == 0) ? A0[mt] : A1[mt];
                mma_bf16_2(S[mt][2 * nt2],     a, Br[0], Br[2]);
                mma_bf16_2(S[mt][2 * nt2 + 1], a, Br[1], Br[3]);
            }
        }
    }

    const float scale = 0.20412414523193154f;
    float inv_[3][2];
    #pragma unroll
    for (int mt = 0; mt < 3; mt++) {
        #pragma unroll
        for (int half = 0; half < 2; half++) {
            if (mt == 2 && half == 1) {
                #pragma unroll
                for (int nt = 0; nt < 6; nt++) { S[2][nt][2] = 0.f; S[2][nt][3] = 0.f; }
                inv_[2][1] = 0.f;
                continue;
            }
            float mx = -1e30f;
            #pragma unroll
            for (int nt = 0; nt < 5; nt++) {
                #pragma unroll
                for (int cc = 0; cc < 2; cc++) {
                    const int col = nt * 8 + l4 * 2 + cc;
                    float v = (col < 36) ? S[mt][nt][half * 2 + cc] * scale : -1e30f;
                    S[mt][nt][half * 2 + cc] = v;
                    mx = fmaxf(mx, v);
                }
            }
            mx = fmaxf(mx, __shfl_xor_sync(0xffffffffu, mx, 1));
            mx = fmaxf(mx, __shfl_xor_sync(0xffffffffu, mx, 2));
            float sum = 0.f;
            #pragma unroll
            for (int nt = 0; nt < 5; nt++) {
                #pragma unroll
                for (int cc = 0; cc < 2; cc++) {
                    float e = __expf(S[mt][nt][half * 2 + cc] - mx);
                    S[mt][nt][half * 2 + cc] = e;
                    sum += e;
                }
            }
            S[mt][5][half * 2 + 0] = 0.f;
            S[mt][5][half * 2 + 1] = 0.f;
            sum += __shfl_xor_sync(0xffffffffu, sum, 1);
            sum += __shfl_xor_sync(0xffffffffu, sum, 2);
            inv_[mt][half] = 1.f / sum;
        }
    }

    uint32_t P[3][3][4];
    #pragma unroll
    for (int mt = 0; mt < 3; mt++)
        #pragma unroll
        for (int kt = 0; kt < 3; kt++) {
            P[mt][kt][0] = pk2(S[mt][2 * kt][0],     S[mt][2 * kt][1]);
            P[mt][kt][1] = pk2(S[mt][2 * kt][2],     S[mt][2 * kt][3]);
            P[mt][kt][2] = pk2(S[mt][2 * kt + 1][0], S[mt][2 * kt + 1][1]);
            P[mt][kt][3] = pk2(S[mt][2 * kt + 1][2], S[mt][2 * kt + 1][3]);
        }

    float Oa[3][4][4];
    #pragma unroll
    for (int mt = 0; mt < 3; mt++)
        #pragma unroll
        for (int nt = 0; nt < 4; nt++)
            #pragma unroll
            for (int i = 0; i < 4; i++) Oa[mt][nt][i] = 0.f;

    #pragma unroll
    for (int kt = 0; kt < 3; kt++) {
        #pragma unroll
        for (int nt2 = 0; nt2 < 2; nt2++) {
            uint32_t B[4];
            ldsm_x4_t(B, vb + (uint32_t)(((kt * 16 + lane15) * 40 + nt2 * 16 + lane16 * 8) * 2));
            #pragma unroll
            for (int mt = 0; mt < 3; mt++) {
                mma_bf16(Oa[mt][2 * nt2],     P[mt][kt], B + 0);
                mma_bf16(Oa[mt][2 * nt2 + 1], P[mt][kt], B + 2);
            }
        }
    }

    #pragma unroll
    for (int mt = 0; mt < 3; mt++)
        #pragma unroll
        for (int half = 0; half < 2; half++) {
            const int row = mt * 16 + g + half * 8;
            if (row >= 36) continue;
            const int grow = sidx[row];
            const float inv = inv_[mt][half];
            bf16* op = O + (size_t)grow * 192 + h * 24;
            #pragma unroll
            for (int nt = 0; nt < 3; nt++) {
                const int col = nt * 8 + l4 * 2;
                __nv_bfloat162 o = __floats2bfloat162_rn(
                    Oa[mt][nt][half * 2 + 0] * inv, Oa[mt][nt][half * 2 + 1] * inv);
                *(__nv_bfloat162*)(op + col) = o;
            }
        }
}

// ---------------- host ----------------
extern "C" void kernel_launch(void* const* d_in, const int* in_sizes, int n_in,
                              void* d_out, int out_size)
{
    (void)in_sizes; (void)n_in; (void)out_size;
    const float* src    = (const float*)d_in[0];
    const float* pos    = (const float*)d_in[1];
    const float* qkv_w  = (const float*)d_in[2];
    const float* qkv_b  = (const float*)d_in[3];
    const float* out_w  = (const float*)d_in[4];
    const float* out_b  = (const float*)d_in[5];
    const float* ln_w   = (const float*)d_in[6];
    const float* ln_b   = (const float*)d_in[7];
    const float* w1     = (const float*)d_in[8];
    const float* b1     = (const float*)d_in[9];
    const float* w2     = (const float*)d_in[10];
    const float* b2     = (const float*)d_in[11];
    const int*   inds   = (const int*)d_in[12];
    float*       outp   = (float*)d_out;

    bf16 *QKh, *Vh, *Oh, *Hh, *Xh, *Wh;
    float *Xb;
    cudaGetSymbolAddress((void**)&QKh, g_QKh);
    cudaGetSymbolAddress((void**)&Vh,  g_Vh);
    cudaGetSymbolAddress((void**)&Oh,  g_Oh);
    cudaGetSymbolAddress((void**)&Hh,  g_Hh);
    cudaGetSymbolAddress((void**)&Xh,  g_Xh);
    cudaGetSymbolAddress((void**)&Xb,  g_X);
    cudaGetSymbolAddress((void**)&Wh,  g_Wh);

    cudaFuncSetAttribute(attn_tc, cudaFuncAttributeMaxDynamicSharedMemorySize, ATTN_SMEM);

    const int sm_qk  = 2 * 73728 + 36864;              // 184320 (1 CTA/SM)
    const int sm_ffd = 2 * 73728 + 2 * 36864;          // 221184 (1 CTA/SM)
    const int sm_one = 73728 + 36864;                  // 110592 (2 CTAs/SM)
    cudaFuncSetAttribute((const void*)gemm_qk,
                         cudaFuncAttributeMaxDynamicSharedMemorySize, sm_qk);
    cudaFuncSetAttribute((const void*)gemm_ffn1d,
                         cudaFuncAttributeMaxDynamicSharedMemorySize, sm_ffd);
    cudaFuncSetAttribute((const void*)gemm_bf<false>,
                         cudaFuncAttributeMaxDynamicSharedMemorySize, sm_one);
    cudaFuncSetAttribute((const void*)gemm_oln,
                         cudaFuncAttributeMaxDynamicSharedMemorySize, sm_one);
    cudaFuncSetAttribute((const void*)gemm_f2ln,
                         cudaFuncAttributeMaxDynamicSharedMemorySize, sm_ffd);

    // pack both layers once
    pack_kernel<<<(2 * 294912 + 255) / 256, 256>>>(qkv_w, out_w, w1, w2);

    for (int l = 0; l < NL; l++) {
        const float* xin = (l == 0) ? src : Xb;
        const int*   idx = inds + (size_t)l * NV;
        const float* pel = pos  + (size_t)l * NV * DM;
        const float* qb  = qkv_b + (size_t)l * 3 * DM;
        bf16* Wl = Wh + (size_t)l * 294912;

        // Q|K GEMM; also emits bf16(x) into Oh for the V GEMM
        gemm_qk<<<GRID, 384, sm_qk>>>(xin, pel, Wl + 0 * 36864, Wl + 1 * 36864, qb, QKh, Oh);

        // V = bf16(x) @ Wv + bv   (reads Oh)
        gemm_bf<false><<<GRID2, 256, sm_one>>>(Oh, Wl + 2 * 36864, qb + 384, Vh, 192, 0);

        // attention: gather rows by idx, write O (overwrites Oh) in natural order
        attn_tc<<<NSET, 256, ATTN_SMEM>>>(QKh, Vh, idx, Oh);

        // O-proj + residual + LN1 -> Xb (fp32) and Xh (bf16)
        gemm_oln<<<GRID2, 256, sm_one>>>(Oh, Wl + 3 * 36864, out_b + (size_t)l * DM, xin,
                                         ln_w + (size_t)(l * 2) * DM, ln_b + (size_t)(l * 2) * DM,
                                         Xb, Xh);

        // H = gelu(Xh @ [W1a|W1b] + b1): single dual-B launch, Xh read once
        gemm_ffn1d<<<GRID, 384, sm_ffd>>>(Xh, Wl + 4 * 36864, Wl + 5 * 36864,
                                          b1 + (size_t)l * DFF, Hh);

        // x = LN(x1 + Hh @ W2 + b2)
        float* lnout = (l == NL - 1) ? outp : Xb;
        gemm_f2ln<<<GRID, 384, sm_ffd>>>(Hh, Wl + 6 * 36864, Wl + 7 * 36864,
                                         b2 + (size_t)l * DM, Xb,
                                         ln_w + (size_t)(l * 2 + 1) * DM,
                                         ln_b + (size_t)(l * 2 + 1) * DM, lnout);
    }
}